// round 1
// baseline (speedup 1.0000x reference)
#include <cuda_runtime.h>
#include <cstddef>

// ---------------------------------------------------------------------------
// EP free-phase relaxation, T=20 steps, dt=1  =>  each step is
//   s0' = rho(s1 @ W0^T + b0)
//   s1' = rho(s2 @ W1^T + b1 + s0 @ W0)
//   s2' = rho(C2 + s1 @ W1),  C2 = data @ W2^T + b2  (hoisted, step-invariant)
// rho(x) = clip(x, 0, 1)
// Shapes: B=256, sizes [512, 2048, 2048, 4096]
//   W0: (512,2048)  W1: (2048,2048)  W2: (2048,4096)
// ---------------------------------------------------------------------------

#define BATCH 256
#define D0 512
#define D1 2048
#define D2 2048
#define DIN 4096
#define T_STEPS 20

#define BM 64
#define BN 64
#define BK 16
// 256 threads, 16x16 grid, each computes 4x4 outputs

// Ping-pong state buffers + hoisted C2 (no allocations allowed -> device globals)
__device__ float g_s0[2][BATCH * D0];
__device__ float g_s1[2][BATCH * D1];
__device__ float g_s2[2][BATCH * D2];
__device__ float g_c2[BATCH * D2];

// ---------------------------------------------------------------------------
// Block-level GEMM accumulate: acc += A[m0: , :K] * op(B)[:K, n0:]
//   btrans = true : B is (N, K) row-major, use B[n, k]   (the  X @ W^T  case)
//   btrans = false: B is (K, N) row-major, use B[k, n]   (the  X @ W    case)
// All dims are multiples of the tile sizes; no bounds checks needed.
// ---------------------------------------------------------------------------
__device__ __forceinline__ void gemm_acc(
    const float* __restrict__ A, int lda,
    const float* __restrict__ Bm, int ldb, bool btrans,
    int K, int m0, int n0,
    float (&acc)[4][4],
    float (&As)[BK][BM], float (&Bs)[BK][BN])
{
    const int tid = threadIdx.x;
    const int tx = tid & 15;
    const int ty = tid >> 4;

    for (int k0 = 0; k0 < K; k0 += BK) {
        // --- load A tile (64 rows x 16 k), transposed into As[k][m]
        {
            int row = tid >> 2;            // 0..63
            int kg  = (tid & 3) << 2;      // 0,4,8,12
            float4 v = *(const float4*)(A + (size_t)(m0 + row) * lda + k0 + kg);
            As[kg + 0][row] = v.x;
            As[kg + 1][row] = v.y;
            As[kg + 2][row] = v.z;
            As[kg + 3][row] = v.w;
        }
        // --- load B tile into Bs[k][n]
        if (btrans) {
            int row = tid >> 2;            // n index 0..63
            int kg  = (tid & 3) << 2;
            float4 v = *(const float4*)(Bm + (size_t)(n0 + row) * ldb + k0 + kg);
            Bs[kg + 0][row] = v.x;
            Bs[kg + 1][row] = v.y;
            Bs[kg + 2][row] = v.z;
            Bs[kg + 3][row] = v.w;
        } else {
            int kk = tid >> 4;             // 0..15
            int nc = (tid & 15) << 2;      // 0..60
            float4 v = *(const float4*)(Bm + (size_t)(k0 + kk) * ldb + n0 + nc);
            *(float4*)&Bs[kk][nc] = v;
        }
        __syncthreads();

        #pragma unroll
        for (int kk = 0; kk < BK; kk++) {
            float4 a = *(const float4*)&As[kk][ty << 2];
            float4 b = *(const float4*)&Bs[kk][tx << 2];
            float av[4] = {a.x, a.y, a.z, a.w};
            float bv[4] = {b.x, b.y, b.z, b.w};
            #pragma unroll
            for (int i = 0; i < 4; i++)
                #pragma unroll
                for (int j = 0; j < 4; j++)
                    acc[i][j] += av[i] * bv[j];
        }
        __syncthreads();
    }
}

// Epilogue: optional per-col bias, optional elementwise add matrix (C2),
// optional rho, vectorized float4 store.
__device__ __forceinline__ void epilogue(
    float* __restrict__ Cout, int ldc,
    const float* __restrict__ bias, const float* __restrict__ addmat,
    int m0, int n0, float (&acc)[4][4], bool do_rho)
{
    const int tid = threadIdx.x;
    const int tx = tid & 15;
    const int ty = tid >> 4;
    const int nbase = n0 + (tx << 2);

    float bvals[4] = {0.f, 0.f, 0.f, 0.f};
    if (bias) {
        float4 bv = *(const float4*)(bias + nbase);
        bvals[0] = bv.x; bvals[1] = bv.y; bvals[2] = bv.z; bvals[3] = bv.w;
    }

    #pragma unroll
    for (int i = 0; i < 4; i++) {
        int m = m0 + (ty << 2) + i;
        float x[4];
        #pragma unroll
        for (int j = 0; j < 4; j++) x[j] = acc[i][j] + bvals[j];
        if (addmat) {
            float4 av = *(const float4*)(addmat + (size_t)m * ldc + nbase);
            x[0] += av.x; x[1] += av.y; x[2] += av.z; x[3] += av.w;
        }
        if (do_rho) {
            #pragma unroll
            for (int j = 0; j < 4; j++) x[j] = fminf(fmaxf(x[j], 0.f), 1.f);
        }
        float4 o = make_float4(x[0], x[1], x[2], x[3]);
        *(float4*)(Cout + (size_t)m * ldc + nbase) = o;
    }
}

// ---------------------------------------------------------------------------
// One relaxation step, all three state updates fused into one grid.
// Block partition (288 blocks total):
//   [0, 32)    region A: s0' = rho(s1 W0^T + b0)        grid 4 x 8
//   [32, 160)  region B: s1' = rho(s2 W1^T + b1 + s0 W0) grid 4 x 32
//   [160, 288) region C: s2' = rho(C2 + s1 W1)           grid 4 x 32
// ---------------------------------------------------------------------------
__global__ void __launch_bounds__(256) ep_step_kernel(
    const float* __restrict__ s0, const float* __restrict__ s1,
    const float* __restrict__ s2,
    float* __restrict__ o0, float* __restrict__ o1, float* __restrict__ o2,
    const float* __restrict__ W0, const float* __restrict__ b0,
    const float* __restrict__ W1, const float* __restrict__ b1,
    const float* __restrict__ c2)
{
    __shared__ float As[BK][BM];
    __shared__ float Bs[BK][BN];
    float acc[4][4];
    #pragma unroll
    for (int i = 0; i < 4; i++)
        #pragma unroll
        for (int j = 0; j < 4; j++) acc[i][j] = 0.f;

    int blk = blockIdx.x;
    if (blk < 32) {
        int m0 = (blk >> 3) * BM;
        int n0 = (blk & 7) * BN;
        gemm_acc(s1, D1, W0, D1, true, D1, m0, n0, acc, As, Bs);
        epilogue(o0, D0, b0, nullptr, m0, n0, acc, true);
    } else if (blk < 160) {
        int l = blk - 32;
        int m0 = (l >> 5) * BM;
        int n0 = (l & 31) * BN;
        gemm_acc(s2, D2, W1, D2, true, D2, m0, n0, acc, As, Bs);
        gemm_acc(s0, D0, W0, D1, false, D0, m0, n0, acc, As, Bs);
        epilogue(o1, D1, b1, nullptr, m0, n0, acc, true);
    } else {
        int l = blk - 160;
        int m0 = (l >> 5) * BM;
        int n0 = (l & 31) * BN;
        gemm_acc(s1, D1, W1, D1, false, D1, m0, n0, acc, As, Bs);
        epilogue(o2, D2, nullptr, c2, m0, n0, acc, true);
    }
}

// C2 = data @ W2^T + b2   (256 x 2048, K = 4096), computed once per launch.
__global__ void __launch_bounds__(256) ep_c2_kernel(
    const float* __restrict__ data,
    const float* __restrict__ W2, const float* __restrict__ b2,
    float* __restrict__ c2)
{
    __shared__ float As[BK][BM];
    __shared__ float Bs[BK][BN];
    float acc[4][4];
    #pragma unroll
    for (int i = 0; i < 4; i++)
        #pragma unroll
        for (int j = 0; j < 4; j++) acc[i][j] = 0.f;

    int blk = blockIdx.x;          // 128 blocks: 4 x 32
    int m0 = (blk >> 5) * BM;
    int n0 = (blk & 31) * BN;
    gemm_acc(data, DIN, W2, DIN, true, DIN, m0, n0, acc, As, Bs);
    epilogue(c2, D2, b2, nullptr, m0, n0, acc, false);
}

extern "C" void kernel_launch(void* const* d_in, const int* in_sizes, int n_in,
                              void* d_out, int out_size)
{
    const float* data = (const float*)d_in[0];
    const float* in_s0 = (const float*)d_in[1];
    const float* in_s1 = (const float*)d_in[2];
    const float* in_s2 = (const float*)d_in[3];
    const float* W0 = (const float*)d_in[4];
    const float* b0 = (const float*)d_in[5];
    const float* W1 = (const float*)d_in[6];
    const float* b1 = (const float*)d_in[7];
    const float* W2 = (const float*)d_in[8];
    const float* b2 = (const float*)d_in[9];
    float* out = (float*)d_out;

    float *gs0, *gs1, *gs2, *gc2;
    cudaGetSymbolAddress((void**)&gs0, g_s0);
    cudaGetSymbolAddress((void**)&gs1, g_s1);
    cudaGetSymbolAddress((void**)&gs2, g_s2);
    cudaGetSymbolAddress((void**)&gc2, g_c2);

    // Hoisted: C2 = data @ W2^T + b2
    ep_c2_kernel<<<128, 256>>>(data, W2, b2, gc2);

    const float *i0 = in_s0, *i1 = in_s1, *i2 = in_s2;
    for (int t = 1; t <= T_STEPS; t++) {
        float *o0, *o1, *o2;
        if (t == T_STEPS) {
            // last step writes straight into d_out: [s0 | s1 | s2]
            o0 = out;
            o1 = out + (size_t)BATCH * D0;
            o2 = out + (size_t)BATCH * D0 + (size_t)BATCH * D1;
        } else {
            int p = t & 1;
            o0 = gs0 + (size_t)p * BATCH * D0;
            o1 = gs1 + (size_t)p * BATCH * D1;
            o2 = gs2 + (size_t)p * BATCH * D2;
        }
        ep_step_kernel<<<288, 256>>>(i0, i1, i2, o0, o1, o2,
                                     W0, b0, W1, b1, gc2);
        i0 = o0; i1 = o1; i2 = o2;
    }
}

// round 3
// speedup vs baseline: 1.2817x; 1.2817x over previous
#include <cuda_runtime.h>
#include <cuda_bf16.h>
#include <cstdint>
#include <cstddef>

// ---------------------------------------------------------------------------
// EP free-phase relaxation via mma.sync bf16 split-hi/lo (fp32-equivalent):
//   s0' = rho(s1 @ W0^T + b0)
//   s1' = rho(s2 @ W1^T + b1 + s0 @ W0)
//   s2' = rho(C2 + s1 @ W1),  C2 = data @ W2^T + b2  (hoisted)
// x = hi + lo (bf16 each); x*y ~= hi*hi' + hi*lo' + lo*hi'  (3 MMA passes)
// ---------------------------------------------------------------------------

#define BATCH 256
#define D0 512
#define D1 2048
#define D2 2048
#define DIN 4096
#define T_STEPS 20

#define BM 128
#define BN 128
#define BK 32
#define ROW_HALFS 40            // 32 + 8 pad  -> 80B row stride, conflict-free
#define ROW_BYTES (ROW_HALFS * 2)
#define MAT_BYTES (128 * ROW_BYTES)      // 10240
#define OFF_AH 0
#define OFF_AL (1 * MAT_BYTES)
#define OFF_BH (2 * MAT_BYTES)
#define OFF_BL (3 * MAT_BYTES)
#define STAGE_BYTES (4 * MAT_BYTES)      // 40960
#define DSMEM_BYTES (2 * STAGE_BYTES)    // 81920

// --------------------------- device scratch --------------------------------
__device__ __nv_bfloat16 g_W0h[D0 * D1],  g_W0l[D0 * D1];
__device__ __nv_bfloat16 g_W1h[D1 * D2],  g_W1l[D1 * D2];
__device__ __nv_bfloat16 g_W2h[D2 * DIN], g_W2l[D2 * DIN];
__device__ __nv_bfloat16 g_W0Th[D1 * D0], g_W0Tl[D1 * D0];
__device__ __nv_bfloat16 g_W1Th[D2 * D1], g_W1Tl[D2 * D1];
__device__ __nv_bfloat16 g_dh[BATCH * DIN], g_dl[BATCH * DIN];
__device__ __nv_bfloat16 g_s0h[2][BATCH * D0], g_s0l[2][BATCH * D0];
__device__ __nv_bfloat16 g_s1h[2][BATCH * D1], g_s1l[2][BATCH * D1];
__device__ __nv_bfloat16 g_s2h[2][BATCH * D2], g_s2l[2][BATCH * D2];
__device__ float g_c2[BATCH * D2];

// ------------------------------ PTX helpers --------------------------------
__device__ __forceinline__ uint32_t smem_u32(const void* p) {
    uint32_t a;
    asm("{ .reg .u64 t; cvta.to.shared.u64 t, %1; cvt.u32.u64 %0, t; }"
        : "=r"(a) : "l"(p));
    return a;
}
__device__ __forceinline__ void cp16(uint32_t dst, const void* src) {
    asm volatile("cp.async.cg.shared.global [%0], [%1], 16;"
                 :: "r"(dst), "l"(src) : "memory");
}
__device__ __forceinline__ void cp_commit() {
    asm volatile("cp.async.commit_group;" ::: "memory");
}
template <int N>
__device__ __forceinline__ void cp_wait() {
    asm volatile("cp.async.wait_group %0;" :: "n"(N) : "memory");
}
__device__ __forceinline__ void ldm_x4(uint32_t (&r)[4], uint32_t addr) {
    asm volatile("ldmatrix.sync.aligned.m8n8.x4.shared.b16 {%0,%1,%2,%3}, [%4];"
                 : "=r"(r[0]), "=r"(r[1]), "=r"(r[2]), "=r"(r[3]) : "r"(addr));
}
__device__ __forceinline__ void mma_bf16(float (&d)[4], const uint32_t (&a)[4],
                                         uint32_t b0, uint32_t b1) {
    asm volatile(
        "mma.sync.aligned.m16n8k16.row.col.f32.bf16.bf16.f32 "
        "{%0,%1,%2,%3}, {%4,%5,%6,%7}, {%8,%9}, {%0,%1,%2,%3};"
        : "+f"(d[0]), "+f"(d[1]), "+f"(d[2]), "+f"(d[3])
        : "r"(a[0]), "r"(a[1]), "r"(a[2]), "r"(a[3]), "r"(b0), "r"(b1));
}

// ---------------------------------------------------------------------------
// Stage loader: Ah/Al rows [m0,m0+128) x k[k0,k0+32), Bh/Bl rows [n0,n0+128).
// 256 threads, each does 2 16B chunks per matrix (8 cp.async total).
// ---------------------------------------------------------------------------
__device__ __forceinline__ void load_stage(
    uint32_t sb,
    const __nv_bfloat16* __restrict__ Ah, const __nv_bfloat16* __restrict__ Al,
    int lda, int m0,
    const __nv_bfloat16* __restrict__ Bh, const __nv_bfloat16* __restrict__ Bl,
    int ldb, int n0, int k0)
{
    int tid = threadIdx.x;
    int r = tid >> 1;                        // 0..127
    int cb = (tid & 1) * 2;                  // chunk base 0 or 2
    uint32_t rowoff = (uint32_t)r * ROW_BYTES;
    const __nv_bfloat16* pah = Ah + (size_t)(m0 + r) * lda + k0;
    const __nv_bfloat16* pal = Al + (size_t)(m0 + r) * lda + k0;
    const __nv_bfloat16* pbh = Bh + (size_t)(n0 + r) * ldb + k0;
    const __nv_bfloat16* pbl = Bl + (size_t)(n0 + r) * ldb + k0;
    #pragma unroll
    for (int j = 0; j < 2; j++) {
        int c = cb + j;
        uint32_t d = rowoff + (uint32_t)c * 16;
        cp16(sb + OFF_AH + d, pah + c * 8);
        cp16(sb + OFF_AL + d, pal + c * 8);
        cp16(sb + OFF_BH + d, pbh + c * 8);
        cp16(sb + OFF_BL + d, pbl + c * 8);
    }
}

// ---------------------------------------------------------------------------
// Compute one BK=32 stage: 2 x k16 steps, 3-pass hi/lo MMAs.
// Warp grid 2x4, warp tile 64x32, acc[4][4][4].
// ---------------------------------------------------------------------------
__device__ __forceinline__ void compute_stage(uint32_t sb, float (&acc)[4][4][4])
{
    int tid = threadIdx.x;
    int lane = tid & 31, wid = tid >> 5;
    int wm = wid >> 2, wn = wid & 3;
    int lr = lane & 15, lc = lane >> 4;
    uint32_t a_base = (uint32_t)(wm * 64 + lr) * ROW_BYTES + (uint32_t)lc * 16;
    uint32_t b_base = (uint32_t)(wn * 32 + lr) * ROW_BYTES + (uint32_t)lc * 16;

    #pragma unroll
    for (int kk = 0; kk < 2; kk++) {
        uint32_t koff = (uint32_t)kk * 32;
        uint32_t ah[4][4], al[4][4], bh[2][4], bl[2][4];
        #pragma unroll
        for (int mi = 0; mi < 4; mi++) {
            uint32_t o = a_base + (uint32_t)mi * (16 * ROW_BYTES) + koff;
            ldm_x4(ah[mi], sb + OFF_AH + o);
            ldm_x4(al[mi], sb + OFF_AL + o);
        }
        #pragma unroll
        for (int p = 0; p < 2; p++) {
            uint32_t o = b_base + (uint32_t)p * (16 * ROW_BYTES) + koff;
            ldm_x4(bh[p], sb + OFF_BH + o);
            ldm_x4(bl[p], sb + OFF_BL + o);
        }
        #pragma unroll
        for (int mi = 0; mi < 4; mi++) {
            #pragma unroll
            for (int ni = 0; ni < 4; ni++) {
                int p = ni >> 1, q = ni & 1;
                uint32_t bh0 = bh[p][q], bh1 = bh[p][q + 2];
                mma_bf16(acc[mi][ni], ah[mi], bh0, bh1);
                mma_bf16(acc[mi][ni], ah[mi], bl[p][q], bl[p][q + 2]);
                mma_bf16(acc[mi][ni], al[mi], bh0, bh1);
            }
        }
    }
}

// Pipelined K-loop accumulating into acc (can be called multiple times).
__device__ void gemm_segment(
    uint32_t sbase,
    const __nv_bfloat16* Ah, const __nv_bfloat16* Al, int lda, int m0,
    const __nv_bfloat16* Bh, const __nv_bfloat16* Bl, int ldb, int n0,
    int K, float (&acc)[4][4][4])
{
    int nst = K / BK;
    load_stage(sbase, Ah, Al, lda, m0, Bh, Bl, ldb, n0, 0);
    cp_commit();
    for (int s = 0; s < nst; s++) {
        if (s + 1 < nst) {
            load_stage(sbase + (uint32_t)((s + 1) & 1) * STAGE_BYTES,
                       Ah, Al, lda, m0, Bh, Bl, ldb, n0, (s + 1) * BK);
            cp_commit();
            cp_wait<1>();
        } else {
            cp_wait<0>();
        }
        __syncthreads();
        compute_stage(sbase + (uint32_t)(s & 1) * STAGE_BYTES, acc);
        __syncthreads();
    }
}

// ---------------------------------------------------------------------------
// Epilogue straight from fragments: bias / C2-add / rho, write bf16 hi/lo
// (for next step) and optionally fp32 (final output / C2).
// ---------------------------------------------------------------------------
__device__ void epilogue(
    float (&acc)[4][4][4], int m0, int n0, int outw,
    const float* __restrict__ bias, const float* __restrict__ addm, bool do_rho,
    __nv_bfloat16* __restrict__ oh, __nv_bfloat16* __restrict__ ol,
    float* __restrict__ of)
{
    int tid = threadIdx.x;
    int lane = tid & 31, wid = tid >> 5;
    int wm = wid >> 2, wn = wid & 3;
    int g = lane >> 2, t = lane & 3;

    #pragma unroll
    for (int mi = 0; mi < 4; mi++) {
        #pragma unroll
        for (int ni = 0; ni < 4; ni++) {
            int nc = n0 + wn * 32 + ni * 8 + 2 * t;
            float bv0 = 0.f, bv1 = 0.f;
            if (bias) { bv0 = bias[nc]; bv1 = bias[nc + 1]; }
            #pragma unroll
            for (int h = 0; h < 2; h++) {
                int mr = m0 + wm * 64 + mi * 16 + g + h * 8;
                float v0 = acc[mi][ni][2 * h + 0] + bv0;
                float v1 = acc[mi][ni][2 * h + 1] + bv1;
                size_t o = (size_t)mr * outw + nc;
                if (addm) { v0 += addm[o]; v1 += addm[o + 1]; }
                if (do_rho) {
                    v0 = fminf(fmaxf(v0, 0.f), 1.f);
                    v1 = fminf(fmaxf(v1, 0.f), 1.f);
                }
                if (oh) {
                    __nv_bfloat16 h0 = __float2bfloat16(v0);
                    __nv_bfloat16 h1 = __float2bfloat16(v1);
                    __nv_bfloat162 hp; hp.x = h0; hp.y = h1;
                    __nv_bfloat162 lp;
                    lp.x = __float2bfloat16(v0 - __bfloat162float(h0));
                    lp.y = __float2bfloat16(v1 - __bfloat162float(h1));
                    *(__nv_bfloat162*)&oh[o] = hp;
                    *(__nv_bfloat162*)&ol[o] = lp;
                }
                if (of) *(float2*)&of[o] = make_float2(v0, v1);
            }
        }
    }
}

// ---------------------------------------------------------------------------
// One relaxation step, fused. 72 CTAs:
//  [0,8)   s0' tiles 2x4    [8,40) s1' 2x16    [40,72) s2' 2x16
// ---------------------------------------------------------------------------
__global__ void __launch_bounds__(256) ep_step_kernel(
    const __nv_bfloat16* s0h, const __nv_bfloat16* s0l,
    const __nv_bfloat16* s1h, const __nv_bfloat16* s1l,
    const __nv_bfloat16* s2h, const __nv_bfloat16* s2l,
    __nv_bfloat16* o0h, __nv_bfloat16* o0l,
    __nv_bfloat16* o1h, __nv_bfloat16* o1l,
    __nv_bfloat16* o2h, __nv_bfloat16* o2l,
    const __nv_bfloat16* W0h, const __nv_bfloat16* W0l,
    const __nv_bfloat16* W1h, const __nv_bfloat16* W1l,
    const __nv_bfloat16* W0Th, const __nv_bfloat16* W0Tl,
    const __nv_bfloat16* W1Th, const __nv_bfloat16* W1Tl,
    const float* b0, const float* b1, const float* c2,
    float* f0, float* f1, float* f2)
{
    extern __shared__ char dyn[];
    uint32_t sb = smem_u32(dyn);

    float acc[4][4][4];
    #pragma unroll
    for (int i = 0; i < 4; i++)
        #pragma unroll
        for (int j = 0; j < 4; j++)
            #pragma unroll
            for (int k = 0; k < 4; k++) acc[i][j][k] = 0.f;

    int blk = blockIdx.x;
    if (blk < 8) {
        int m0 = (blk >> 2) * BM, n0 = (blk & 3) * BN;
        gemm_segment(sb, s1h, s1l, D1, m0, W0h, W0l, D1, n0, D1, acc);
        epilogue(acc, m0, n0, D0, b0, nullptr, true, o0h, o0l, f0);
    } else if (blk < 40) {
        int l = blk - 8;
        int m0 = (l >> 4) * BM, n0 = (l & 15) * BN;
        gemm_segment(sb, s2h, s2l, D2, m0, W1h, W1l, D2, n0, D2, acc);
        gemm_segment(sb, s0h, s0l, D0, m0, W0Th, W0Tl, D0, n0, D0, acc);
        epilogue(acc, m0, n0, D1, b1, nullptr, true, o1h, o1l, f1);
    } else {
        int l = blk - 40;
        int m0 = (l >> 4) * BM, n0 = (l & 15) * BN;
        gemm_segment(sb, s1h, s1l, D1, m0, W1Th, W1Tl, D1, n0, D1, acc);
        epilogue(acc, m0, n0, D2, nullptr, c2, true, o2h, o2l, f2);
    }
}

// C2 = data @ W2^T + b2  (fp32 out only). 32 CTAs: 2x16, K=4096.
__global__ void __launch_bounds__(256) ep_c2_kernel(
    const __nv_bfloat16* dh, const __nv_bfloat16* dl,
    const __nv_bfloat16* W2h, const __nv_bfloat16* W2l,
    const float* b2, float* c2)
{
    extern __shared__ char dyn[];
    uint32_t sb = smem_u32(dyn);

    float acc[4][4][4];
    #pragma unroll
    for (int i = 0; i < 4; i++)
        #pragma unroll
        for (int j = 0; j < 4; j++)
            #pragma unroll
            for (int k = 0; k < 4; k++) acc[i][j][k] = 0.f;

    int blk = blockIdx.x;
    int m0 = (blk >> 4) * BM, n0 = (blk & 15) * BN;
    gemm_segment(sb, dh, dl, DIN, m0, W2h, W2l, DIN, n0, DIN, acc);
    epilogue(acc, m0, n0, D2, b2, nullptr, false, nullptr, nullptr, c2);
}

// ------------------------- conversion kernels ------------------------------
__global__ void convert_split(const float* __restrict__ x,
                              __nv_bfloat16* __restrict__ h,
                              __nv_bfloat16* __restrict__ l, int n)
{
    int i = blockIdx.x * blockDim.x + threadIdx.x;
    if (i < n) {
        float v = x[i];
        __nv_bfloat16 hi = __float2bfloat16(v);
        h[i] = hi;
        l[i] = __float2bfloat16(v - __bfloat162float(hi));
    }
}

// W (R x C) -> T (C x R), split into bf16 hi/lo. 32x32 tiles, 256 threads.
__global__ void transpose_split(const float* __restrict__ W, int R, int C,
                                __nv_bfloat16* __restrict__ Th,
                                __nv_bfloat16* __restrict__ Tl)
{
    __shared__ float tile[32][33];
    int tx = threadIdx.x & 31, ty = threadIdx.x >> 5;   // 32 x 8
    int c0 = blockIdx.x * 32, r0 = blockIdx.y * 32;
    #pragma unroll
    for (int k = 0; k < 4; k++)
        tile[ty + 8 * k][tx] = W[(size_t)(r0 + ty + 8 * k) * C + c0 + tx];
    __syncthreads();
    #pragma unroll
    for (int k = 0; k < 4; k++) {
        float v = tile[tx][ty + 8 * k];
        __nv_bfloat16 hi = __float2bfloat16(v);
        size_t o = (size_t)(c0 + ty + 8 * k) * R + r0 + tx;
        Th[o] = hi;
        Tl[o] = __float2bfloat16(v - __bfloat162float(hi));
    }
}

// ------------------------------- host side ---------------------------------
static inline void* sym(const void* s) {
    void* p = nullptr;
    cudaGetSymbolAddress(&p, s);
    return p;
}

extern "C" void kernel_launch(void* const* d_in, const int* in_sizes, int n_in,
                              void* d_out, int out_size)
{
    const float* data = (const float*)d_in[0];
    const float* in_s0 = (const float*)d_in[1];
    const float* in_s1 = (const float*)d_in[2];
    const float* in_s2 = (const float*)d_in[3];
    const float* W0 = (const float*)d_in[4];
    const float* b0 = (const float*)d_in[5];
    const float* W1 = (const float*)d_in[6];
    const float* b1 = (const float*)d_in[7];
    const float* W2 = (const float*)d_in[8];
    const float* b2 = (const float*)d_in[9];
    float* out = (float*)d_out;

    cudaFuncSetAttribute(ep_step_kernel, cudaFuncAttributeMaxDynamicSharedMemorySize, DSMEM_BYTES);
    cudaFuncSetAttribute(ep_c2_kernel,  cudaFuncAttributeMaxDynamicSharedMemorySize, DSMEM_BYTES);

    __nv_bfloat16 *W0h = (__nv_bfloat16*)sym(g_W0h),  *W0l = (__nv_bfloat16*)sym(g_W0l);
    __nv_bfloat16 *W1h = (__nv_bfloat16*)sym(g_W1h),  *W1l = (__nv_bfloat16*)sym(g_W1l);
    __nv_bfloat16 *W2h = (__nv_bfloat16*)sym(g_W2h),  *W2l = (__nv_bfloat16*)sym(g_W2l);
    __nv_bfloat16 *W0Th = (__nv_bfloat16*)sym(g_W0Th), *W0Tl = (__nv_bfloat16*)sym(g_W0Tl);
    __nv_bfloat16 *W1Th = (__nv_bfloat16*)sym(g_W1Th), *W1Tl = (__nv_bfloat16*)sym(g_W1Tl);
    __nv_bfloat16 *dh = (__nv_bfloat16*)sym(g_dh),    *dl = (__nv_bfloat16*)sym(g_dl);
    __nv_bfloat16 *s0h = (__nv_bfloat16*)sym(g_s0h),  *s0l = (__nv_bfloat16*)sym(g_s0l);
    __nv_bfloat16 *s1h = (__nv_bfloat16*)sym(g_s1h),  *s1l = (__nv_bfloat16*)sym(g_s1l);
    __nv_bfloat16 *s2h = (__nv_bfloat16*)sym(g_s2h),  *s2l = (__nv_bfloat16*)sym(g_s2l);
    float* c2 = (float*)sym(g_c2);

    const int THR = 256;
    auto cvt = [&](const float* x, __nv_bfloat16* h, __nv_bfloat16* l, int n) {
        convert_split<<<(n + THR - 1) / THR, THR>>>(x, h, l, n);
    };
    cvt(W0, W0h, W0l, D0 * D1);
    cvt(W1, W1h, W1l, D1 * D2);
    cvt(W2, W2h, W2l, D2 * DIN);
    cvt(data, dh, dl, BATCH * DIN);
    cvt(in_s0, s0h, s0l, BATCH * D0);
    cvt(in_s1, s1h, s1l, BATCH * D1);
    cvt(in_s2, s2h, s2l, BATCH * D2);

    transpose_split<<<dim3(D1 / 32, D0 / 32), 256>>>(W0, D0, D1, W0Th, W0Tl);
    transpose_split<<<dim3(D2 / 32, D1 / 32), 256>>>(W1, D1, D2, W1Th, W1Tl);

    ep_c2_kernel<<<32, 256, DSMEM_BYTES>>>(dh, dl, W2h, W2l, b2, c2);

    for (int t = 1; t <= T_STEPS; t++) {
        int pi = (t - 1) & 1, po = t & 1;
        size_t n0e = (size_t)BATCH * D0, n1e = (size_t)BATCH * D1, n2e = (size_t)BATCH * D2;
        float *f0 = nullptr, *f1 = nullptr, *f2 = nullptr;
        if (t == T_STEPS) {
            f0 = out;
            f1 = out + n0e;
            f2 = out + n0e + n1e;
        }
        ep_step_kernel<<<72, 256, DSMEM_BYTES>>>(
            s0h + pi * n0e, s0l + pi * n0e,
            s1h + pi * n1e, s1l + pi * n1e,
            s2h + pi * n2e, s2l + pi * n2e,
            s0h + po * n0e, s0l + po * n0e,
            s1h + po * n1e, s1l + po * n1e,
            s2h + po * n2e, s2l + po * n2e,
            W0h, W0l, W1h, W1l, W0Th, W0Tl, W1Th, W1Tl,
            b0, b1, c2, f0, f1, f2);
    }
}

// round 4
// speedup vs baseline: 1.7828x; 1.3909x over previous
#include <cuda_runtime.h>
#include <cuda_bf16.h>
#include <cstdint>
#include <cstddef>

// ---------------------------------------------------------------------------
// EP free-phase relaxation via mma.sync bf16 split-hi/lo (fp32-equivalent):
//   s0' = rho(s1 @ W0^T + b0)
//   s1' = rho(s2 @ W1^T + b1 + s0 @ W0)
//   s2' = rho(C2 + s1 @ W1),  C2 = data @ W2^T + b2  (hoisted)
// 144-CTA one-wave step kernel, 4-deep cp.async pipeline, 1 sync/stage.
// ---------------------------------------------------------------------------

#define BATCH 256
#define D0 512
#define D1 2048
#define D2 2048
#define DIN 4096
#define T_STEPS 20

#define BM 128
#define BN 64
#define BK 32
#define DEPTH 4
#define ROW_HALFS 40            // 32 + 8 pad  -> 80B row stride, conflict-free
#define ROW_BYTES (ROW_HALFS * 2)
#define A_MAT (128 * ROW_BYTES)          // 10240
#define B_MAT (64 * ROW_BYTES)           // 5120
#define OFF_AH 0
#define OFF_AL (A_MAT)
#define OFF_BH (2 * A_MAT)
#define OFF_BL (2 * A_MAT + B_MAT)
#define STAGE_BYTES (2 * A_MAT + 2 * B_MAT)   // 30720
#define DSMEM_BYTES (DEPTH * STAGE_BYTES)     // 122880

// --------------------------- device scratch --------------------------------
__device__ __nv_bfloat16 g_W0h[D0 * D1],  g_W0l[D0 * D1];
__device__ __nv_bfloat16 g_W1h[D1 * D2],  g_W1l[D1 * D2];
__device__ __nv_bfloat16 g_W2h[D2 * DIN], g_W2l[D2 * DIN];
__device__ __nv_bfloat16 g_W0Th[D1 * D0], g_W0Tl[D1 * D0];
__device__ __nv_bfloat16 g_W1Th[D2 * D1], g_W1Tl[D2 * D1];
__device__ __nv_bfloat16 g_dh[BATCH * DIN], g_dl[BATCH * DIN];
__device__ __nv_bfloat16 g_s0h[2][BATCH * D0], g_s0l[2][BATCH * D0];
__device__ __nv_bfloat16 g_s1h[2][BATCH * D1], g_s1l[2][BATCH * D1];
__device__ __nv_bfloat16 g_s2h[2][BATCH * D2], g_s2l[2][BATCH * D2];
__device__ float g_c2[BATCH * D2];

// ------------------------------ PTX helpers --------------------------------
__device__ __forceinline__ uint32_t smem_u32(const void* p) {
    uint32_t a;
    asm("{ .reg .u64 t; cvta.to.shared.u64 t, %1; cvt.u32.u64 %0, t; }"
        : "=r"(a) : "l"(p));
    return a;
}
__device__ __forceinline__ void cp16(uint32_t dst, const void* src) {
    asm volatile("cp.async.cg.shared.global [%0], [%1], 16;"
                 :: "r"(dst), "l"(src) : "memory");
}
__device__ __forceinline__ void cp_commit() {
    asm volatile("cp.async.commit_group;" ::: "memory");
}
template <int N>
__device__ __forceinline__ void cp_wait() {
    asm volatile("cp.async.wait_group %0;" :: "n"(N) : "memory");
}
__device__ __forceinline__ void ldm_x4(uint32_t (&r)[4], uint32_t addr) {
    asm volatile("ldmatrix.sync.aligned.m8n8.x4.shared.b16 {%0,%1,%2,%3}, [%4];"
                 : "=r"(r[0]), "=r"(r[1]), "=r"(r[2]), "=r"(r[3]) : "r"(addr));
}
__device__ __forceinline__ void mma_bf16(float (&d)[4], const uint32_t (&a)[4],
                                         uint32_t b0, uint32_t b1) {
    asm volatile(
        "mma.sync.aligned.m16n8k16.row.col.f32.bf16.bf16.f32 "
        "{%0,%1,%2,%3}, {%4,%5,%6,%7}, {%8,%9}, {%0,%1,%2,%3};"
        : "+f"(d[0]), "+f"(d[1]), "+f"(d[2]), "+f"(d[3])
        : "r"(a[0]), "r"(a[1]), "r"(a[2]), "r"(a[3]), "r"(b0), "r"(b1));
}

// ---------------------------------------------------------------------------
// Stage loader: A rows [m0,m0+128) x k[k0,k0+32), B rows [n0,n0+64).
// 128 threads, 12 cp16 each (8 for A hi/lo, 4 for B hi/lo).
// ---------------------------------------------------------------------------
__device__ __forceinline__ void load_stage(
    uint32_t sb,
    const __nv_bfloat16* __restrict__ Ah, const __nv_bfloat16* __restrict__ Al,
    int lda, int m0,
    const __nv_bfloat16* __restrict__ Bh, const __nv_bfloat16* __restrict__ Bl,
    int ldb, int n0, int k0)
{
    int t = threadIdx.x;
    // A: one row per thread, 4 chunks of 16B each, hi + lo
    {
        uint32_t rowoff = (uint32_t)t * ROW_BYTES;
        const __nv_bfloat16* pah = Ah + (size_t)(m0 + t) * lda + k0;
        const __nv_bfloat16* pal = Al + (size_t)(m0 + t) * lda + k0;
        #pragma unroll
        for (int c = 0; c < 4; c++) {
            uint32_t d = rowoff + (uint32_t)c * 16;
            cp16(sb + OFF_AH + d, pah + c * 8);
            cp16(sb + OFF_AL + d, pal + c * 8);
        }
    }
    // B: row = t>>1, two chunks selected by t&1, hi + lo
    {
        int rb = t >> 1, cb = (t & 1) * 2;
        uint32_t rowoff = (uint32_t)rb * ROW_BYTES;
        const __nv_bfloat16* pbh = Bh + (size_t)(n0 + rb) * ldb + k0;
        const __nv_bfloat16* pbl = Bl + (size_t)(n0 + rb) * ldb + k0;
        #pragma unroll
        for (int j = 0; j < 2; j++) {
            int c = cb + j;
            uint32_t d = rowoff + (uint32_t)c * 16;
            cp16(sb + OFF_BH + d, pbh + c * 8);
            cp16(sb + OFF_BL + d, pbl + c * 8);
        }
    }
}

// ---------------------------------------------------------------------------
// Compute one BK=32 stage: 2 x k16 steps, 3-pass hi/lo MMAs.
// 4 warps in 2x2 grid, warp tile 64x32, acc[4][4][4] (validated mapping).
// ---------------------------------------------------------------------------
__device__ __forceinline__ void compute_stage(uint32_t sb, float (&acc)[4][4][4])
{
    int tid = threadIdx.x;
    int lane = tid & 31, wid = tid >> 5;
    int wm = wid >> 1, wn = wid & 1;
    int lr = lane & 15, lc = lane >> 4;
    uint32_t a_base = (uint32_t)(wm * 64 + lr) * ROW_BYTES + (uint32_t)lc * 16;
    uint32_t b_base = (uint32_t)(wn * 32 + lr) * ROW_BYTES + (uint32_t)lc * 16;

    #pragma unroll
    for (int kk = 0; kk < 2; kk++) {
        uint32_t koff = (uint32_t)kk * 32;
        uint32_t ah[4][4], al[4][4], bh[2][4], bl[2][4];
        #pragma unroll
        for (int mi = 0; mi < 4; mi++) {
            uint32_t o = a_base + (uint32_t)mi * (16 * ROW_BYTES) + koff;
            ldm_x4(ah[mi], sb + OFF_AH + o);
            ldm_x4(al[mi], sb + OFF_AL + o);
        }
        #pragma unroll
        for (int p = 0; p < 2; p++) {
            uint32_t o = b_base + (uint32_t)p * (16 * ROW_BYTES) + koff;
            ldm_x4(bh[p], sb + OFF_BH + o);
            ldm_x4(bl[p], sb + OFF_BL + o);
        }
        #pragma unroll
        for (int mi = 0; mi < 4; mi++) {
            #pragma unroll
            for (int ni = 0; ni < 4; ni++) {
                int p = ni >> 1, q = ni & 1;
                uint32_t bh0 = bh[p][q], bh1 = bh[p][q + 2];
                mma_bf16(acc[mi][ni], ah[mi], bh0, bh1);
                mma_bf16(acc[mi][ni], ah[mi], bl[p][q], bl[p][q + 2]);
                mma_bf16(acc[mi][ni], al[mi], bh0, bh1);
            }
        }
    }
}

// ---------------------------------------------------------------------------
// Pipelined K-loop accumulating into acc (callable multiple times; cp-group
// accounting stays consistent across segments: one commit per iteration).
// ---------------------------------------------------------------------------
__device__ void gemm_segment(
    uint32_t sbase,
    const __nv_bfloat16* Ah, const __nv_bfloat16* Al, int lda, int m0,
    const __nv_bfloat16* Bh, const __nv_bfloat16* Bl, int ldb, int n0,
    int K, float (&acc)[4][4][4])
{
    int nst = K / BK;
    #pragma unroll
    for (int p = 0; p < DEPTH - 1; p++) {
        if (p < nst)
            load_stage(sbase + (uint32_t)p * STAGE_BYTES,
                       Ah, Al, lda, m0, Bh, Bl, ldb, n0, p * BK);
        cp_commit();
    }
    for (int s = 0; s < nst; s++) {
        cp_wait<DEPTH - 2>();
        __syncthreads();
        int nf = s + DEPTH - 1;
        if (nf < nst)
            load_stage(sbase + (uint32_t)(nf % DEPTH) * STAGE_BYTES,
                       Ah, Al, lda, m0, Bh, Bl, ldb, n0, nf * BK);
        cp_commit();
        compute_stage(sbase + (uint32_t)(s % DEPTH) * STAGE_BYTES, acc);
    }
}

// ---------------------------------------------------------------------------
// Epilogue straight from fragments: bias / C2-add / rho, write bf16 hi/lo
// (next step's operands) and/or fp32 (final output / C2).
// ---------------------------------------------------------------------------
__device__ void epilogue(
    float (&acc)[4][4][4], int m0, int n0, int outw,
    const float* __restrict__ bias, const float* __restrict__ addm, bool do_rho,
    __nv_bfloat16* __restrict__ oh, __nv_bfloat16* __restrict__ ol,
    float* __restrict__ of)
{
    int tid = threadIdx.x;
    int lane = tid & 31, wid = tid >> 5;
    int wm = wid >> 1, wn = wid & 1;
    int g = lane >> 2, t = lane & 3;

    #pragma unroll
    for (int mi = 0; mi < 4; mi++) {
        #pragma unroll
        for (int ni = 0; ni < 4; ni++) {
            int nc = n0 + wn * 32 + ni * 8 + 2 * t;
            float bv0 = 0.f, bv1 = 0.f;
            if (bias) { bv0 = bias[nc]; bv1 = bias[nc + 1]; }
            #pragma unroll
            for (int h = 0; h < 2; h++) {
                int mr = m0 + wm * 64 + mi * 16 + g + h * 8;
                float v0 = acc[mi][ni][2 * h + 0] + bv0;
                float v1 = acc[mi][ni][2 * h + 1] + bv1;
                size_t o = (size_t)mr * outw + nc;
                if (addm) {
                    float2 av = *(const float2*)&addm[o];
                    v0 += av.x; v1 += av.y;
                }
                if (do_rho) {
                    v0 = fminf(fmaxf(v0, 0.f), 1.f);
                    v1 = fminf(fmaxf(v1, 0.f), 1.f);
                }
                if (oh) {
                    __nv_bfloat16 h0 = __float2bfloat16(v0);
                    __nv_bfloat16 h1 = __float2bfloat16(v1);
                    __nv_bfloat162 hp; hp.x = h0; hp.y = h1;
                    __nv_bfloat162 lp;
                    lp.x = __float2bfloat16(v0 - __bfloat162float(h0));
                    lp.y = __float2bfloat16(v1 - __bfloat162float(h1));
                    *(__nv_bfloat162*)&oh[o] = hp;
                    *(__nv_bfloat162*)&ol[o] = lp;
                }
                if (of) *(float2*)&of[o] = make_float2(v0, v1);
            }
        }
    }
}

// ---------------------------------------------------------------------------
// One relaxation step, fused. 144 CTAs (one full wave):
//  [0,16)    s0' tiles 2x8     [16,80)  s1' 2x32     [80,144) s2' 2x32
// ---------------------------------------------------------------------------
__global__ void __launch_bounds__(128, 1) ep_step_kernel(
    const __nv_bfloat16* s0h, const __nv_bfloat16* s0l,
    const __nv_bfloat16* s1h, const __nv_bfloat16* s1l,
    const __nv_bfloat16* s2h, const __nv_bfloat16* s2l,
    __nv_bfloat16* o0h, __nv_bfloat16* o0l,
    __nv_bfloat16* o1h, __nv_bfloat16* o1l,
    __nv_bfloat16* o2h, __nv_bfloat16* o2l,
    const __nv_bfloat16* W0h, const __nv_bfloat16* W0l,
    const __nv_bfloat16* W1h, const __nv_bfloat16* W1l,
    const __nv_bfloat16* W0Th, const __nv_bfloat16* W0Tl,
    const __nv_bfloat16* W1Th, const __nv_bfloat16* W1Tl,
    const float* b0, const float* b1, const float* c2,
    float* f0, float* f1, float* f2)
{
    extern __shared__ char dyn[];
    uint32_t sb = smem_u32(dyn);

    float acc[4][4][4];
    #pragma unroll
    for (int i = 0; i < 4; i++)
        #pragma unroll
        for (int j = 0; j < 4; j++)
            #pragma unroll
            for (int k = 0; k < 4; k++) acc[i][j][k] = 0.f;

    int blk = blockIdx.x;
    if (blk < 16) {
        int m0 = (blk >> 3) * BM, n0 = (blk & 7) * BN;
        gemm_segment(sb, s1h, s1l, D1, m0, W0h, W0l, D1, n0, D1, acc);
        epilogue(acc, m0, n0, D0, b0, nullptr, true, o0h, o0l, f0);
    } else if (blk < 80) {
        int l = blk - 16;
        int m0 = (l >> 5) * BM, n0 = (l & 31) * BN;
        gemm_segment(sb, s2h, s2l, D2, m0, W1h, W1l, D2, n0, D2, acc);
        gemm_segment(sb, s0h, s0l, D0, m0, W0Th, W0Tl, D0, n0, D0, acc);
        epilogue(acc, m0, n0, D1, b1, nullptr, true, o1h, o1l, f1);
    } else {
        int l = blk - 80;
        int m0 = (l >> 5) * BM, n0 = (l & 31) * BN;
        gemm_segment(sb, s1h, s1l, D1, m0, W1Th, W1Tl, D1, n0, D1, acc);
        epilogue(acc, m0, n0, D2, nullptr, c2, true, o2h, o2l, f2);
    }
}

// C2 = data @ W2^T + b2  (fp32 out only). 64 CTAs: 2x32, K=4096.
__global__ void __launch_bounds__(128, 1) ep_c2_kernel(
    const __nv_bfloat16* dh, const __nv_bfloat16* dl,
    const __nv_bfloat16* W2h, const __nv_bfloat16* W2l,
    const float* b2, float* c2)
{
    extern __shared__ char dyn[];
    uint32_t sb = smem_u32(dyn);

    float acc[4][4][4];
    #pragma unroll
    for (int i = 0; i < 4; i++)
        #pragma unroll
        for (int j = 0; j < 4; j++)
            #pragma unroll
            for (int k = 0; k < 4; k++) acc[i][j][k] = 0.f;

    int blk = blockIdx.x;
    int m0 = (blk >> 5) * BM, n0 = (blk & 31) * BN;
    gemm_segment(sb, dh, dl, DIN, m0, W2h, W2l, DIN, n0, DIN, acc);
    epilogue(acc, m0, n0, D2, b2, nullptr, false, nullptr, nullptr, c2);
}

// ------------------------- conversion kernels ------------------------------
__global__ void convert_split(const float* __restrict__ x,
                              __nv_bfloat16* __restrict__ h,
                              __nv_bfloat16* __restrict__ l, int n)
{
    int i = blockIdx.x * blockDim.x + threadIdx.x;
    int idx = i * 4;
    if (idx < n) {
        float4 v = *(const float4*)&x[idx];
        __nv_bfloat16 h0 = __float2bfloat16(v.x), h1 = __float2bfloat16(v.y);
        __nv_bfloat16 h2 = __float2bfloat16(v.z), h3 = __float2bfloat16(v.w);
        __nv_bfloat162 hp0, hp1, lp0, lp1;
        hp0.x = h0; hp0.y = h1; hp1.x = h2; hp1.y = h3;
        lp0.x = __float2bfloat16(v.x - __bfloat162float(h0));
        lp0.y = __float2bfloat16(v.y - __bfloat162float(h1));
        lp1.x = __float2bfloat16(v.z - __bfloat162float(h2));
        lp1.y = __float2bfloat16(v.w - __bfloat162float(h3));
        *(__nv_bfloat162*)&h[idx] = hp0;
        *(__nv_bfloat162*)&h[idx + 2] = hp1;
        *(__nv_bfloat162*)&l[idx] = lp0;
        *(__nv_bfloat162*)&l[idx + 2] = lp1;
    }
}

// W (R x C) -> T (C x R), split into bf16 hi/lo. 32x32 tiles, 256 threads.
__global__ void transpose_split(const float* __restrict__ W, int R, int C,
                                __nv_bfloat16* __restrict__ Th,
                                __nv_bfloat16* __restrict__ Tl)
{
    __shared__ float tile[32][33];
    int tx = threadIdx.x & 31, ty = threadIdx.x >> 5;   // 32 x 8
    int c0 = blockIdx.x * 32, r0 = blockIdx.y * 32;
    #pragma unroll
    for (int k = 0; k < 4; k++)
        tile[ty + 8 * k][tx] = W[(size_t)(r0 + ty + 8 * k) * C + c0 + tx];
    __syncthreads();
    #pragma unroll
    for (int k = 0; k < 4; k++) {
        float v = tile[tx][ty + 8 * k];
        __nv_bfloat16 hi = __float2bfloat16(v);
        size_t o = (size_t)(c0 + ty + 8 * k) * R + r0 + tx;
        Th[o] = hi;
        Tl[o] = __float2bfloat16(v - __bfloat162float(hi));
    }
}

// ------------------------------- host side ---------------------------------
static inline void* sym(const void* s) {
    void* p = nullptr;
    cudaGetSymbolAddress(&p, s);
    return p;
}

extern "C" void kernel_launch(void* const* d_in, const int* in_sizes, int n_in,
                              void* d_out, int out_size)
{
    const float* data = (const float*)d_in[0];
    const float* in_s0 = (const float*)d_in[1];
    const float* in_s1 = (const float*)d_in[2];
    const float* in_s2 = (const float*)d_in[3];
    const float* W0 = (const float*)d_in[4];
    const float* b0 = (const float*)d_in[5];
    const float* W1 = (const float*)d_in[6];
    const float* b1 = (const float*)d_in[7];
    const float* W2 = (const float*)d_in[8];
    const float* b2 = (const float*)d_in[9];
    float* out = (float*)d_out;

    cudaFuncSetAttribute(ep_step_kernel, cudaFuncAttributeMaxDynamicSharedMemorySize, DSMEM_BYTES);
    cudaFuncSetAttribute(ep_c2_kernel,  cudaFuncAttributeMaxDynamicSharedMemorySize, DSMEM_BYTES);

    __nv_bfloat16 *W0h = (__nv_bfloat16*)sym(g_W0h),  *W0l = (__nv_bfloat16*)sym(g_W0l);
    __nv_bfloat16 *W1h = (__nv_bfloat16*)sym(g_W1h),  *W1l = (__nv_bfloat16*)sym(g_W1l);
    __nv_bfloat16 *W2h = (__nv_bfloat16*)sym(g_W2h),  *W2l = (__nv_bfloat16*)sym(g_W2l);
    __nv_bfloat16 *W0Th = (__nv_bfloat16*)sym(g_W0Th), *W0Tl = (__nv_bfloat16*)sym(g_W0Tl);
    __nv_bfloat16 *W1Th = (__nv_bfloat16*)sym(g_W1Th), *W1Tl = (__nv_bfloat16*)sym(g_W1Tl);
    __nv_bfloat16 *dh = (__nv_bfloat16*)sym(g_dh),    *dl = (__nv_bfloat16*)sym(g_dl);
    __nv_bfloat16 *s0h = (__nv_bfloat16*)sym(g_s0h),  *s0l = (__nv_bfloat16*)sym(g_s0l);
    __nv_bfloat16 *s1h = (__nv_bfloat16*)sym(g_s1h),  *s1l = (__nv_bfloat16*)sym(g_s1l);
    __nv_bfloat16 *s2h = (__nv_bfloat16*)sym(g_s2h),  *s2l = (__nv_bfloat16*)sym(g_s2l);
    float* c2 = (float*)sym(g_c2);

    const int THR = 256;
    auto cvt = [&](const float* x, __nv_bfloat16* h, __nv_bfloat16* l, int n) {
        convert_split<<<(n / 4 + THR - 1) / THR, THR>>>(x, h, l, n);
    };
    cvt(W0, W0h, W0l, D0 * D1);
    cvt(W1, W1h, W1l, D1 * D2);
    cvt(W2, W2h, W2l, D2 * DIN);
    cvt(data, dh, dl, BATCH * DIN);
    cvt(in_s0, s0h, s0l, BATCH * D0);
    cvt(in_s1, s1h, s1l, BATCH * D1);
    cvt(in_s2, s2h, s2l, BATCH * D2);

    transpose_split<<<dim3(D1 / 32, D0 / 32), 256>>>(W0, D0, D1, W0Th, W0Tl);
    transpose_split<<<dim3(D2 / 32, D1 / 32), 256>>>(W1, D1, D2, W1Th, W1Tl);

    ep_c2_kernel<<<64, 128, DSMEM_BYTES>>>(dh, dl, W2h, W2l, b2, c2);

    for (int t = 1; t <= T_STEPS; t++) {
        int pi = (t - 1) & 1, po = t & 1;
        size_t n0e = (size_t)BATCH * D0, n1e = (size_t)BATCH * D1, n2e = (size_t)BATCH * D2;
        float *f0 = nullptr, *f1 = nullptr, *f2 = nullptr;
        bool last = (t == T_STEPS);
        if (last) {
            f0 = out;
            f1 = out + n0e;
            f2 = out + n0e + n1e;
        }
        ep_step_kernel<<<144, 128, DSMEM_BYTES>>>(
            s0h + pi * n0e, s0l + pi * n0e,
            s1h + pi * n1e, s1l + pi * n1e,
            s2h + pi * n2e, s2l + pi * n2e,
            last ? nullptr : s0h + po * n0e, last ? nullptr : s0l + po * n0e,
            last ? nullptr : s1h + po * n1e, last ? nullptr : s1l + po * n1e,
            last ? nullptr : s2h + po * n2e, last ? nullptr : s2l + po * n2e,
            W0h, W0l, W1h, W1l, W0Th, W0Tl, W1Th, W1Tl,
            b0, b1, c2, f0, f1, f2);
    }
}

// round 5
// speedup vs baseline: 2.2501x; 1.2621x over previous
#include <cuda_runtime.h>
#include <cuda_bf16.h>
#include <cstdint>
#include <cstddef>

// ---------------------------------------------------------------------------
// EP free-phase relaxation via mma.sync bf16 split-hi/lo (fp32-equivalent):
//   s0' = rho(s1 @ W0^T + b0)
//   s1' = rho(s2 @ W1^T + b1 + s0 @ W0)
//   s2' = rho(C2 + s1 @ W1),  C2 = data @ W2^T + b2  (hoisted)
// 144-CTA one-wave step kernel, 256 thr (8 warps 4x2, warp tile 32x32),
// 4-deep cp.async pipeline, 1 sync/stage.
// ---------------------------------------------------------------------------

#define BATCH 256
#define D0 512
#define D1 2048
#define D2 2048
#define DIN 4096
#define T_STEPS 20

#define BM 128
#define BN 64
#define BK 32
#define DEPTH 4
#define ROW_HALFS 40            // 32 + 8 pad  -> 80B row stride, conflict-free
#define ROW_BYTES (ROW_HALFS * 2)
#define A_MAT (128 * ROW_BYTES)          // 10240
#define B_MAT (64 * ROW_BYTES)           // 5120
#define OFF_AH 0
#define OFF_AL (A_MAT)
#define OFF_BH (2 * A_MAT)
#define OFF_BL (2 * A_MAT + B_MAT)
#define STAGE_BYTES (2 * A_MAT + 2 * B_MAT)   // 30720
#define DSMEM_BYTES (DEPTH * STAGE_BYTES)     // 122880

// --------------------------- device scratch --------------------------------
__device__ __nv_bfloat16 g_W0h[D0 * D1],  g_W0l[D0 * D1];
__device__ __nv_bfloat16 g_W1h[D1 * D2],  g_W1l[D1 * D2];
__device__ __nv_bfloat16 g_W2h[D2 * DIN], g_W2l[D2 * DIN];
__device__ __nv_bfloat16 g_W0Th[D1 * D0], g_W0Tl[D1 * D0];
__device__ __nv_bfloat16 g_W1Th[D2 * D1], g_W1Tl[D2 * D1];
__device__ __nv_bfloat16 g_dh[BATCH * DIN], g_dl[BATCH * DIN];
__device__ __nv_bfloat16 g_s0h[2][BATCH * D0], g_s0l[2][BATCH * D0];
__device__ __nv_bfloat16 g_s1h[2][BATCH * D1], g_s1l[2][BATCH * D1];
__device__ __nv_bfloat16 g_s2h[2][BATCH * D2], g_s2l[2][BATCH * D2];
__device__ float g_c2[BATCH * D2];

// ------------------------------ PTX helpers --------------------------------
__device__ __forceinline__ uint32_t smem_u32(const void* p) {
    uint32_t a;
    asm("{ .reg .u64 t; cvta.to.shared.u64 t, %1; cvt.u32.u64 %0, t; }"
        : "=r"(a) : "l"(p));
    return a;
}
__device__ __forceinline__ void cp16(uint32_t dst, const void* src) {
    asm volatile("cp.async.cg.shared.global [%0], [%1], 16;"
                 :: "r"(dst), "l"(src) : "memory");
}
__device__ __forceinline__ void cp_commit() {
    asm volatile("cp.async.commit_group;" ::: "memory");
}
template <int N>
__device__ __forceinline__ void cp_wait() {
    asm volatile("cp.async.wait_group %0;" :: "n"(N) : "memory");
}
__device__ __forceinline__ void ldm_x4(uint32_t (&r)[4], uint32_t addr) {
    asm volatile("ldmatrix.sync.aligned.m8n8.x4.shared.b16 {%0,%1,%2,%3}, [%4];"
                 : "=r"(r[0]), "=r"(r[1]), "=r"(r[2]), "=r"(r[3]) : "r"(addr));
}
__device__ __forceinline__ void mma_bf16(float (&d)[4], const uint32_t (&a)[4],
                                         uint32_t b0, uint32_t b1) {
    asm volatile(
        "mma.sync.aligned.m16n8k16.row.col.f32.bf16.bf16.f32 "
        "{%0,%1,%2,%3}, {%4,%5,%6,%7}, {%8,%9}, {%0,%1,%2,%3};"
        : "+f"(d[0]), "+f"(d[1]), "+f"(d[2]), "+f"(d[3])
        : "r"(a[0]), "r"(a[1]), "r"(a[2]), "r"(a[3]), "r"(b0), "r"(b1));
}

// ---------------------------------------------------------------------------
// Stage loader: A rows [m0,m0+128) x k[k0,k0+32), B rows [n0,n0+64).
// 256 threads, 6 cp16 each (4 for A hi/lo, 2 for B hi/lo).
// ---------------------------------------------------------------------------
__device__ __forceinline__ void load_stage(
    uint32_t sb,
    const __nv_bfloat16* __restrict__ Ah, const __nv_bfloat16* __restrict__ Al,
    int lda, int m0,
    const __nv_bfloat16* __restrict__ Bh, const __nv_bfloat16* __restrict__ Bl,
    int ldb, int n0, int k0)
{
    int t = threadIdx.x;
    // A: row = t>>1 (0..127), chunk pair selected by t&1; hi + lo
    {
        int r = t >> 1, cb = (t & 1) * 2;
        uint32_t rowoff = (uint32_t)r * ROW_BYTES;
        const __nv_bfloat16* pah = Ah + (size_t)(m0 + r) * lda + k0;
        const __nv_bfloat16* pal = Al + (size_t)(m0 + r) * lda + k0;
        #pragma unroll
        for (int j = 0; j < 2; j++) {
            int c = cb + j;
            uint32_t d = rowoff + (uint32_t)c * 16;
            cp16(sb + OFF_AH + d, pah + c * 8);
            cp16(sb + OFF_AL + d, pal + c * 8);
        }
    }
    // B: row = t>>2 (0..63), chunk = t&3; hi + lo
    {
        int r = t >> 2, c = t & 3;
        uint32_t d = (uint32_t)r * ROW_BYTES + (uint32_t)c * 16;
        const __nv_bfloat16* pbh = Bh + (size_t)(n0 + r) * ldb + k0;
        const __nv_bfloat16* pbl = Bl + (size_t)(n0 + r) * ldb + k0;
        cp16(sb + OFF_BH + d, pbh + c * 8);
        cp16(sb + OFF_BL + d, pbl + c * 8);
    }
}

// ---------------------------------------------------------------------------
// Compute one BK=32 stage: 2 x k16 steps, 3-pass hi/lo MMAs.
// 8 warps in 4(m) x 2(n) grid, warp tile 32x32, acc[2][4][4].
// ---------------------------------------------------------------------------
__device__ __forceinline__ void compute_stage(uint32_t sb, float (&acc)[2][4][4])
{
    int tid = threadIdx.x;
    int lane = tid & 31, wid = tid >> 5;
    int wm = wid >> 1, wn = wid & 1;
    int lr = lane & 15, lc = lane >> 4;
    uint32_t a_base = (uint32_t)(wm * 32 + lr) * ROW_BYTES + (uint32_t)lc * 16;
    uint32_t b_base = (uint32_t)(wn * 32 + lr) * ROW_BYTES + (uint32_t)lc * 16;

    #pragma unroll
    for (int kk = 0; kk < 2; kk++) {
        uint32_t koff = (uint32_t)kk * 32;
        uint32_t ah[2][4], al[2][4], bh[2][4], bl[2][4];
        #pragma unroll
        for (int mi = 0; mi < 2; mi++) {
            uint32_t o = a_base + (uint32_t)mi * (16 * ROW_BYTES) + koff;
            ldm_x4(ah[mi], sb + OFF_AH + o);
            ldm_x4(al[mi], sb + OFF_AL + o);
        }
        #pragma unroll
        for (int p = 0; p < 2; p++) {
            uint32_t o = b_base + (uint32_t)p * (16 * ROW_BYTES) + koff;
            ldm_x4(bh[p], sb + OFF_BH + o);
            ldm_x4(bl[p], sb + OFF_BL + o);
        }
        #pragma unroll
        for (int mi = 0; mi < 2; mi++) {
            #pragma unroll
            for (int ni = 0; ni < 4; ni++) {
                int p = ni >> 1, q = ni & 1;
                uint32_t bh0 = bh[p][q], bh1 = bh[p][q + 2];
                mma_bf16(acc[mi][ni], ah[mi], bh0, bh1);
                mma_bf16(acc[mi][ni], ah[mi], bl[p][q], bl[p][q + 2]);
                mma_bf16(acc[mi][ni], al[mi], bh0, bh1);
            }
        }
    }
}

// ---------------------------------------------------------------------------
// Pipelined K-loop accumulating into acc (callable multiple times; cp-group
// accounting stays consistent across segments: one commit per iteration).
// ---------------------------------------------------------------------------
__device__ void gemm_segment(
    uint32_t sbase,
    const __nv_bfloat16* Ah, const __nv_bfloat16* Al, int lda, int m0,
    const __nv_bfloat16* Bh, const __nv_bfloat16* Bl, int ldb, int n0,
    int K, float (&acc)[2][4][4])
{
    int nst = K / BK;
    #pragma unroll
    for (int p = 0; p < DEPTH - 1; p++) {
        if (p < nst)
            load_stage(sbase + (uint32_t)p * STAGE_BYTES,
                       Ah, Al, lda, m0, Bh, Bl, ldb, n0, p * BK);
        cp_commit();
    }
    for (int s = 0; s < nst; s++) {
        cp_wait<DEPTH - 2>();
        __syncthreads();
        int nf = s + DEPTH - 1;
        if (nf < nst)
            load_stage(sbase + (uint32_t)(nf % DEPTH) * STAGE_BYTES,
                       Ah, Al, lda, m0, Bh, Bl, ldb, n0, nf * BK);
        cp_commit();
        compute_stage(sbase + (uint32_t)(s % DEPTH) * STAGE_BYTES, acc);
    }
}

// ---------------------------------------------------------------------------
// Epilogue straight from fragments: bias / C2-add / rho, write bf16 hi/lo
// (next step's operands) and/or fp32 (final output / C2).
// ---------------------------------------------------------------------------
__device__ void epilogue(
    float (&acc)[2][4][4], int m0, int n0, int outw,
    const float* __restrict__ bias, const float* __restrict__ addm, bool do_rho,
    __nv_bfloat16* __restrict__ oh, __nv_bfloat16* __restrict__ ol,
    float* __restrict__ of)
{
    int tid = threadIdx.x;
    int lane = tid & 31, wid = tid >> 5;
    int wm = wid >> 1, wn = wid & 1;
    int g = lane >> 2, t = lane & 3;

    #pragma unroll
    for (int mi = 0; mi < 2; mi++) {
        #pragma unroll
        for (int ni = 0; ni < 4; ni++) {
            int nc = n0 + wn * 32 + ni * 8 + 2 * t;
            float bv0 = 0.f, bv1 = 0.f;
            if (bias) { bv0 = bias[nc]; bv1 = bias[nc + 1]; }
            #pragma unroll
            for (int h = 0; h < 2; h++) {
                int mr = m0 + wm * 32 + mi * 16 + g + h * 8;
                float v0 = acc[mi][ni][2 * h + 0] + bv0;
                float v1 = acc[mi][ni][2 * h + 1] + bv1;
                size_t o = (size_t)mr * outw + nc;
                if (addm) {
                    float2 av = *(const float2*)&addm[o];
                    v0 += av.x; v1 += av.y;
                }
                if (do_rho) {
                    v0 = fminf(fmaxf(v0, 0.f), 1.f);
                    v1 = fminf(fmaxf(v1, 0.f), 1.f);
                }
                if (oh) {
                    __nv_bfloat16 h0 = __float2bfloat16(v0);
                    __nv_bfloat16 h1 = __float2bfloat16(v1);
                    __nv_bfloat162 hp; hp.x = h0; hp.y = h1;
                    __nv_bfloat162 lp;
                    lp.x = __float2bfloat16(v0 - __bfloat162float(h0));
                    lp.y = __float2bfloat16(v1 - __bfloat162float(h1));
                    *(__nv_bfloat162*)&oh[o] = hp;
                    *(__nv_bfloat162*)&ol[o] = lp;
                }
                if (of) *(float2*)&of[o] = make_float2(v0, v1);
            }
        }
    }
}

// ---------------------------------------------------------------------------
// One relaxation step, fused. 144 CTAs (one full wave):
//  [0,16)    s0' tiles 2x8     [16,80)  s1' 2x32     [80,144) s2' 2x32
// ---------------------------------------------------------------------------
__global__ void __launch_bounds__(256, 1) ep_step_kernel(
    const __nv_bfloat16* s0h, const __nv_bfloat16* s0l,
    const __nv_bfloat16* s1h, const __nv_bfloat16* s1l,
    const __nv_bfloat16* s2h, const __nv_bfloat16* s2l,
    __nv_bfloat16* o0h, __nv_bfloat16* o0l,
    __nv_bfloat16* o1h, __nv_bfloat16* o1l,
    __nv_bfloat16* o2h, __nv_bfloat16* o2l,
    const __nv_bfloat16* W0h, const __nv_bfloat16* W0l,
    const __nv_bfloat16* W1h, const __nv_bfloat16* W1l,
    const __nv_bfloat16* W0Th, const __nv_bfloat16* W0Tl,
    const __nv_bfloat16* W1Th, const __nv_bfloat16* W1Tl,
    const float* b0, const float* b1, const float* c2,
    float* f0, float* f1, float* f2)
{
    extern __shared__ char dyn[];
    uint32_t sb = smem_u32(dyn);

    float acc[2][4][4];
    #pragma unroll
    for (int i = 0; i < 2; i++)
        #pragma unroll
        for (int j = 0; j < 4; j++)
            #pragma unroll
            for (int k = 0; k < 4; k++) acc[i][j][k] = 0.f;

    int blk = blockIdx.x;
    if (blk < 16) {
        int m0 = (blk >> 3) * BM, n0 = (blk & 7) * BN;
        gemm_segment(sb, s1h, s1l, D1, m0, W0h, W0l, D1, n0, D1, acc);
        epilogue(acc, m0, n0, D0, b0, nullptr, true, o0h, o0l, f0);
    } else if (blk < 80) {
        int l = blk - 16;
        int m0 = (l >> 5) * BM, n0 = (l & 31) * BN;
        gemm_segment(sb, s2h, s2l, D2, m0, W1h, W1l, D2, n0, D2, acc);
        gemm_segment(sb, s0h, s0l, D0, m0, W0Th, W0Tl, D0, n0, D0, acc);
        epilogue(acc, m0, n0, D1, b1, nullptr, true, o1h, o1l, f1);
    } else {
        int l = blk - 80;
        int m0 = (l >> 5) * BM, n0 = (l & 31) * BN;
        gemm_segment(sb, s1h, s1l, D1, m0, W1Th, W1Tl, D1, n0, D1, acc);
        epilogue(acc, m0, n0, D2, nullptr, c2, true, o2h, o2l, f2);
    }
}

// C2 = data @ W2^T + b2  (fp32 out only). 64 CTAs: 2x32, K=4096.
__global__ void __launch_bounds__(256, 1) ep_c2_kernel(
    const __nv_bfloat16* dh, const __nv_bfloat16* dl,
    const __nv_bfloat16* W2h, const __nv_bfloat16* W2l,
    const float* b2, float* c2)
{
    extern __shared__ char dyn[];
    uint32_t sb = smem_u32(dyn);

    float acc[2][4][4];
    #pragma unroll
    for (int i = 0; i < 2; i++)
        #pragma unroll
        for (int j = 0; j < 4; j++)
            #pragma unroll
            for (int k = 0; k < 4; k++) acc[i][j][k] = 0.f;

    int blk = blockIdx.x;
    int m0 = (blk >> 5) * BM, n0 = (blk & 31) * BN;
    gemm_segment(sb, dh, dl, DIN, m0, W2h, W2l, DIN, n0, DIN, acc);
    epilogue(acc, m0, n0, D2, b2, nullptr, false, nullptr, nullptr, c2);
}

// ------------------------- conversion kernels ------------------------------
__global__ void convert_split(const float* __restrict__ x,
                              __nv_bfloat16* __restrict__ h,
                              __nv_bfloat16* __restrict__ l, int n)
{
    int i = blockIdx.x * blockDim.x + threadIdx.x;
    int idx = i * 4;
    if (idx < n) {
        float4 v = *(const float4*)&x[idx];
        __nv_bfloat16 h0 = __float2bfloat16(v.x), h1 = __float2bfloat16(v.y);
        __nv_bfloat16 h2 = __float2bfloat16(v.z), h3 = __float2bfloat16(v.w);
        __nv_bfloat162 hp0, hp1, lp0, lp1;
        hp0.x = h0; hp0.y = h1; hp1.x = h2; hp1.y = h3;
        lp0.x = __float2bfloat16(v.x - __bfloat162float(h0));
        lp0.y = __float2bfloat16(v.y - __bfloat162float(h1));
        lp1.x = __float2bfloat16(v.z - __bfloat162float(h2));
        lp1.y = __float2bfloat16(v.w - __bfloat162float(h3));
        *(__nv_bfloat162*)&h[idx] = hp0;
        *(__nv_bfloat162*)&h[idx + 2] = hp1;
        *(__nv_bfloat162*)&l[idx] = lp0;
        *(__nv_bfloat162*)&l[idx + 2] = lp1;
    }
}

// W (R x C) -> T (C x R), split into bf16 hi/lo. 32x32 tiles, 256 threads.
__global__ void transpose_split(const float* __restrict__ W, int R, int C,
                                __nv_bfloat16* __restrict__ Th,
                                __nv_bfloat16* __restrict__ Tl)
{
    __shared__ float tile[32][33];
    int tx = threadIdx.x & 31, ty = threadIdx.x >> 5;   // 32 x 8
    int c0 = blockIdx.x * 32, r0 = blockIdx.y * 32;
    #pragma unroll
    for (int k = 0; k < 4; k++)
        tile[ty + 8 * k][tx] = W[(size_t)(r0 + ty + 8 * k) * C + c0 + tx];
    __syncthreads();
    #pragma unroll
    for (int k = 0; k < 4; k++) {
        float v = tile[tx][ty + 8 * k];
        __nv_bfloat16 hi = __float2bfloat16(v);
        size_t o = (size_t)(c0 + ty + 8 * k) * R + r0 + tx;
        Th[o] = hi;
        Tl[o] = __float2bfloat16(v - __bfloat162float(hi));
    }
}

// ------------------------------- host side ---------------------------------
static inline void* sym(const void* s) {
    void* p = nullptr;
    cudaGetSymbolAddress(&p, s);
    return p;
}

extern "C" void kernel_launch(void* const* d_in, const int* in_sizes, int n_in,
                              void* d_out, int out_size)
{
    const float* data = (const float*)d_in[0];
    const float* in_s0 = (const float*)d_in[1];
    const float* in_s1 = (const float*)d_in[2];
    const float* in_s2 = (const float*)d_in[3];
    const float* W0 = (const float*)d_in[4];
    const float* b0 = (const float*)d_in[5];
    const float* W1 = (const float*)d_in[6];
    const float* b1 = (const float*)d_in[7];
    const float* W2 = (const float*)d_in[8];
    const float* b2 = (const float*)d_in[9];
    float* out = (float*)d_out;

    cudaFuncSetAttribute(ep_step_kernel, cudaFuncAttributeMaxDynamicSharedMemorySize, DSMEM_BYTES);
    cudaFuncSetAttribute(ep_c2_kernel,  cudaFuncAttributeMaxDynamicSharedMemorySize, DSMEM_BYTES);

    __nv_bfloat16 *W0h = (__nv_bfloat16*)sym(g_W0h),  *W0l = (__nv_bfloat16*)sym(g_W0l);
    __nv_bfloat16 *W1h = (__nv_bfloat16*)sym(g_W1h),  *W1l = (__nv_bfloat16*)sym(g_W1l);
    __nv_bfloat16 *W2h = (__nv_bfloat16*)sym(g_W2h),  *W2l = (__nv_bfloat16*)sym(g_W2l);
    __nv_bfloat16 *W0Th = (__nv_bfloat16*)sym(g_W0Th), *W0Tl = (__nv_bfloat16*)sym(g_W0Tl);
    __nv_bfloat16 *W1Th = (__nv_bfloat16*)sym(g_W1Th), *W1Tl = (__nv_bfloat16*)sym(g_W1Tl);
    __nv_bfloat16 *dh = (__nv_bfloat16*)sym(g_dh),    *dl = (__nv_bfloat16*)sym(g_dl);
    __nv_bfloat16 *s0h = (__nv_bfloat16*)sym(g_s0h),  *s0l = (__nv_bfloat16*)sym(g_s0l);
    __nv_bfloat16 *s1h = (__nv_bfloat16*)sym(g_s1h),  *s1l = (__nv_bfloat16*)sym(g_s1l);
    __nv_bfloat16 *s2h = (__nv_bfloat16*)sym(g_s2h),  *s2l = (__nv_bfloat16*)sym(g_s2l);
    float* c2 = (float*)sym(g_c2);

    const int THR = 256;
    auto cvt = [&](const float* x, __nv_bfloat16* h, __nv_bfloat16* l, int n) {
        convert_split<<<(n / 4 + THR - 1) / THR, THR>>>(x, h, l, n);
    };
    cvt(W0, W0h, W0l, D0 * D1);
    cvt(W1, W1h, W1l, D1 * D2);
    cvt(W2, W2h, W2l, D2 * DIN);
    cvt(data, dh, dl, BATCH * DIN);
    cvt(in_s0, s0h, s0l, BATCH * D0);
    cvt(in_s1, s1h, s1l, BATCH * D1);
    cvt(in_s2, s2h, s2l, BATCH * D2);

    transpose_split<<<dim3(D1 / 32, D0 / 32), 256>>>(W0, D0, D1, W0Th, W0Tl);
    transpose_split<<<dim3(D2 / 32, D1 / 32), 256>>>(W1, D1, D2, W1Th, W1Tl);

    ep_c2_kernel<<<64, 256, DSMEM_BYTES>>>(dh, dl, W2h, W2l, b2, c2);

    for (int t = 1; t <= T_STEPS; t++) {
        int pi = (t - 1) & 1, po = t & 1;
        size_t n0e = (size_t)BATCH * D0, n1e = (size_t)BATCH * D1, n2e = (size_t)BATCH * D2;
        float *f0 = nullptr, *f1 = nullptr, *f2 = nullptr;
        bool last = (t == T_STEPS);
        if (last) {
            f0 = out;
            f1 = out + n0e;
            f2 = out + n0e + n1e;
        }
        ep_step_kernel<<<144, 256, DSMEM_BYTES>>>(
            s0h + pi * n0e, s0l + pi * n0e,
            s1h + pi * n1e, s1l + pi * n1e,
            s2h + pi * n2e, s2l + pi * n2e,
            last ? nullptr : s0h + po * n0e, last ? nullptr : s0l + po * n0e,
            last ? nullptr : s1h + po * n1e, last ? nullptr : s1l + po * n1e,
            last ? nullptr : s2h + po * n2e, last ? nullptr : s2l + po * n2e,
            W0h, W0l, W1h, W1l, W0Th, W0Tl, W1Th, W1Tl,
            b0, b1, c2, f0, f1, f2);
    }
}

// round 6
// speedup vs baseline: 3.9536x; 1.7570x over previous
#include <cuda_runtime.h>
#include <cuda_bf16.h>
#include <cstdint>
#include <cstddef>

// ---------------------------------------------------------------------------
// EP free-phase relaxation. Hot loop on INT8 mma.sync (m16n8k32.s8) with
// two-limb fixed-point operands (exact s32 accumulation):
//   s  = (A0*128 + A1) * 2^-14     (state in [0,1], limbs int8)
//   w  = (B0*128 + B1) * 2^-19     (|w| <= 1/sqrt(512) fits: w*4096 < 127)
//   z  = P00*2^-19 + PX*2^-26,  P00 = sum A0B0,  PX = sum (A0B1 + A1B0)
// C2 = data@W2^T + b2 computed once via the proven bf16 3-pass path.
// ---------------------------------------------------------------------------

#define BATCH 256
#define D0 512
#define D1 2048
#define D2 2048
#define DIN 4096
#define T_STEPS 20

#define BM 128
#define BN 64
#define DEPTH 4

// shared layout (identical byte footprint for int8-BK64 and bf16-BK32 paths)
#define ROW_BYTES 80                    // 64B data + 16B pad, conflict-free
#define A_MAT (128 * ROW_BYTES)         // 10240
#define B_MAT (64 * ROW_BYTES)          // 5120
#define OFF_A0 0
#define OFF_A1 (A_MAT)
#define OFF_B0 (2 * A_MAT)
#define OFF_B1 (2 * A_MAT + B_MAT)
#define STAGE_BYTES (2 * A_MAT + 2 * B_MAT)   // 30720
#define DSMEM_BYTES (DEPTH * STAGE_BYTES)     // 122880

#define I_BK 64     // int8 K per stage
#define BF_BK 32    // bf16 K per stage (c2 kernel)

// --------------------------- device scratch --------------------------------
__device__ char g_iW0[2][D0 * D1];
__device__ char g_iW1[2][D1 * D2];
__device__ char g_iW0T[2][D1 * D0];
__device__ char g_iW1T[2][D2 * D1];
__device__ char g_is0[2][2][BATCH * D0];   // [pingpong][limb]
__device__ char g_is1[2][2][BATCH * D1];
__device__ char g_is2[2][2][BATCH * D2];
__device__ __nv_bfloat16 g_W2h[D2 * DIN], g_W2l[D2 * DIN];
__device__ __nv_bfloat16 g_dh[BATCH * DIN], g_dl[BATCH * DIN];
__device__ float g_c2[BATCH * D2];

// ------------------------------ PTX helpers --------------------------------
__device__ __forceinline__ uint32_t smem_u32(const void* p) {
    uint32_t a;
    asm("{ .reg .u64 t; cvta.to.shared.u64 t, %1; cvt.u32.u64 %0, t; }"
        : "=r"(a) : "l"(p));
    return a;
}
__device__ __forceinline__ void cp16(uint32_t dst, const void* src) {
    asm volatile("cp.async.cg.shared.global [%0], [%1], 16;"
                 :: "r"(dst), "l"(src) : "memory");
}
__device__ __forceinline__ void cp_commit() {
    asm volatile("cp.async.commit_group;" ::: "memory");
}
template <int N>
__device__ __forceinline__ void cp_wait() {
    asm volatile("cp.async.wait_group %0;" :: "n"(N) : "memory");
}
__device__ __forceinline__ void ldm_x4(uint32_t (&r)[4], uint32_t addr) {
    asm volatile("ldmatrix.sync.aligned.m8n8.x4.shared.b16 {%0,%1,%2,%3}, [%4];"
                 : "=r"(r[0]), "=r"(r[1]), "=r"(r[2]), "=r"(r[3]) : "r"(addr));
}
__device__ __forceinline__ void mma_s8(int (&d)[4], const uint32_t (&a)[4],
                                       uint32_t b0, uint32_t b1) {
    asm volatile(
        "mma.sync.aligned.m16n8k32.row.col.s32.s8.s8.s32 "
        "{%0,%1,%2,%3}, {%4,%5,%6,%7}, {%8,%9}, {%0,%1,%2,%3};"
        : "+r"(d[0]), "+r"(d[1]), "+r"(d[2]), "+r"(d[3])
        : "r"(a[0]), "r"(a[1]), "r"(a[2]), "r"(a[3]), "r"(b0), "r"(b1));
}
__device__ __forceinline__ void mma_bf16(float (&d)[4], const uint32_t (&a)[4],
                                         uint32_t b0, uint32_t b1) {
    asm volatile(
        "mma.sync.aligned.m16n8k16.row.col.f32.bf16.bf16.f32 "
        "{%0,%1,%2,%3}, {%4,%5,%6,%7}, {%8,%9}, {%0,%1,%2,%3};"
        : "+f"(d[0]), "+f"(d[1]), "+f"(d[2]), "+f"(d[3])
        : "r"(a[0]), "r"(a[1]), "r"(a[2]), "r"(a[3]), "r"(b0), "r"(b1));
}

// ============================ INT8 GEMM path ===============================
// Stage loader: A limbs rows [m0,m0+128) x k[k0,k0+64) int8, B rows [n0,n0+64).
// 256 threads, 6 cp16 each.
__device__ __forceinline__ void load_stage_i8(
    uint32_t sb,
    const char* __restrict__ A0p, const char* __restrict__ A1p, int lda, int m0,
    const char* __restrict__ B0p, const char* __restrict__ B1p, int ldb, int n0,
    int k0)
{
    int t = threadIdx.x;
    {   // A: row = t>>1, chunk pair by t&1, both limbs
        int r = t >> 1, cb = (t & 1) * 2;
        uint32_t rowoff = (uint32_t)r * ROW_BYTES;
        const char* pa0 = A0p + (size_t)(m0 + r) * lda + k0;
        const char* pa1 = A1p + (size_t)(m0 + r) * lda + k0;
        #pragma unroll
        for (int j = 0; j < 2; j++) {
            int c = cb + j;
            uint32_t d = rowoff + (uint32_t)c * 16;
            cp16(sb + OFF_A0 + d, pa0 + c * 16);
            cp16(sb + OFF_A1 + d, pa1 + c * 16);
        }
    }
    {   // B: row = t>>2, chunk = t&3, both limbs
        int r = t >> 2, c = t & 3;
        uint32_t d = (uint32_t)r * ROW_BYTES + (uint32_t)c * 16;
        const char* pb0 = B0p + (size_t)(n0 + r) * ldb + k0;
        const char* pb1 = B1p + (size_t)(n0 + r) * ldb + k0;
        cp16(sb + OFF_B0 + d, pb0 + c * 16);
        cp16(sb + OFF_B1 + d, pb1 + c * 16);
    }
}

// One BK=64 stage: 2 k32 chunks x 3 MMAs per (mi,ni).
// 8 warps 4(m) x 2(n), warp tile 32x32.
__device__ __forceinline__ void compute_stage_i8(
    uint32_t sb, int (&acc0)[2][4][4], int (&accX)[2][4][4])
{
    int tid = threadIdx.x;
    int lane = tid & 31, wid = tid >> 5;
    int wm = wid >> 1, wn = wid & 1;
    int lr = lane & 15, lc = lane >> 4;
    uint32_t a_base = (uint32_t)(wm * 32 + lr) * ROW_BYTES + (uint32_t)lc * 16;
    uint32_t b_base = (uint32_t)(wn * 32 + lr) * ROW_BYTES + (uint32_t)lc * 16;

    #pragma unroll
    for (int kc = 0; kc < 2; kc++) {
        uint32_t koff = (uint32_t)kc * 32;
        uint32_t a0[2][4], a1[2][4], b0[2][4], b1[2][4];
        #pragma unroll
        for (int mi = 0; mi < 2; mi++) {
            uint32_t o = a_base + (uint32_t)mi * (16 * ROW_BYTES) + koff;
            ldm_x4(a0[mi], sb + OFF_A0 + o);
            ldm_x4(a1[mi], sb + OFF_A1 + o);
        }
        #pragma unroll
        for (int p = 0; p < 2; p++) {
            uint32_t o = b_base + (uint32_t)p * (16 * ROW_BYTES) + koff;
            ldm_x4(b0[p], sb + OFF_B0 + o);
            ldm_x4(b1[p], sb + OFF_B1 + o);
        }
        #pragma unroll
        for (int mi = 0; mi < 2; mi++) {
            #pragma unroll
            for (int ni = 0; ni < 4; ni++) {
                int p = ni >> 1, q = ni & 1;
                uint32_t c00 = b0[p][q], c01 = b0[p][q + 2];
                mma_s8(acc0[mi][ni], a0[mi], c00, c01);
                mma_s8(accX[mi][ni], a0[mi], b1[p][q], b1[p][q + 2]);
                mma_s8(accX[mi][ni], a1[mi], c00, c01);
            }
        }
    }
}

__device__ void gemm_segment_i8(
    uint32_t sbase,
    const char* A0p, const char* A1p, int lda, int m0,
    const char* B0p, const char* B1p, int ldb, int n0,
    int K, int (&acc0)[2][4][4], int (&accX)[2][4][4])
{
    int nst = K / I_BK;
    #pragma unroll
    for (int p = 0; p < DEPTH - 1; p++) {
        if (p < nst)
            load_stage_i8(sbase + (uint32_t)p * STAGE_BYTES,
                          A0p, A1p, lda, m0, B0p, B1p, ldb, n0, p * I_BK);
        cp_commit();
    }
    for (int s = 0; s < nst; s++) {
        cp_wait<DEPTH - 2>();
        __syncthreads();
        int nf = s + DEPTH - 1;
        if (nf < nst)
            load_stage_i8(sbase + (uint32_t)(nf % DEPTH) * STAGE_BYTES,
                          A0p, A1p, lda, m0, B0p, B1p, ldb, n0, nf * I_BK);
        cp_commit();
        compute_stage_i8(sbase + (uint32_t)(s % DEPTH) * STAGE_BYTES, acc0, accX);
    }
}

// Quantize v in [0,1] -> two int8 limbs (s = (q0*128+q1) * 2^-14)
__device__ __forceinline__ void quant_state(float v, int& q0, int& q1) {
    float v128 = v * 128.f;
    q0 = __float2int_rn(v128);
    if (q0 > 127) q0 = 127;
    float r = (v128 - (float)q0) * 128.f;
    q1 = __float2int_rn(r);
    if (q1 > 127) q1 = 127;
    if (q1 < -128) q1 = -128;
}

// Epilogue: z = acc0*2^-19 + accX*2^-26 (+bias,+addm), rho, write int8 limbs
// (next step's A operand) and/or fp32 (final output).
__device__ void epilogue_i8(
    int (&acc0)[2][4][4], int (&accX)[2][4][4], int m0, int n0, int outw,
    const float* __restrict__ bias, const float* __restrict__ addm, bool do_rho,
    char* __restrict__ o0, char* __restrict__ o1, float* __restrict__ of)
{
    const float S0 = 0x1p-19f, SX = 0x1p-26f;
    int tid = threadIdx.x;
    int lane = tid & 31, wid = tid >> 5;
    int wm = wid >> 1, wn = wid & 1;
    int g = lane >> 2, t = lane & 3;

    #pragma unroll
    for (int mi = 0; mi < 2; mi++) {
        #pragma unroll
        for (int ni = 0; ni < 4; ni++) {
            int nc = n0 + wn * 32 + ni * 8 + 2 * t;
            float bv0 = 0.f, bv1 = 0.f;
            if (bias) { bv0 = bias[nc]; bv1 = bias[nc + 1]; }
            #pragma unroll
            for (int h = 0; h < 2; h++) {
                int mr = m0 + wm * 32 + mi * 16 + g + h * 8;
                float v0 = (float)acc0[mi][ni][2 * h + 0] * S0
                         + (float)accX[mi][ni][2 * h + 0] * SX + bv0;
                float v1 = (float)acc0[mi][ni][2 * h + 1] * S0
                         + (float)accX[mi][ni][2 * h + 1] * SX + bv1;
                size_t o = (size_t)mr * outw + nc;
                if (addm) {
                    float2 av = *(const float2*)&addm[o];
                    v0 += av.x; v1 += av.y;
                }
                if (do_rho) {
                    v0 = fminf(fmaxf(v0, 0.f), 1.f);
                    v1 = fminf(fmaxf(v1, 0.f), 1.f);
                }
                if (o0) {
                    int a0, a1, b0, b1;
                    quant_state(v0, a0, a1);
                    quant_state(v1, b0, b1);
                    char2 p0; p0.x = (char)a0; p0.y = (char)b0;
                    char2 p1; p1.x = (char)a1; p1.y = (char)b1;
                    *(char2*)&o0[o] = p0;
                    *(char2*)&o1[o] = p1;
                }
                if (of) *(float2*)&of[o] = make_float2(v0, v1);
            }
        }
    }
}

// ---------------------------------------------------------------------------
// One relaxation step (int8). 144 CTAs:
//  [0,16)  s0' 2x8      [16,80) s1' 2x32      [80,144) s2' 2x32
// ---------------------------------------------------------------------------
__global__ void __launch_bounds__(256, 1) ep_step_i8(
    const char* s0a, const char* s0b,
    const char* s1a, const char* s1b,
    const char* s2a, const char* s2b,
    char* o0a, char* o0b, char* o1a, char* o1b, char* o2a, char* o2b,
    const char* W0a, const char* W0b,
    const char* W1a, const char* W1b,
    const char* W0Ta, const char* W0Tb,
    const char* W1Ta, const char* W1Tb,
    const float* b0, const float* b1, const float* c2,
    float* f0, float* f1, float* f2)
{
    extern __shared__ char dyn[];
    uint32_t sb = smem_u32(dyn);

    int acc0[2][4][4], accX[2][4][4];
    #pragma unroll
    for (int i = 0; i < 2; i++)
        #pragma unroll
        for (int j = 0; j < 4; j++)
            #pragma unroll
            for (int k = 0; k < 4; k++) { acc0[i][j][k] = 0; accX[i][j][k] = 0; }

    int blk = blockIdx.x;
    if (blk < 16) {
        int m0 = (blk >> 3) * BM, n0 = (blk & 7) * BN;
        gemm_segment_i8(sb, s1a, s1b, D1, m0, W0a, W0b, D1, n0, D1, acc0, accX);
        epilogue_i8(acc0, accX, m0, n0, D0, b0, nullptr, true, o0a, o0b, f0);
    } else if (blk < 80) {
        int l = blk - 16;
        int m0 = (l >> 5) * BM, n0 = (l & 31) * BN;
        gemm_segment_i8(sb, s2a, s2b, D2, m0, W1a, W1b, D2, n0, D2, acc0, accX);
        gemm_segment_i8(sb, s0a, s0b, D0, m0, W0Ta, W0Tb, D0, n0, D0, acc0, accX);
        epilogue_i8(acc0, accX, m0, n0, D1, b1, nullptr, true, o1a, o1b, f1);
    } else {
        int l = blk - 80;
        int m0 = (l >> 5) * BM, n0 = (l & 31) * BN;
        gemm_segment_i8(sb, s1a, s1b, D1, m0, W1Ta, W1Tb, D1, n0, D1, acc0, accX);
        epilogue_i8(acc0, accX, m0, n0, D2, nullptr, c2, true, o2a, o2b, f2);
    }
}

// ============================ bf16 path (C2 only) ==========================
__device__ __forceinline__ void load_stage_bf(
    uint32_t sb,
    const __nv_bfloat16* __restrict__ Ah, const __nv_bfloat16* __restrict__ Al,
    int lda, int m0,
    const __nv_bfloat16* __restrict__ Bh, const __nv_bfloat16* __restrict__ Bl,
    int ldb, int n0, int k0)
{
    int t = threadIdx.x;
    {
        int r = t >> 1, cb = (t & 1) * 2;
        uint32_t rowoff = (uint32_t)r * ROW_BYTES;
        const __nv_bfloat16* pah = Ah + (size_t)(m0 + r) * lda + k0;
        const __nv_bfloat16* pal = Al + (size_t)(m0 + r) * lda + k0;
        #pragma unroll
        for (int j = 0; j < 2; j++) {
            int c = cb + j;
            uint32_t d = rowoff + (uint32_t)c * 16;
            cp16(sb + OFF_A0 + d, pah + c * 8);
            cp16(sb + OFF_A1 + d, pal + c * 8);
        }
    }
    {
        int r = t >> 2, c = t & 3;
        uint32_t d = (uint32_t)r * ROW_BYTES + (uint32_t)c * 16;
        const __nv_bfloat16* pbh = Bh + (size_t)(n0 + r) * ldb + k0;
        const __nv_bfloat16* pbl = Bl + (size_t)(n0 + r) * ldb + k0;
        cp16(sb + OFF_B0 + d, pbh + c * 8);
        cp16(sb + OFF_B1 + d, pbl + c * 8);
    }
}

__device__ __forceinline__ void compute_stage_bf(uint32_t sb, float (&acc)[2][4][4])
{
    int tid = threadIdx.x;
    int lane = tid & 31, wid = tid >> 5;
    int wm = wid >> 1, wn = wid & 1;
    int lr = lane & 15, lc = lane >> 4;
    uint32_t a_base = (uint32_t)(wm * 32 + lr) * ROW_BYTES + (uint32_t)lc * 16;
    uint32_t b_base = (uint32_t)(wn * 32 + lr) * ROW_BYTES + (uint32_t)lc * 16;

    #pragma unroll
    for (int kk = 0; kk < 2; kk++) {
        uint32_t koff = (uint32_t)kk * 32;
        uint32_t ah[2][4], al[2][4], bh[2][4], bl[2][4];
        #pragma unroll
        for (int mi = 0; mi < 2; mi++) {
            uint32_t o = a_base + (uint32_t)mi * (16 * ROW_BYTES) + koff;
            ldm_x4(ah[mi], sb + OFF_A0 + o);
            ldm_x4(al[mi], sb + OFF_A1 + o);
        }
        #pragma unroll
        for (int p = 0; p < 2; p++) {
            uint32_t o = b_base + (uint32_t)p * (16 * ROW_BYTES) + koff;
            ldm_x4(bh[p], sb + OFF_B0 + o);
            ldm_x4(bl[p], sb + OFF_B1 + o);
        }
        #pragma unroll
        for (int mi = 0; mi < 2; mi++) {
            #pragma unroll
            for (int ni = 0; ni < 4; ni++) {
                int p = ni >> 1, q = ni & 1;
                uint32_t bh0 = bh[p][q], bh1 = bh[p][q + 2];
                mma_bf16(acc[mi][ni], ah[mi], bh0, bh1);
                mma_bf16(acc[mi][ni], ah[mi], bl[p][q], bl[p][q + 2]);
                mma_bf16(acc[mi][ni], al[mi], bh0, bh1);
            }
        }
    }
}

// C2 = data @ W2^T + b2  (fp32 out). 64 CTAs: 2x32, K=4096, BK=32.
__global__ void __launch_bounds__(256, 1) ep_c2_kernel(
    const __nv_bfloat16* dh, const __nv_bfloat16* dl,
    const __nv_bfloat16* W2h, const __nv_bfloat16* W2l,
    const float* b2, float* c2)
{
    extern __shared__ char dyn[];
    uint32_t sb = smem_u32(dyn);

    float acc[2][4][4];
    #pragma unroll
    for (int i = 0; i < 2; i++)
        #pragma unroll
        for (int j = 0; j < 4; j++)
            #pragma unroll
            for (int k = 0; k < 4; k++) acc[i][j][k] = 0.f;

    int blk = blockIdx.x;
    int m0 = (blk >> 5) * BM, n0 = (blk & 31) * BN;

    int nst = DIN / BF_BK;
    #pragma unroll
    for (int p = 0; p < DEPTH - 1; p++) {
        if (p < nst)
            load_stage_bf(sb + (uint32_t)p * STAGE_BYTES,
                          dh, dl, DIN, m0, W2h, W2l, DIN, n0, p * BF_BK);
        cp_commit();
    }
    for (int s = 0; s < nst; s++) {
        cp_wait<DEPTH - 2>();
        __syncthreads();
        int nf = s + DEPTH - 1;
        if (nf < nst)
            load_stage_bf(sb + (uint32_t)(nf % DEPTH) * STAGE_BYTES,
                          dh, dl, DIN, m0, W2h, W2l, DIN, n0, nf * BF_BK);
        cp_commit();
        compute_stage_bf(sb + (uint32_t)(s % DEPTH) * STAGE_BYTES, acc);
    }

    // epilogue: bias, fp32 store
    int tid = threadIdx.x;
    int lane = tid & 31, wid = tid >> 5;
    int wm = wid >> 1, wn = wid & 1;
    int g = lane >> 2, t = lane & 3;
    #pragma unroll
    for (int mi = 0; mi < 2; mi++) {
        #pragma unroll
        for (int ni = 0; ni < 4; ni++) {
            int nc = n0 + wn * 32 + ni * 8 + 2 * t;
            float bv0 = b2[nc], bv1 = b2[nc + 1];
            #pragma unroll
            for (int h = 0; h < 2; h++) {
                int mr = m0 + wm * 32 + mi * 16 + g + h * 8;
                float v0 = acc[mi][ni][2 * h + 0] + bv0;
                float v1 = acc[mi][ni][2 * h + 1] + bv1;
                *(float2*)&c2[(size_t)mr * D2 + nc] = make_float2(v0, v1);
            }
        }
    }
}

// ------------------------- conversion kernels ------------------------------
__global__ void convert_split(const float* __restrict__ x,
                              __nv_bfloat16* __restrict__ h,
                              __nv_bfloat16* __restrict__ l, int n)
{
    int i = blockIdx.x * blockDim.x + threadIdx.x;
    int idx = i * 4;
    if (idx < n) {
        float4 v = *(const float4*)&x[idx];
        __nv_bfloat16 h0 = __float2bfloat16(v.x), h1 = __float2bfloat16(v.y);
        __nv_bfloat16 h2 = __float2bfloat16(v.z), h3 = __float2bfloat16(v.w);
        __nv_bfloat162 hp0, hp1, lp0, lp1;
        hp0.x = h0; hp0.y = h1; hp1.x = h2; hp1.y = h3;
        lp0.x = __float2bfloat16(v.x - __bfloat162float(h0));
        lp0.y = __float2bfloat16(v.y - __bfloat162float(h1));
        lp1.x = __float2bfloat16(v.z - __bfloat162float(h2));
        lp1.y = __float2bfloat16(v.w - __bfloat162float(h3));
        *(__nv_bfloat162*)&h[idx] = hp0;
        *(__nv_bfloat162*)&h[idx + 2] = hp1;
        *(__nv_bfloat162*)&l[idx] = lp0;
        *(__nv_bfloat162*)&l[idx + 2] = lp1;
    }
}

// weight -> int8 limbs: w = (B0*128 + B1) * 2^-19
__device__ __forceinline__ void quant_w(float w, int& q0, int& q1) {
    float w0 = w * 4096.f;
    q0 = __float2int_rn(w0);
    if (q0 > 127) q0 = 127;
    if (q0 < -128) q0 = -128;
    float r = (w0 - (float)q0) * 128.f;
    q1 = __float2int_rn(r);
    if (q1 > 127) q1 = 127;
    if (q1 < -128) q1 = -128;
}

__global__ void convert_w_i8(const float* __restrict__ w,
                             char* __restrict__ l0, char* __restrict__ l1, int n)
{
    int i = blockIdx.x * blockDim.x + threadIdx.x;
    int idx = i * 4;
    if (idx < n) {
        float4 v = *(const float4*)&w[idx];
        int a0, a1, b0, b1, c0, c1, d0, d1;
        quant_w(v.x, a0, a1); quant_w(v.y, b0, b1);
        quant_w(v.z, c0, c1); quant_w(v.w, d0, d1);
        char4 p0; p0.x = (char)a0; p0.y = (char)b0; p0.z = (char)c0; p0.w = (char)d0;
        char4 p1; p1.x = (char)a1; p1.y = (char)b1; p1.z = (char)c1; p1.w = (char)d1;
        *(char4*)&l0[idx] = p0;
        *(char4*)&l1[idx] = p1;
    }
}

// state -> int8 limbs (handles the all-zero initial states; v in [0,1])
__global__ void convert_s_i8(const float* __restrict__ x,
                             char* __restrict__ l0, char* __restrict__ l1, int n)
{
    int i = blockIdx.x * blockDim.x + threadIdx.x;
    if (i < n) {
        int q0, q1;
        float v = fminf(fmaxf(x[i], -1.f), 1.f);
        float v128 = v * 128.f;
        q0 = __float2int_rn(v128);
        if (q0 > 127) q0 = 127;
        if (q0 < -128) q0 = -128;
        float r = (v128 - (float)q0) * 128.f;
        q1 = __float2int_rn(r);
        if (q1 > 127) q1 = 127;
        if (q1 < -128) q1 = -128;
        l0[i] = (char)q0;
        l1[i] = (char)q1;
    }
}

// W (R x C) fp32 -> T (C x R) int8 limbs
__global__ void transpose_w_i8(const float* __restrict__ W, int R, int C,
                               char* __restrict__ T0, char* __restrict__ T1)
{
    __shared__ float tile[32][33];
    int tx = threadIdx.x & 31, ty = threadIdx.x >> 5;   // 32 x 8
    int c0 = blockIdx.x * 32, r0 = blockIdx.y * 32;
    #pragma unroll
    for (int k = 0; k < 4; k++)
        tile[ty + 8 * k][tx] = W[(size_t)(r0 + ty + 8 * k) * C + c0 + tx];
    __syncthreads();
    #pragma unroll
    for (int k = 0; k < 4; k++) {
        float v = tile[tx][ty + 8 * k];
        int q0, q1;
        quant_w(v, q0, q1);
        size_t o = (size_t)(c0 + ty + 8 * k) * R + r0 + tx;
        T0[o] = (char)q0;
        T1[o] = (char)q1;
    }
}

// ------------------------------- host side ---------------------------------
static inline void* sym(const void* s) {
    void* p = nullptr;
    cudaGetSymbolAddress(&p, s);
    return p;
}

extern "C" void kernel_launch(void* const* d_in, const int* in_sizes, int n_in,
                              void* d_out, int out_size)
{
    const float* data = (const float*)d_in[0];
    const float* in_s0 = (const float*)d_in[1];
    const float* in_s1 = (const float*)d_in[2];
    const float* in_s2 = (const float*)d_in[3];
    const float* W0 = (const float*)d_in[4];
    const float* b0 = (const float*)d_in[5];
    const float* W1 = (const float*)d_in[6];
    const float* b1 = (const float*)d_in[7];
    const float* W2 = (const float*)d_in[8];
    const float* b2 = (const float*)d_in[9];
    float* out = (float*)d_out;

    cudaFuncSetAttribute(ep_step_i8,  cudaFuncAttributeMaxDynamicSharedMemorySize, DSMEM_BYTES);
    cudaFuncSetAttribute(ep_c2_kernel, cudaFuncAttributeMaxDynamicSharedMemorySize, DSMEM_BYTES);

    char *W0a = (char*)sym(g_iW0),  *W0b = W0a + (size_t)D0 * D1;
    char *W1a = (char*)sym(g_iW1),  *W1b = W1a + (size_t)D1 * D2;
    char *W0Ta = (char*)sym(g_iW0T), *W0Tb = W0Ta + (size_t)D1 * D0;
    char *W1Ta = (char*)sym(g_iW1T), *W1Tb = W1Ta + (size_t)D2 * D1;
    char *s0base = (char*)sym(g_is0);
    char *s1base = (char*)sym(g_is1);
    char *s2base = (char*)sym(g_is2);
    __nv_bfloat16 *W2h = (__nv_bfloat16*)sym(g_W2h), *W2l = (__nv_bfloat16*)sym(g_W2l);
    __nv_bfloat16 *dh = (__nv_bfloat16*)sym(g_dh),   *dl = (__nv_bfloat16*)sym(g_dl);
    float* c2 = (float*)sym(g_c2);

    const size_t n0e = (size_t)BATCH * D0;
    const size_t n1e = (size_t)BATCH * D1;
    const size_t n2e = (size_t)BATCH * D2;

    const int THR = 256;
    convert_w_i8<<<(D0 * D1 / 4 + THR - 1) / THR, THR>>>(W0, W0a, W0b, D0 * D1);
    convert_w_i8<<<(D1 * D2 / 4 + THR - 1) / THR, THR>>>(W1, W1a, W1b, D1 * D2);
    transpose_w_i8<<<dim3(D1 / 32, D0 / 32), 256>>>(W0, D0, D1, W0Ta, W0Tb);
    transpose_w_i8<<<dim3(D2 / 32, D1 / 32), 256>>>(W1, D1, D2, W1Ta, W1Tb);
    convert_split<<<(D2 * DIN / 4 + THR - 1) / THR, THR>>>(W2, W2h, W2l, D2 * DIN);
    convert_split<<<((int)(BATCH * DIN) / 4 + THR - 1) / THR, THR>>>(data, dh, dl, BATCH * DIN);
    convert_s_i8<<<((int)n0e + THR - 1) / THR, THR>>>(in_s0, s0base, s0base + n0e, (int)n0e);
    convert_s_i8<<<((int)n1e + THR - 1) / THR, THR>>>(in_s1, s1base, s1base + n1e, (int)n1e);
    convert_s_i8<<<((int)n2e + THR - 1) / THR, THR>>>(in_s2, s2base, s2base + n2e, (int)n2e);

    ep_c2_kernel<<<64, 256, DSMEM_BYTES>>>(dh, dl, W2h, W2l, b2, c2);

    for (int t = 1; t <= T_STEPS; t++) {
        int pi = (t - 1) & 1, po = t & 1;
        char *i0a = s0base + (size_t)pi * 2 * n0e, *i0b = i0a + n0e;
        char *i1a = s1base + (size_t)pi * 2 * n1e, *i1b = i1a + n1e;
        char *i2a = s2base + (size_t)pi * 2 * n2e, *i2b = i2a + n2e;
        char *o0a = s0base + (size_t)po * 2 * n0e, *o0b = o0a + n0e;
        char *o1a = s1base + (size_t)po * 2 * n1e, *o1b = o1a + n1e;
        char *o2a = s2base + (size_t)po * 2 * n2e, *o2b = o2a + n2e;
        float *f0 = nullptr, *f1 = nullptr, *f2 = nullptr;
        bool last = (t == T_STEPS);
        if (last) {
            f0 = out;
            f1 = out + n0e;
            f2 = out + n0e + n1e;
            o0a = nullptr; o0b = nullptr;
            o1a = nullptr; o1b = nullptr;
            o2a = nullptr; o2b = nullptr;
        }
        ep_step_i8<<<144, 256, DSMEM_BYTES>>>(
            i0a, i0b, i1a, i1b, i2a, i2b,
            o0a, o0b, o1a, o1b, o2a, o2b,
            W0a, W0b, W1a, W1b, W0Ta, W0Tb, W1Ta, W1Tb,
            b0, b1, c2, f0, f1, f2);
    }
}

// round 7
// speedup vs baseline: 4.1930x; 1.0605x over previous
#include <cuda_runtime.h>
#include <cuda_bf16.h>
#include <cstdint>
#include <cstddef>

// ---------------------------------------------------------------------------
// EP free-phase relaxation. Persistent int8 mma.sync kernel (all 20 steps in
// one launch, software grid barrier). Two-limb fixed point (exact s32 accum):
//   s  = (A0*128 + A1) * 2^-14,  w = (B0*128 + B1) * 2^-19
//   z  = P00*2^-19 + PX*2^-26,   P00 = sum A0B0, PX = sum(A0B1 + A1B0)
// C2 = data@W2^T + b2 via bf16 3-pass, split-K over 128 CTAs (c2 + c2p).
// ---------------------------------------------------------------------------

#define BATCH 256
#define D0 512
#define D1 2048
#define D2 2048
#define DIN 4096
#define T_STEPS 20
#define NBLK 144

#define BM 128
#define BN 64
#define DEPTH 4

#define ROW_BYTES 80
#define A_MAT (128 * ROW_BYTES)
#define B_MAT (64 * ROW_BYTES)
#define OFF_A0 0
#define OFF_A1 (A_MAT)
#define OFF_B0 (2 * A_MAT)
#define OFF_B1 (2 * A_MAT + B_MAT)
#define STAGE_BYTES (2 * A_MAT + 2 * B_MAT)   // 30720
#define DSMEM_BYTES (DEPTH * STAGE_BYTES)     // 122880

#define I_BK 64
#define BF_BK 32

// --------------------------- device scratch --------------------------------
__device__ char g_iW0[2][D0 * D1];
__device__ char g_iW1[2][D1 * D2];
__device__ char g_iW0T[2][D1 * D0];
__device__ char g_iW1T[2][D2 * D1];
__device__ char g_is0[2][2][BATCH * D0];
__device__ char g_is1[2][2][BATCH * D1];
__device__ char g_is2[2][2][BATCH * D2];
__device__ __nv_bfloat16 g_W2h[D2 * DIN], g_W2l[D2 * DIN];
__device__ __nv_bfloat16 g_dh[BATCH * DIN], g_dl[BATCH * DIN];
__device__ float g_c2[BATCH * D2];
__device__ float g_c2p[BATCH * D2];
__device__ int g_cnt;
__device__ volatile int g_release;

// ------------------------------ PTX helpers --------------------------------
__device__ __forceinline__ uint32_t smem_u32(const void* p) {
    uint32_t a;
    asm("{ .reg .u64 t; cvta.to.shared.u64 t, %1; cvt.u32.u64 %0, t; }"
        : "=r"(a) : "l"(p));
    return a;
}
__device__ __forceinline__ void cp16(uint32_t dst, const void* src) {
    asm volatile("cp.async.cg.shared.global [%0], [%1], 16;"
                 :: "r"(dst), "l"(src) : "memory");
}
__device__ __forceinline__ void cp_commit() {
    asm volatile("cp.async.commit_group;" ::: "memory");
}
template <int N>
__device__ __forceinline__ void cp_wait() {
    asm volatile("cp.async.wait_group %0;" :: "n"(N) : "memory");
}
__device__ __forceinline__ void ldm_x4(uint32_t (&r)[4], uint32_t addr) {
    asm volatile("ldmatrix.sync.aligned.m8n8.x4.shared.b16 {%0,%1,%2,%3}, [%4];"
                 : "=r"(r[0]), "=r"(r[1]), "=r"(r[2]), "=r"(r[3]) : "r"(addr));
}
__device__ __forceinline__ void mma_s8(int (&d)[4], const uint32_t (&a)[4],
                                       uint32_t b0, uint32_t b1) {
    asm volatile(
        "mma.sync.aligned.m16n8k32.row.col.s32.s8.s8.s32 "
        "{%0,%1,%2,%3}, {%4,%5,%6,%7}, {%8,%9}, {%0,%1,%2,%3};"
        : "+r"(d[0]), "+r"(d[1]), "+r"(d[2]), "+r"(d[3])
        : "r"(a[0]), "r"(a[1]), "r"(a[2]), "r"(a[3]), "r"(b0), "r"(b1));
}
__device__ __forceinline__ void mma_bf16(float (&d)[4], const uint32_t (&a)[4],
                                         uint32_t b0, uint32_t b1) {
    asm volatile(
        "mma.sync.aligned.m16n8k16.row.col.f32.bf16.bf16.f32 "
        "{%0,%1,%2,%3}, {%4,%5,%6,%7}, {%8,%9}, {%0,%1,%2,%3};"
        : "+f"(d[0]), "+f"(d[1]), "+f"(d[2]), "+f"(d[3])
        : "r"(a[0]), "r"(a[1]), "r"(a[2]), "r"(a[3]), "r"(b0), "r"(b1));
}

// Software grid barrier (cumulative counter; reset by fused_convert)
__device__ __forceinline__ void grid_barrier(int target) {
    __syncthreads();
    if (threadIdx.x == 0) {
        __threadfence();
        int t = atomicAdd(&g_cnt, 1);
        if (t == target * NBLK - 1) {
            g_release = target;
        } else {
            while (g_release < target) { }
        }
        __threadfence();
    }
    __syncthreads();
}

// ============================ INT8 GEMM path ===============================
__device__ __forceinline__ void load_stage_i8(
    uint32_t sb,
    const char* __restrict__ A0p, const char* __restrict__ A1p, int lda, int m0,
    const char* __restrict__ B0p, const char* __restrict__ B1p, int ldb, int n0,
    int k0)
{
    int t = threadIdx.x;
    {
        int r = t >> 1, cb = (t & 1) * 2;
        uint32_t rowoff = (uint32_t)r * ROW_BYTES;
        const char* pa0 = A0p + (size_t)(m0 + r) * lda + k0;
        const char* pa1 = A1p + (size_t)(m0 + r) * lda + k0;
        #pragma unroll
        for (int j = 0; j < 2; j++) {
            int c = cb + j;
            uint32_t d = rowoff + (uint32_t)c * 16;
            cp16(sb + OFF_A0 + d, pa0 + c * 16);
            cp16(sb + OFF_A1 + d, pa1 + c * 16);
        }
    }
    {
        int r = t >> 2, c = t & 3;
        uint32_t d = (uint32_t)r * ROW_BYTES + (uint32_t)c * 16;
        const char* pb0 = B0p + (size_t)(n0 + r) * ldb + k0;
        const char* pb1 = B1p + (size_t)(n0 + r) * ldb + k0;
        cp16(sb + OFF_B0 + d, pb0 + c * 16);
        cp16(sb + OFF_B1 + d, pb1 + c * 16);
    }
}

__device__ __forceinline__ void compute_stage_i8(
    uint32_t sb, int (&acc0)[2][4][4], int (&accX)[2][4][4])
{
    int tid = threadIdx.x;
    int lane = tid & 31, wid = tid >> 5;
    int wm = wid >> 1, wn = wid & 1;
    int lr = lane & 15, lc = lane >> 4;
    uint32_t a_base = (uint32_t)(wm * 32 + lr) * ROW_BYTES + (uint32_t)lc * 16;
    uint32_t b_base = (uint32_t)(wn * 32 + lr) * ROW_BYTES + (uint32_t)lc * 16;

    #pragma unroll
    for (int kc = 0; kc < 2; kc++) {
        uint32_t koff = (uint32_t)kc * 32;
        uint32_t a0[2][4], a1[2][4], b0[2][4], b1[2][4];
        #pragma unroll
        for (int mi = 0; mi < 2; mi++) {
            uint32_t o = a_base + (uint32_t)mi * (16 * ROW_BYTES) + koff;
            ldm_x4(a0[mi], sb + OFF_A0 + o);
            ldm_x4(a1[mi], sb + OFF_A1 + o);
        }
        #pragma unroll
        for (int p = 0; p < 2; p++) {
            uint32_t o = b_base + (uint32_t)p * (16 * ROW_BYTES) + koff;
            ldm_x4(b0[p], sb + OFF_B0 + o);
            ldm_x4(b1[p], sb + OFF_B1 + o);
        }
        #pragma unroll
        for (int mi = 0; mi < 2; mi++) {
            #pragma unroll
            for (int ni = 0; ni < 4; ni++) {
                int p = ni >> 1, q = ni & 1;
                uint32_t c00 = b0[p][q], c01 = b0[p][q + 2];
                mma_s8(acc0[mi][ni], a0[mi], c00, c01);
                mma_s8(accX[mi][ni], a0[mi], b1[p][q], b1[p][q + 2]);
                mma_s8(accX[mi][ni], a1[mi], c00, c01);
            }
        }
    }
}

// Dual-segment continuous pipeline: stages [0,nst1) from set1, rest from set2.
__device__ void gemm_dual_i8(
    uint32_t sbase,
    const char* A1a, const char* A1b, int lda1,
    const char* B1a, const char* B1b, int ldb1, int K1,
    const char* A2a, const char* A2b, int lda2,
    const char* B2a, const char* B2b, int ldb2, int K2,
    int m0, int n0,
    int (&acc0)[2][4][4], int (&accX)[2][4][4])
{
    int nst1 = K1 / I_BK;
    int nst = nst1 + K2 / I_BK;

    #pragma unroll
    for (int p = 0; p < DEPTH - 1; p++) {
        if (p < nst) {
            if (p < nst1)
                load_stage_i8(sbase + (uint32_t)p * STAGE_BYTES,
                              A1a, A1b, lda1, m0, B1a, B1b, ldb1, n0, p * I_BK);
            else
                load_stage_i8(sbase + (uint32_t)p * STAGE_BYTES,
                              A2a, A2b, lda2, m0, B2a, B2b, ldb2, n0,
                              (p - nst1) * I_BK);
        }
        cp_commit();
    }
    for (int s = 0; s < nst; s++) {
        cp_wait<DEPTH - 2>();
        __syncthreads();
        int nf = s + DEPTH - 1;
        if (nf < nst) {
            uint32_t buf = sbase + (uint32_t)(nf % DEPTH) * STAGE_BYTES;
            if (nf < nst1)
                load_stage_i8(buf, A1a, A1b, lda1, m0, B1a, B1b, ldb1, n0,
                              nf * I_BK);
            else
                load_stage_i8(buf, A2a, A2b, lda2, m0, B2a, B2b, ldb2, n0,
                              (nf - nst1) * I_BK);
        }
        cp_commit();
        compute_stage_i8(sbase + (uint32_t)(s % DEPTH) * STAGE_BYTES, acc0, accX);
    }
}

__device__ __forceinline__ void quant_state(float v, int& q0, int& q1) {
    float v128 = v * 128.f;
    q0 = __float2int_rn(v128);
    if (q0 > 127) q0 = 127;
    float r = (v128 - (float)q0) * 128.f;
    q1 = __float2int_rn(r);
    if (q1 > 127) q1 = 127;
    if (q1 < -128) q1 = -128;
}

__device__ void epilogue_i8(
    int (&acc0)[2][4][4], int (&accX)[2][4][4], int m0, int n0, int outw,
    const float* __restrict__ bias, const float* __restrict__ addm,
    const float* __restrict__ addm2,
    char* __restrict__ o0, char* __restrict__ o1, float* __restrict__ of)
{
    const float S0 = 0x1p-19f, SX = 0x1p-26f;
    int tid = threadIdx.x;
    int lane = tid & 31, wid = tid >> 5;
    int wm = wid >> 1, wn = wid & 1;
    int g = lane >> 2, t = lane & 3;

    #pragma unroll
    for (int mi = 0; mi < 2; mi++) {
        #pragma unroll
        for (int ni = 0; ni < 4; ni++) {
            int nc = n0 + wn * 32 + ni * 8 + 2 * t;
            float bv0 = 0.f, bv1 = 0.f;
            if (bias) { bv0 = bias[nc]; bv1 = bias[nc + 1]; }
            #pragma unroll
            for (int h = 0; h < 2; h++) {
                int mr = m0 + wm * 32 + mi * 16 + g + h * 8;
                float v0 = (float)acc0[mi][ni][2 * h + 0] * S0
                         + (float)accX[mi][ni][2 * h + 0] * SX + bv0;
                float v1 = (float)acc0[mi][ni][2 * h + 1] * S0
                         + (float)accX[mi][ni][2 * h + 1] * SX + bv1;
                size_t o = (size_t)mr * outw + nc;
                if (addm) {
                    float2 av = *(const float2*)&addm[o];
                    v0 += av.x; v1 += av.y;
                }
                if (addm2) {
                    float2 av = *(const float2*)&addm2[o];
                    v0 += av.x; v1 += av.y;
                }
                v0 = fminf(fmaxf(v0, 0.f), 1.f);
                v1 = fminf(fmaxf(v1, 0.f), 1.f);
                if (o0) {
                    int a0, a1, b0, b1;
                    quant_state(v0, a0, a1);
                    quant_state(v1, b0, b1);
                    char2 p0; p0.x = (char)a0; p0.y = (char)b0;
                    char2 p1; p1.x = (char)a1; p1.y = (char)b1;
                    *(char2*)&o0[o] = p0;
                    *(char2*)&o1[o] = p1;
                }
                if (of) *(float2*)&of[o] = make_float2(v0, v1);
            }
        }
    }
}

// ---------------------------------------------------------------------------
// Persistent kernel: all T_STEPS steps, grid barrier between steps.
// 144 CTAs: [0,16) s0' 2x8   [16,80) s1' 2x32   [80,144) s2' 2x32
// ---------------------------------------------------------------------------
__global__ void __launch_bounds__(256, 1) ep_steps_persist(
    char* s0base, char* s1base, char* s2base,
    const char* W0a, const char* W0b,
    const char* W1a, const char* W1b,
    const char* W0Ta, const char* W0Tb,
    const char* W1Ta, const char* W1Tb,
    const float* b0, const float* b1,
    const float* c2, const float* c2p, float* out)
{
    extern __shared__ char dyn[];
    uint32_t sb = smem_u32(dyn);
    const size_t n0e = (size_t)BATCH * D0;
    const size_t n1e = (size_t)BATCH * D1;
    const size_t n2e = (size_t)BATCH * D2;
    int blk = blockIdx.x;

    for (int t = 1; t <= T_STEPS; t++) {
        int pi = (t - 1) & 1, po = t & 1;
        const char* i0a = s0base + (size_t)pi * 2 * n0e; const char* i0b = i0a + n0e;
        const char* i1a = s1base + (size_t)pi * 2 * n1e; const char* i1b = i1a + n1e;
        const char* i2a = s2base + (size_t)pi * 2 * n2e; const char* i2b = i2a + n2e;
        bool last = (t == T_STEPS);
        char *o0a = nullptr, *o0b = nullptr, *o1a = nullptr, *o1b = nullptr,
             *o2a = nullptr, *o2b = nullptr;
        float *f0 = nullptr, *f1 = nullptr, *f2 = nullptr;
        if (last) {
            f0 = out;
            f1 = out + n0e;
            f2 = out + n0e + n1e;
        } else {
            o0a = s0base + (size_t)po * 2 * n0e; o0b = o0a + n0e;
            o1a = s1base + (size_t)po * 2 * n1e; o1b = o1a + n1e;
            o2a = s2base + (size_t)po * 2 * n2e; o2b = o2a + n2e;
        }

        int acc0[2][4][4], accX[2][4][4];
        #pragma unroll
        for (int i = 0; i < 2; i++)
            #pragma unroll
            for (int j = 0; j < 4; j++)
                #pragma unroll
                for (int k = 0; k < 4; k++) { acc0[i][j][k] = 0; accX[i][j][k] = 0; }

        if (blk < 16) {
            int m0 = (blk >> 3) * BM, n0 = (blk & 7) * BN;
            gemm_dual_i8(sb, i1a, i1b, D1, W0a, W0b, D1, D1,
                         i1a, i1b, D1, W0a, W0b, D1, 0,
                         m0, n0, acc0, accX);
            epilogue_i8(acc0, accX, m0, n0, D0, b0, nullptr, nullptr, o0a, o0b, f0);
        } else if (blk < 80) {
            int l = blk - 16;
            int m0 = (l >> 5) * BM, n0 = (l & 31) * BN;
            gemm_dual_i8(sb, i2a, i2b, D2, W1a, W1b, D2, D2,
                         i0a, i0b, D0, W0Ta, W0Tb, D0, D0,
                         m0, n0, acc0, accX);
            epilogue_i8(acc0, accX, m0, n0, D1, b1, nullptr, nullptr, o1a, o1b, f1);
        } else {
            int l = blk - 80;
            int m0 = (l >> 5) * BM, n0 = (l & 31) * BN;
            gemm_dual_i8(sb, i1a, i1b, D1, W1Ta, W1Tb, D1, D1,
                         i1a, i1b, D1, W1Ta, W1Tb, D1, 0,
                         m0, n0, acc0, accX);
            epilogue_i8(acc0, accX, m0, n0, D2, nullptr, c2, c2p, o2a, o2b, f2);
        }

        if (t < T_STEPS) grid_barrier(t);
    }
}

// ============================ bf16 path (C2) ===============================
__device__ __forceinline__ void load_stage_bf(
    uint32_t sb,
    const __nv_bfloat16* __restrict__ Ah, const __nv_bfloat16* __restrict__ Al,
    int lda, int m0,
    const __nv_bfloat16* __restrict__ Bh, const __nv_bfloat16* __restrict__ Bl,
    int ldb, int n0, int k0)
{
    int t = threadIdx.x;
    {
        int r = t >> 1, cb = (t & 1) * 2;
        uint32_t rowoff = (uint32_t)r * ROW_BYTES;
        const __nv_bfloat16* pah = Ah + (size_t)(m0 + r) * lda + k0;
        const __nv_bfloat16* pal = Al + (size_t)(m0 + r) * lda + k0;
        #pragma unroll
        for (int j = 0; j < 2; j++) {
            int c = cb + j;
            uint32_t d = rowoff + (uint32_t)c * 16;
            cp16(sb + OFF_A0 + d, pah + c * 8);
            cp16(sb + OFF_A1 + d, pal + c * 8);
        }
    }
    {
        int r = t >> 2, c = t & 3;
        uint32_t d = (uint32_t)r * ROW_BYTES + (uint32_t)c * 16;
        const __nv_bfloat16* pbh = Bh + (size_t)(n0 + r) * ldb + k0;
        const __nv_bfloat16* pbl = Bl + (size_t)(n0 + r) * ldb + k0;
        cp16(sb + OFF_B0 + d, pbh + c * 8);
        cp16(sb + OFF_B1 + d, pbl + c * 8);
    }
}

__device__ __forceinline__ void compute_stage_bf(uint32_t sb, float (&acc)[2][4][4])
{
    int tid = threadIdx.x;
    int lane = tid & 31, wid = tid >> 5;
    int wm = wid >> 1, wn = wid & 1;
    int lr = lane & 15, lc = lane >> 4;
    uint32_t a_base = (uint32_t)(wm * 32 + lr) * ROW_BYTES + (uint32_t)lc * 16;
    uint32_t b_base = (uint32_t)(wn * 32 + lr) * ROW_BYTES + (uint32_t)lc * 16;

    #pragma unroll
    for (int kk = 0; kk < 2; kk++) {
        uint32_t koff = (uint32_t)kk * 32;
        uint32_t ah[2][4], al[2][4], bh[2][4], bl[2][4];
        #pragma unroll
        for (int mi = 0; mi < 2; mi++) {
            uint32_t o = a_base + (uint32_t)mi * (16 * ROW_BYTES) + koff;
            ldm_x4(ah[mi], sb + OFF_A0 + o);
            ldm_x4(al[mi], sb + OFF_A1 + o);
        }
        #pragma unroll
        for (int p = 0; p < 2; p++) {
            uint32_t o = b_base + (uint32_t)p * (16 * ROW_BYTES) + koff;
            ldm_x4(bh[p], sb + OFF_B0 + o);
            ldm_x4(bl[p], sb + OFF_B1 + o);
        }
        #pragma unroll
        for (int mi = 0; mi < 2; mi++) {
            #pragma unroll
            for (int ni = 0; ni < 4; ni++) {
                int p = ni >> 1, q = ni & 1;
                uint32_t bh0 = bh[p][q], bh1 = bh[p][q + 2];
                mma_bf16(acc[mi][ni], ah[mi], bh0, bh1);
                mma_bf16(acc[mi][ni], ah[mi], bl[p][q], bl[p][q + 2]);
                mma_bf16(acc[mi][ni], al[mi], bh0, bh1);
            }
        }
    }
}

// C2 split-K: 128 CTAs. half 0: c2 = z(K[0,2048)) + b2. half 1: c2p = z(K[2048,4096)).
__global__ void __launch_bounds__(256, 1) ep_c2_kernel(
    const __nv_bfloat16* dh, const __nv_bfloat16* dl,
    const __nv_bfloat16* W2h, const __nv_bfloat16* W2l,
    const float* b2, float* c2, float* c2p)
{
    extern __shared__ char dyn[];
    uint32_t sb = smem_u32(dyn);

    float acc[2][4][4];
    #pragma unroll
    for (int i = 0; i < 2; i++)
        #pragma unroll
        for (int j = 0; j < 4; j++)
            #pragma unroll
            for (int k = 0; k < 4; k++) acc[i][j][k] = 0.f;

    int blk = blockIdx.x;
    int half = blk >> 6;
    int l = blk & 63;
    int m0 = (l >> 5) * BM, n0 = (l & 31) * BN;
    int kbase = half * (DIN / 2);
    int nst = (DIN / 2) / BF_BK;   // 32

    #pragma unroll
    for (int p = 0; p < DEPTH - 1; p++) {
        if (p < nst)
            load_stage_bf(sb + (uint32_t)p * STAGE_BYTES,
                          dh, dl, DIN, m0, W2h, W2l, DIN, n0, kbase + p * BF_BK);
        cp_commit();
    }
    for (int s = 0; s < nst; s++) {
        cp_wait<DEPTH - 2>();
        __syncthreads();
        int nf = s + DEPTH - 1;
        if (nf < nst)
            load_stage_bf(sb + (uint32_t)(nf % DEPTH) * STAGE_BYTES,
                          dh, dl, DIN, m0, W2h, W2l, DIN, n0, kbase + nf * BF_BK);
        cp_commit();
        compute_stage_bf(sb + (uint32_t)(s % DEPTH) * STAGE_BYTES, acc);
    }

    int tid = threadIdx.x;
    int lane = tid & 31, wid = tid >> 5;
    int wm = wid >> 1, wn = wid & 1;
    int g = lane >> 2, t = lane & 3;
    float* dst = half ? c2p : c2;
    #pragma unroll
    for (int mi = 0; mi < 2; mi++) {
        #pragma unroll
        for (int ni = 0; ni < 4; ni++) {
            int nc = n0 + wn * 32 + ni * 8 + 2 * t;
            float bv0 = half ? 0.f : b2[nc];
            float bv1 = half ? 0.f : b2[nc + 1];
            #pragma unroll
            for (int h = 0; h < 2; h++) {
                int mr = m0 + wm * 32 + mi * 16 + g + h * 8;
                float v0 = acc[mi][ni][2 * h + 0] + bv0;
                float v1 = acc[mi][ni][2 * h + 1] + bv1;
                *(float2*)&dst[(size_t)mr * D2 + nc] = make_float2(v0, v1);
            }
        }
    }
}

// ====================== fused conversion kernel ============================
__device__ __forceinline__ void quant_w(float w, int& q0, int& q1) {
    float w0 = w * 4096.f;
    q0 = __float2int_rn(w0);
    if (q0 > 127) q0 = 127;
    if (q0 < -128) q0 = -128;
    float r = (w0 - (float)q0) * 128.f;
    q1 = __float2int_rn(r);
    if (q1 > 127) q1 = 127;
    if (q1 < -128) q1 = -128;
}
__device__ __forceinline__ void quant_s_clamped(float v, int& q0, int& q1) {
    v = fminf(fmaxf(v, -1.f), 1.f);
    float v128 = v * 128.f;
    q0 = __float2int_rn(v128);
    if (q0 > 127) q0 = 127;
    if (q0 < -128) q0 = -128;
    float r = (v128 - (float)q0) * 128.f;
    q1 = __float2int_rn(r);
    if (q1 > 127) q1 = 127;
    if (q1 < -128) q1 = -128;
}

__device__ __forceinline__ void vec4_quant_w(const float* x, char* l0, char* l1, int idx) {
    float4 v = *(const float4*)&x[idx];
    int a0, a1, b0, b1, c0, c1, d0, d1;
    quant_w(v.x, a0, a1); quant_w(v.y, b0, b1);
    quant_w(v.z, c0, c1); quant_w(v.w, d0, d1);
    char4 p0; p0.x = (char)a0; p0.y = (char)b0; p0.z = (char)c0; p0.w = (char)d0;
    char4 p1; p1.x = (char)a1; p1.y = (char)b1; p1.z = (char)c1; p1.w = (char)d1;
    *(char4*)&l0[idx] = p0;
    *(char4*)&l1[idx] = p1;
}
__device__ __forceinline__ void vec4_split_bf(const float* x, __nv_bfloat16* h,
                                              __nv_bfloat16* l, int idx) {
    float4 v = *(const float4*)&x[idx];
    __nv_bfloat16 h0 = __float2bfloat16(v.x), h1 = __float2bfloat16(v.y);
    __nv_bfloat16 h2 = __float2bfloat16(v.z), h3 = __float2bfloat16(v.w);
    __nv_bfloat162 hp0, hp1, lp0, lp1;
    hp0.x = h0; hp0.y = h1; hp1.x = h2; hp1.y = h3;
    lp0.x = __float2bfloat16(v.x - __bfloat162float(h0));
    lp0.y = __float2bfloat16(v.y - __bfloat162float(h1));
    lp1.x = __float2bfloat16(v.z - __bfloat162float(h2));
    lp1.y = __float2bfloat16(v.w - __bfloat162float(h3));
    *(__nv_bfloat162*)&h[idx] = hp0;
    *(__nv_bfloat162*)&h[idx + 2] = hp1;
    *(__nv_bfloat162*)&l[idx] = lp0;
    *(__nv_bfloat162*)&l[idx + 2] = lp1;
}
__device__ __forceinline__ void vec4_quant_s(const float* x, char* l0, char* l1, int idx) {
    float4 v = *(const float4*)&x[idx];
    int a0, a1, b0, b1, c0, c1, d0, d1;
    quant_s_clamped(v.x, a0, a1); quant_s_clamped(v.y, b0, b1);
    quant_s_clamped(v.z, c0, c1); quant_s_clamped(v.w, d0, d1);
    char4 p0; p0.x = (char)a0; p0.y = (char)b0; p0.z = (char)c0; p0.w = (char)d0;
    char4 p1; p1.x = (char)a1; p1.y = (char)b1; p1.z = (char)c1; p1.w = (char)d1;
    *(char4*)&l0[idx] = p0;
    *(char4*)&l1[idx] = p1;
}

// block ranges
#define CB_W1   1024
#define CB_W2   5120
#define CB_DATA 13312
#define CB_S0   14336
#define CB_S1   14464
#define CB_S2   14976
#define CB_W0T  15488
#define CB_W1T  16512
#define CB_TOTAL 20608

__global__ void __launch_bounds__(256) fused_convert(
    const float* __restrict__ W0, const float* __restrict__ W1,
    const float* __restrict__ W2, const float* __restrict__ data,
    const float* __restrict__ s0, const float* __restrict__ s1,
    const float* __restrict__ s2,
    char* W0a, char* W0b, char* W1a, char* W1b,
    char* W0Ta, char* W0Tb, char* W1Ta, char* W1Tb,
    __nv_bfloat16* W2h, __nv_bfloat16* W2l,
    __nv_bfloat16* dh, __nv_bfloat16* dl,
    char* s0a, char* s0b, char* s1a, char* s1b, char* s2a, char* s2b)
{
    __shared__ float tile[32][33];
    int b = blockIdx.x, tid = threadIdx.x;
    if (b == 0 && tid == 0) { g_cnt = 0; g_release = 0; }

    if (b < CB_W1) {
        vec4_quant_w(W0, W0a, W0b, (b * 256 + tid) * 4);
    } else if (b < CB_W2) {
        vec4_quant_w(W1, W1a, W1b, ((b - CB_W1) * 256 + tid) * 4);
    } else if (b < CB_DATA) {
        vec4_split_bf(W2, W2h, W2l, ((b - CB_W2) * 256 + tid) * 4);
    } else if (b < CB_S0) {
        vec4_split_bf(data, dh, dl, ((b - CB_DATA) * 256 + tid) * 4);
    } else if (b < CB_S1) {
        vec4_quant_s(s0, s0a, s0b, ((b - CB_S0) * 256 + tid) * 4);
    } else if (b < CB_S2) {
        vec4_quant_s(s1, s1a, s1b, ((b - CB_S1) * 256 + tid) * 4);
    } else if (b < CB_W0T) {
        vec4_quant_s(s2, s2a, s2b, ((b - CB_S2) * 256 + tid) * 4);
    } else if (b < CB_W1T) {
        // W0 (D0 x D1) -> W0T (D1 x D0) int8 limbs
        int local = b - CB_W0T;
        int bx = local % (D1 / 32), by = local / (D1 / 32);
        int tx = tid & 31, ty = tid >> 5;
        int c0 = bx * 32, r0 = by * 32;
        #pragma unroll
        for (int k = 0; k < 4; k++)
            tile[ty + 8 * k][tx] = W0[(size_t)(r0 + ty + 8 * k) * D1 + c0 + tx];
        __syncthreads();
        #pragma unroll
        for (int k = 0; k < 4; k++) {
            float v = tile[tx][ty + 8 * k];
            int q0, q1;
            quant_w(v, q0, q1);
            size_t o = (size_t)(c0 + ty + 8 * k) * D0 + r0 + tx;
            W0Ta[o] = (char)q0;
            W0Tb[o] = (char)q1;
        }
    } else {
        // W1 (D1 x D2) -> W1T (D2 x D1) int8 limbs
        int local = b - CB_W1T;
        int bx = local % (D2 / 32), by = local / (D2 / 32);
        int tx = tid & 31, ty = tid >> 5;
        int c0 = bx * 32, r0 = by * 32;
        #pragma unroll
        for (int k = 0; k < 4; k++)
            tile[ty + 8 * k][tx] = W1[(size_t)(r0 + ty + 8 * k) * D2 + c0 + tx];
        __syncthreads();
        #pragma unroll
        for (int k = 0; k < 4; k++) {
            float v = tile[tx][ty + 8 * k];
            int q0, q1;
            quant_w(v, q0, q1);
            size_t o = (size_t)(c0 + ty + 8 * k) * D1 + r0 + tx;
            W1Ta[o] = (char)q0;
            W1Tb[o] = (char)q1;
        }
    }
}

// ------------------------------- host side ---------------------------------
static inline void* sym(const void* s) {
    void* p = nullptr;
    cudaGetSymbolAddress(&p, s);
    return p;
}

extern "C" void kernel_launch(void* const* d_in, const int* in_sizes, int n_in,
                              void* d_out, int out_size)
{
    const float* data = (const float*)d_in[0];
    const float* in_s0 = (const float*)d_in[1];
    const float* in_s1 = (const float*)d_in[2];
    const float* in_s2 = (const float*)d_in[3];
    const float* W0 = (const float*)d_in[4];
    const float* b0 = (const float*)d_in[5];
    const float* W1 = (const float*)d_in[6];
    const float* b1 = (const float*)d_in[7];
    const float* W2 = (const float*)d_in[8];
    const float* b2 = (const float*)d_in[9];
    float* out = (float*)d_out;

    cudaFuncSetAttribute(ep_steps_persist, cudaFuncAttributeMaxDynamicSharedMemorySize, DSMEM_BYTES);
    cudaFuncSetAttribute(ep_c2_kernel,     cudaFuncAttributeMaxDynamicSharedMemorySize, DSMEM_BYTES);

    char *W0a = (char*)sym(g_iW0),   *W0b = W0a + (size_t)D0 * D1;
    char *W1a = (char*)sym(g_iW1),   *W1b = W1a + (size_t)D1 * D2;
    char *W0Ta = (char*)sym(g_iW0T), *W0Tb = W0Ta + (size_t)D1 * D0;
    char *W1Ta = (char*)sym(g_iW1T), *W1Tb = W1Ta + (size_t)D2 * D1;
    char *s0base = (char*)sym(g_is0);
    char *s1base = (char*)sym(g_is1);
    char *s2base = (char*)sym(g_is2);
    __nv_bfloat16 *W2h = (__nv_bfloat16*)sym(g_W2h), *W2l = (__nv_bfloat16*)sym(g_W2l);
    __nv_bfloat16 *dh = (__nv_bfloat16*)sym(g_dh),   *dl = (__nv_bfloat16*)sym(g_dl);
    float* c2 = (float*)sym(g_c2);
    float* c2p = (float*)sym(g_c2p);

    const size_t n0e = (size_t)BATCH * D0;
    const size_t n1e = (size_t)BATCH * D1;
    const size_t n2e = (size_t)BATCH * D2;

    fused_convert<<<CB_TOTAL, 256>>>(
        W0, W1, W2, data, in_s0, in_s1, in_s2,
        W0a, W0b, W1a, W1b, W0Ta, W0Tb, W1Ta, W1Tb,
        W2h, W2l, dh, dl,
        s0base, s0base + n0e, s1base, s1base + n1e, s2base, s2base + n2e);

    ep_c2_kernel<<<128, 256, DSMEM_BYTES>>>(dh, dl, W2h, W2l, b2, c2, c2p);

    ep_steps_persist<<<NBLK, 256, DSMEM_BYTES>>>(
        s0base, s1base, s2base,
        W0a, W0b, W1a, W1b, W0Ta, W0Tb, W1Ta, W1Tb,
        b0, b1, c2, c2p, out);
}

// round 8
// speedup vs baseline: 4.9163x; 1.1725x over previous
#include <cuda_runtime.h>
#include <cuda_fp16.h>
#include <cstdint>
#include <cstddef>

// ---------------------------------------------------------------------------
// EP free-phase relaxation. Persistent single-pass fp16 mma.sync kernel
// (m16n8k16.f32.f16.f16.f32, fp32 accumulation). All 20 steps in one launch
// with a software grid barrier. C2 = data@W2^T + b2 via the same fp16 path,
// split-K over 128 CTAs (c2 + c2p, summed deterministically in s2 epilogue).
// ---------------------------------------------------------------------------

#define BATCH 256
#define D0 512
#define D1 2048
#define D2 2048
#define DIN 4096
#define T_STEPS 20
#define NBLK 144

#define BM 128
#define BN 64
#define BK 64
#define DEPTH 4

#define ROW_BYTES 144                    // 64 halves (128B) + 16B pad
#define A_MAT (128 * ROW_BYTES)          // 18432
#define B_MAT (64 * ROW_BYTES)           // 9216
#define OFF_A 0
#define OFF_B (A_MAT)
#define STAGE_BYTES (A_MAT + B_MAT)      // 27648
#define DSMEM_BYTES (DEPTH * STAGE_BYTES) // 110592

// --------------------------- device scratch --------------------------------
__device__ __half g_hW0[D0 * D1];
__device__ __half g_hW1[D1 * D2];
__device__ __half g_hW0T[D1 * D0];
__device__ __half g_hW1T[D2 * D1];
__device__ __half g_hW2[D2 * DIN];
__device__ __half g_hd[BATCH * DIN];
__device__ __half g_hs0[2][BATCH * D0];
__device__ __half g_hs1[2][BATCH * D1];
__device__ __half g_hs2[2][BATCH * D2];
__device__ float g_c2[BATCH * D2];
__device__ float g_c2p[BATCH * D2];
__device__ int g_cnt;
__device__ volatile int g_release;

// ------------------------------ PTX helpers --------------------------------
__device__ __forceinline__ uint32_t smem_u32(const void* p) {
    uint32_t a;
    asm("{ .reg .u64 t; cvta.to.shared.u64 t, %1; cvt.u32.u64 %0, t; }"
        : "=r"(a) : "l"(p));
    return a;
}
__device__ __forceinline__ void cp16(uint32_t dst, const void* src) {
    asm volatile("cp.async.cg.shared.global [%0], [%1], 16;"
                 :: "r"(dst), "l"(src) : "memory");
}
__device__ __forceinline__ void cp_commit() {
    asm volatile("cp.async.commit_group;" ::: "memory");
}
template <int N>
__device__ __forceinline__ void cp_wait() {
    asm volatile("cp.async.wait_group %0;" :: "n"(N) : "memory");
}
__device__ __forceinline__ void ldm_x4(uint32_t (&r)[4], uint32_t addr) {
    asm volatile("ldmatrix.sync.aligned.m8n8.x4.shared.b16 {%0,%1,%2,%3}, [%4];"
                 : "=r"(r[0]), "=r"(r[1]), "=r"(r[2]), "=r"(r[3]) : "r"(addr));
}
__device__ __forceinline__ void mma_f16(float (&d)[4], const uint32_t (&a)[4],
                                        uint32_t b0, uint32_t b1) {
    asm volatile(
        "mma.sync.aligned.m16n8k16.row.col.f32.f16.f16.f32 "
        "{%0,%1,%2,%3}, {%4,%5,%6,%7}, {%8,%9}, {%0,%1,%2,%3};"
        : "+f"(d[0]), "+f"(d[1]), "+f"(d[2]), "+f"(d[3])
        : "r"(a[0]), "r"(a[1]), "r"(a[2]), "r"(a[3]), "r"(b0), "r"(b1));
}

// Software grid barrier (cumulative counter; reset by fused_convert)
__device__ __forceinline__ void grid_barrier(int target) {
    __syncthreads();
    if (threadIdx.x == 0) {
        __threadfence();
        int t = atomicAdd(&g_cnt, 1);
        if (t == target * NBLK - 1) {
            g_release = target;
        } else {
            while (g_release < target) { }
        }
        __threadfence();
    }
    __syncthreads();
}

// ---------------------------------------------------------------------------
// Stage loader: A rows [m0,m0+128) x k[k0,k0+64) fp16, B rows [n0,n0+64).
// 256 threads, 6 cp16 each (4 A, 2 B).
// ---------------------------------------------------------------------------
__device__ __forceinline__ void load_stage(
    uint32_t sb,
    const __half* __restrict__ A, int lda, int m0,
    const __half* __restrict__ B, int ldb, int n0, int k0)
{
    int t = threadIdx.x;
    {   // A: row = t>>1, chunks (t&1)*4 .. +3
        int r = t >> 1, cb = (t & 1) * 4;
        uint32_t rowoff = (uint32_t)r * ROW_BYTES;
        const __half* pa = A + (size_t)(m0 + r) * lda + k0;
        #pragma unroll
        for (int j = 0; j < 4; j++) {
            int c = cb + j;
            cp16(sb + OFF_A + rowoff + (uint32_t)c * 16, pa + c * 8);
        }
    }
    {   // B: row = t>>2, chunks (t&3)*2 .. +1
        int r = t >> 2, cb = (t & 3) * 2;
        uint32_t rowoff = (uint32_t)r * ROW_BYTES;
        const __half* pb = B + (size_t)(n0 + r) * ldb + k0;
        #pragma unroll
        for (int j = 0; j < 2; j++) {
            int c = cb + j;
            cp16(sb + OFF_B + rowoff + (uint32_t)c * 16, pb + c * 8);
        }
    }
}

// ---------------------------------------------------------------------------
// One BK=64 stage: 4 k16 blocks, single-pass fp16 MMAs.
// 8 warps 4(m) x 2(n), warp tile 32x32, acc[2][4][4].
// ---------------------------------------------------------------------------
__device__ __forceinline__ void compute_stage(uint32_t sb, float (&acc)[2][4][4])
{
    int tid = threadIdx.x;
    int lane = tid & 31, wid = tid >> 5;
    int wm = wid >> 1, wn = wid & 1;
    int lr = lane & 15, lc = lane >> 4;
    uint32_t a_base = (uint32_t)(wm * 32 + lr) * ROW_BYTES + (uint32_t)lc * 16;
    uint32_t b_base = (uint32_t)(wn * 32 + lr) * ROW_BYTES + (uint32_t)lc * 16;

    #pragma unroll
    for (int kk = 0; kk < 4; kk++) {
        uint32_t koff = (uint32_t)kk * 32;
        uint32_t a[2][4], b[2][4];
        #pragma unroll
        for (int mi = 0; mi < 2; mi++)
            ldm_x4(a[mi], sb + OFF_A + a_base + (uint32_t)mi * (16 * ROW_BYTES) + koff);
        #pragma unroll
        for (int p = 0; p < 2; p++)
            ldm_x4(b[p], sb + OFF_B + b_base + (uint32_t)p * (16 * ROW_BYTES) + koff);
        #pragma unroll
        for (int mi = 0; mi < 2; mi++) {
            #pragma unroll
            for (int ni = 0; ni < 4; ni++) {
                int p = ni >> 1, q = ni & 1;
                mma_f16(acc[mi][ni], a[mi], b[p][q], b[p][q + 2]);
            }
        }
    }
}

// Dual-segment continuous pipeline: stages [0,nst1) from set1, rest from set2.
__device__ void gemm_dual(
    uint32_t sbase,
    const __half* A1, int lda1, const __half* B1, int ldb1, int K1,
    const __half* A2, int lda2, const __half* B2, int ldb2, int K2,
    int m0, int n0, int kbase1, float (&acc)[2][4][4])
{
    int nst1 = K1 / BK;
    int nst = nst1 + K2 / BK;

    #pragma unroll
    for (int p = 0; p < DEPTH - 1; p++) {
        if (p < nst) {
            if (p < nst1)
                load_stage(sbase + (uint32_t)p * STAGE_BYTES,
                           A1, lda1, m0, B1, ldb1, n0, kbase1 + p * BK);
            else
                load_stage(sbase + (uint32_t)p * STAGE_BYTES,
                           A2, lda2, m0, B2, ldb2, n0, (p - nst1) * BK);
        }
        cp_commit();
    }
    for (int s = 0; s < nst; s++) {
        cp_wait<DEPTH - 2>();
        __syncthreads();
        int nf = s + DEPTH - 1;
        if (nf < nst) {
            uint32_t buf = sbase + (uint32_t)(nf % DEPTH) * STAGE_BYTES;
            if (nf < nst1)
                load_stage(buf, A1, lda1, m0, B1, ldb1, n0, kbase1 + nf * BK);
            else
                load_stage(buf, A2, lda2, m0, B2, ldb2, n0, (nf - nst1) * BK);
        }
        cp_commit();
        compute_stage(sbase + (uint32_t)(s % DEPTH) * STAGE_BYTES, acc);
    }
}

// ---------------------------------------------------------------------------
// Epilogue: bias / C2-add / rho, write fp16 state (next step) and/or fp32.
// ---------------------------------------------------------------------------
__device__ void epilogue(
    float (&acc)[2][4][4], int m0, int n0, int outw,
    const float* __restrict__ bias, const float* __restrict__ addm,
    const float* __restrict__ addm2, bool do_rho,
    __half* __restrict__ oh, float* __restrict__ of)
{
    int tid = threadIdx.x;
    int lane = tid & 31, wid = tid >> 5;
    int wm = wid >> 1, wn = wid & 1;
    int g = lane >> 2, t = lane & 3;

    #pragma unroll
    for (int mi = 0; mi < 2; mi++) {
        #pragma unroll
        for (int ni = 0; ni < 4; ni++) {
            int nc = n0 + wn * 32 + ni * 8 + 2 * t;
            float bv0 = 0.f, bv1 = 0.f;
            if (bias) { bv0 = bias[nc]; bv1 = bias[nc + 1]; }
            #pragma unroll
            for (int h = 0; h < 2; h++) {
                int mr = m0 + wm * 32 + mi * 16 + g + h * 8;
                float v0 = acc[mi][ni][2 * h + 0] + bv0;
                float v1 = acc[mi][ni][2 * h + 1] + bv1;
                size_t o = (size_t)mr * outw + nc;
                if (addm) {
                    float2 av = *(const float2*)&addm[o];
                    v0 += av.x; v1 += av.y;
                }
                if (addm2) {
                    float2 av = *(const float2*)&addm2[o];
                    v0 += av.x; v1 += av.y;
                }
                if (do_rho) {
                    v0 = fminf(fmaxf(v0, 0.f), 1.f);
                    v1 = fminf(fmaxf(v1, 0.f), 1.f);
                }
                if (oh) {
                    __half2 hp;
                    hp.x = __float2half_rn(v0);
                    hp.y = __float2half_rn(v1);
                    *(__half2*)&oh[o] = hp;
                }
                if (of) *(float2*)&of[o] = make_float2(v0, v1);
            }
        }
    }
}

// ---------------------------------------------------------------------------
// Persistent kernel: all T_STEPS steps, grid barrier between steps.
// 144 CTAs: [0,16) s0' 2x8   [16,80) s1' 2x32   [80,144) s2' 2x32
// ---------------------------------------------------------------------------
__global__ void __launch_bounds__(256, 1) ep_steps_persist(
    __half* s0base, __half* s1base, __half* s2base,
    const __half* W0, const __half* W1,
    const __half* W0T, const __half* W1T,
    const float* b0, const float* b1,
    const float* c2, const float* c2p, float* out)
{
    extern __shared__ char dyn[];
    uint32_t sb = smem_u32(dyn);
    const size_t n0e = (size_t)BATCH * D0;
    const size_t n1e = (size_t)BATCH * D1;
    const size_t n2e = (size_t)BATCH * D2;
    int blk = blockIdx.x;

    for (int t = 1; t <= T_STEPS; t++) {
        int pi = (t - 1) & 1, po = t & 1;
        const __half* i0 = s0base + (size_t)pi * n0e;
        const __half* i1 = s1base + (size_t)pi * n1e;
        const __half* i2 = s2base + (size_t)pi * n2e;
        bool last = (t == T_STEPS);
        __half *o0 = nullptr, *o1 = nullptr, *o2 = nullptr;
        float *f0 = nullptr, *f1 = nullptr, *f2 = nullptr;
        if (last) {
            f0 = out;
            f1 = out + n0e;
            f2 = out + n0e + n1e;
        } else {
            o0 = s0base + (size_t)po * n0e;
            o1 = s1base + (size_t)po * n1e;
            o2 = s2base + (size_t)po * n2e;
        }

        float acc[2][4][4];
        #pragma unroll
        for (int i = 0; i < 2; i++)
            #pragma unroll
            for (int j = 0; j < 4; j++)
                #pragma unroll
                for (int k = 0; k < 4; k++) acc[i][j][k] = 0.f;

        if (blk < 16) {
            int m0 = (blk >> 3) * BM, n0 = (blk & 7) * BN;
            gemm_dual(sb, i1, D1, W0, D1, D1,
                      i1, D1, W0, D1, 0, m0, n0, 0, acc);
            epilogue(acc, m0, n0, D0, b0, nullptr, nullptr, true, o0, f0);
        } else if (blk < 80) {
            int l = blk - 16;
            int m0 = (l >> 5) * BM, n0 = (l & 31) * BN;
            gemm_dual(sb, i2, D2, W1, D2, D2,
                      i0, D0, W0T, D0, D0, m0, n0, 0, acc);
            epilogue(acc, m0, n0, D1, b1, nullptr, nullptr, true, o1, f1);
        } else {
            int l = blk - 80;
            int m0 = (l >> 5) * BM, n0 = (l & 31) * BN;
            gemm_dual(sb, i1, D1, W1T, D1, D1,
                      i1, D1, W1T, D1, 0, m0, n0, 0, acc);
            epilogue(acc, m0, n0, D2, nullptr, c2, c2p, true, o2, f2);
        }

        if (t < T_STEPS) grid_barrier(t);
    }
}

// C2 split-K: 128 CTAs. half 0: c2 = z(K[0,2048)) + b2. half 1: c2p = z(K[2048,4096)).
__global__ void __launch_bounds__(256, 1) ep_c2_kernel(
    const __half* dh, const __half* W2, const float* b2,
    float* c2, float* c2p)
{
    extern __shared__ char dyn[];
    uint32_t sb = smem_u32(dyn);

    float acc[2][4][4];
    #pragma unroll
    for (int i = 0; i < 2; i++)
        #pragma unroll
        for (int j = 0; j < 4; j++)
            #pragma unroll
            for (int k = 0; k < 4; k++) acc[i][j][k] = 0.f;

    int blk = blockIdx.x;
    int half = blk >> 6;
    int l = blk & 63;
    int m0 = (l >> 5) * BM, n0 = (l & 31) * BN;
    int kbase = half * (DIN / 2);

    gemm_dual(sb, dh, DIN, W2, DIN, DIN / 2,
              dh, DIN, W2, DIN, 0, m0, n0, kbase, acc);

    int tid = threadIdx.x;
    int lane = tid & 31, wid = tid >> 5;
    int wm = wid >> 1, wn = wid & 1;
    int g = lane >> 2, t = lane & 3;
    float* dst = half ? c2p : c2;
    #pragma unroll
    for (int mi = 0; mi < 2; mi++) {
        #pragma unroll
        for (int ni = 0; ni < 4; ni++) {
            int nc = n0 + wn * 32 + ni * 8 + 2 * t;
            float bv0 = half ? 0.f : b2[nc];
            float bv1 = half ? 0.f : b2[nc + 1];
            #pragma unroll
            for (int h = 0; h < 2; h++) {
                int mr = m0 + wm * 32 + mi * 16 + g + h * 8;
                float v0 = acc[mi][ni][2 * h + 0] + bv0;
                float v1 = acc[mi][ni][2 * h + 1] + bv1;
                *(float2*)&dst[(size_t)mr * D2 + nc] = make_float2(v0, v1);
            }
        }
    }
}

// ====================== fused conversion kernel ============================
__device__ __forceinline__ void vec4_to_h(const float* x, __half* h, int idx) {
    float4 v = *(const float4*)&x[idx];
    __half2 p0, p1;
    p0.x = __float2half_rn(v.x); p0.y = __float2half_rn(v.y);
    p1.x = __float2half_rn(v.z); p1.y = __float2half_rn(v.w);
    *(__half2*)&h[idx] = p0;
    *(__half2*)&h[idx + 2] = p1;
}

// block ranges (each non-transpose block converts 1024 elems)
#define CB_W1   1024
#define CB_W2   5120
#define CB_DATA 13312
#define CB_S0   14336
#define CB_S1   14464
#define CB_S2   14976
#define CB_W0T  15488
#define CB_W1T  16512
#define CB_TOTAL 20608

__global__ void __launch_bounds__(256) fused_convert(
    const float* __restrict__ W0, const float* __restrict__ W1,
    const float* __restrict__ W2, const float* __restrict__ data,
    const float* __restrict__ s0, const float* __restrict__ s1,
    const float* __restrict__ s2,
    __half* hW0, __half* hW1, __half* hW0T, __half* hW1T,
    __half* hW2, __half* hd,
    __half* hs0, __half* hs1, __half* hs2)
{
    __shared__ float tile[32][33];
    int b = blockIdx.x, tid = threadIdx.x;
    if (b == 0 && tid == 0) { g_cnt = 0; g_release = 0; }

    if (b < CB_W1) {
        vec4_to_h(W0, hW0, (b * 256 + tid) * 4);
    } else if (b < CB_W2) {
        vec4_to_h(W1, hW1, ((b - CB_W1) * 256 + tid) * 4);
    } else if (b < CB_DATA) {
        vec4_to_h(W2, hW2, ((b - CB_W2) * 256 + tid) * 4);
    } else if (b < CB_S0) {
        vec4_to_h(data, hd, ((b - CB_DATA) * 256 + tid) * 4);
    } else if (b < CB_S1) {
        vec4_to_h(s0, hs0, ((b - CB_S0) * 256 + tid) * 4);
    } else if (b < CB_S2) {
        vec4_to_h(s1, hs1, ((b - CB_S1) * 256 + tid) * 4);
    } else if (b < CB_W0T) {
        vec4_to_h(s2, hs2, ((b - CB_S2) * 256 + tid) * 4);
    } else if (b < CB_W1T) {
        // W0 (D0 x D1) -> W0T (D1 x D0) fp16
        int local = b - CB_W0T;
        int bx = local % (D1 / 32), by = local / (D1 / 32);
        int tx = tid & 31, ty = tid >> 5;
        int c0 = bx * 32, r0 = by * 32;
        #pragma unroll
        for (int k = 0; k < 4; k++)
            tile[ty + 8 * k][tx] = W0[(size_t)(r0 + ty + 8 * k) * D1 + c0 + tx];
        __syncthreads();
        #pragma unroll
        for (int k = 0; k < 4; k++) {
            size_t o = (size_t)(c0 + ty + 8 * k) * D0 + r0 + tx;
            hW0T[o] = __float2half_rn(tile[tx][ty + 8 * k]);
        }
    } else {
        // W1 (D1 x D2) -> W1T (D2 x D1) fp16
        int local = b - CB_W1T;
        int bx = local % (D2 / 32), by = local / (D2 / 32);
        int tx = tid & 31, ty = tid >> 5;
        int c0 = bx * 32, r0 = by * 32;
        #pragma unroll
        for (int k = 0; k < 4; k++)
            tile[ty + 8 * k][tx] = W1[(size_t)(r0 + ty + 8 * k) * D2 + c0 + tx];
        __syncthreads();
        #pragma unroll
        for (int k = 0; k < 4; k++) {
            size_t o = (size_t)(c0 + ty + 8 * k) * D1 + r0 + tx;
            hW1T[o] = __float2half_rn(tile[tx][ty + 8 * k]);
        }
    }
}

// ------------------------------- host side ---------------------------------
static inline void* sym(const void* s) {
    void* p = nullptr;
    cudaGetSymbolAddress(&p, s);
    return p;
}

extern "C" void kernel_launch(void* const* d_in, const int* in_sizes, int n_in,
                              void* d_out, int out_size)
{
    const float* data = (const float*)d_in[0];
    const float* in_s0 = (const float*)d_in[1];
    const float* in_s1 = (const float*)d_in[2];
    const float* in_s2 = (const float*)d_in[3];
    const float* W0 = (const float*)d_in[4];
    const float* b0 = (const float*)d_in[5];
    const float* W1 = (const float*)d_in[6];
    const float* b1 = (const float*)d_in[7];
    const float* W2 = (const float*)d_in[8];
    const float* b2 = (const float*)d_in[9];
    float* out = (float*)d_out;

    cudaFuncSetAttribute(ep_steps_persist, cudaFuncAttributeMaxDynamicSharedMemorySize, DSMEM_BYTES);
    cudaFuncSetAttribute(ep_c2_kernel,     cudaFuncAttributeMaxDynamicSharedMemorySize, DSMEM_BYTES);

    __half *hW0 = (__half*)sym(g_hW0), *hW1 = (__half*)sym(g_hW1);
    __half *hW0T = (__half*)sym(g_hW0T), *hW1T = (__half*)sym(g_hW1T);
    __half *hW2 = (__half*)sym(g_hW2), *hd = (__half*)sym(g_hd);
    __half *hs0 = (__half*)sym(g_hs0);
    __half *hs1 = (__half*)sym(g_hs1);
    __half *hs2 = (__half*)sym(g_hs2);
    float* c2 = (float*)sym(g_c2);
    float* c2p = (float*)sym(g_c2p);

    fused_convert<<<CB_TOTAL, 256>>>(
        W0, W1, W2, data, in_s0, in_s1, in_s2,
        hW0, hW1, hW0T, hW1T, hW2, hd, hs0, hs1, hs2);

    ep_c2_kernel<<<128, 256, DSMEM_BYTES>>>(hd, hW2, b2, c2, c2p);

    ep_steps_persist<<<NBLK, 256, DSMEM_BYTES>>>(
        hs0, hs1, hs2,
        hW0, hW1, hW0T, hW1T,
        b0, b1, c2, c2p, out);
}

// round 9
// speedup vs baseline: 5.5150x; 1.1218x over previous
#include <cuda_runtime.h>
#include <cuda_fp16.h>
#include <cstdint>
#include <cstddef>

// ---------------------------------------------------------------------------
// EP free-phase relaxation. Persistent single-pass fp16 mma.sync kernel,
// 512 threads/CTA (16 warps 4x4), per-group dataflow flags instead of a
// global grid barrier (s1 group never stalls: its producers finish early).
//   s0' = rho(s1 W0^T + b0)            G0: 16 CTAs, K=2048 (32 stages)
//   s1' = rho(s2 W1^T + b1 + s0 W0)    G1: 64 CTAs, K=2560 (40 stages)
//   s2' = rho(C2 + s1 W1)              G2: 64 CTAs, K=2048 (32 stages)
// C2 = data@W2^T + b2 split-K over 128 CTAs (c2 + c2p).
// ---------------------------------------------------------------------------

#define BATCH 256
#define D0 512
#define D1 2048
#define D2 2048
#define DIN 4096
#define T_STEPS 20

#define BM 128
#define BN 64
#define BK 64
#define DEPTH 4
#define THREADS 512

#define ROW_BYTES 144                    // 64 halves (128B) + 16B pad
#define A_MAT (128 * ROW_BYTES)          // 18432
#define B_MAT (64 * ROW_BYTES)           // 9216
#define OFF_A 0
#define OFF_B (A_MAT)
#define STAGE_BYTES (A_MAT + B_MAT)      // 27648
#define DSMEM_BYTES (DEPTH * STAGE_BYTES) // 110592

// --------------------------- device scratch --------------------------------
__device__ __half g_hW0[D0 * D1];
__device__ __half g_hW1[D1 * D2];
__device__ __half g_hW0T[D1 * D0];
__device__ __half g_hW1T[D2 * D1];
__device__ __half g_hW2[D2 * DIN];
__device__ __half g_hd[BATCH * DIN];
__device__ __half g_hs0[2][BATCH * D0];
__device__ __half g_hs1[2][BATCH * D1];
__device__ __half g_hs2[2][BATCH * D2];
__device__ float g_c2[BATCH * D2];
__device__ float g_c2p[BATCH * D2];
__device__ int g_done0, g_done1, g_done2;   // per-group step counters

// ------------------------------ PTX helpers --------------------------------
__device__ __forceinline__ uint32_t smem_u32(const void* p) {
    uint32_t a;
    asm("{ .reg .u64 t; cvta.to.shared.u64 t, %1; cvt.u32.u64 %0, t; }"
        : "=r"(a) : "l"(p));
    return a;
}
__device__ __forceinline__ void cp16(uint32_t dst, const void* src) {
    asm volatile("cp.async.cg.shared.global [%0], [%1], 16;"
                 :: "r"(dst), "l"(src) : "memory");
}
__device__ __forceinline__ void cp_commit() {
    asm volatile("cp.async.commit_group;" ::: "memory");
}
template <int N>
__device__ __forceinline__ void cp_wait() {
    asm volatile("cp.async.wait_group %0;" :: "n"(N) : "memory");
}
__device__ __forceinline__ void ldm_x4(uint32_t (&r)[4], uint32_t addr) {
    asm volatile("ldmatrix.sync.aligned.m8n8.x4.shared.b16 {%0,%1,%2,%3}, [%4];"
                 : "=r"(r[0]), "=r"(r[1]), "=r"(r[2]), "=r"(r[3]) : "r"(addr));
}
__device__ __forceinline__ void mma_f16(float (&d)[4], const uint32_t (&a)[4],
                                        uint32_t b0, uint32_t b1) {
    asm volatile(
        "mma.sync.aligned.m16n8k16.row.col.f32.f16.f16.f32 "
        "{%0,%1,%2,%3}, {%4,%5,%6,%7}, {%8,%9}, {%0,%1,%2,%3};"
        : "+f"(d[0]), "+f"(d[1]), "+f"(d[2]), "+f"(d[3])
        : "r"(a[0]), "r"(a[1]), "r"(a[2]), "r"(a[3]), "r"(b0), "r"(b1));
}

// Dataflow sync: signal own group's completion of step t; wait on producers.
__device__ __forceinline__ void signal_done(int* flag) {
    __syncthreads();
    if (threadIdx.x == 0) {
        __threadfence();
        atomicAdd(flag, 1);
    }
}
__device__ __forceinline__ void wait_flag(volatile int* flag, int target) {
    if (threadIdx.x == 0) {
        while (*flag < target) { }
        __threadfence();
    }
    __syncthreads();
}

// ---------------------------------------------------------------------------
// Stage loader: A rows [m0,m0+128) x k[k0,k0+64), B rows [n0,n0+64).
// 512 threads, 3 cp16 each (2 A, 1 B).
// ---------------------------------------------------------------------------
__device__ __forceinline__ void load_stage(
    uint32_t sb,
    const __half* __restrict__ A, int lda, int m0,
    const __half* __restrict__ B, int ldb, int n0, int k0)
{
    int t = threadIdx.x;
    {   // A: row = t>>2 (0..127), chunks (t&3)*2, +1
        int r = t >> 2, cb = (t & 3) * 2;
        uint32_t rowoff = (uint32_t)r * ROW_BYTES;
        const __half* pa = A + (size_t)(m0 + r) * lda + k0;
        cp16(sb + OFF_A + rowoff + (uint32_t)cb * 16, pa + cb * 8);
        cp16(sb + OFF_A + rowoff + (uint32_t)(cb + 1) * 16, pa + (cb + 1) * 8);
    }
    {   // B: row = t>>3 (0..63), chunk = t&7
        int r = t >> 3, c = t & 7;
        const __half* pb = B + (size_t)(n0 + r) * ldb + k0;
        cp16(sb + OFF_B + (uint32_t)r * ROW_BYTES + (uint32_t)c * 16, pb + c * 8);
    }
}

// ---------------------------------------------------------------------------
// One BK=64 stage. 16 warps in 4(m) x 4(n), warp tile 32x16, acc[2][2][4].
// Per warp per k16: 2 A-ldmatrix + 1 B-ldmatrix, 4 MMAs.
// ---------------------------------------------------------------------------
__device__ __forceinline__ void compute_stage(uint32_t sb, float (&acc)[2][2][4])
{
    int tid = threadIdx.x;
    int lane = tid & 31, wid = tid >> 5;
    int wm = wid >> 2, wn = wid & 3;
    int lr = lane & 15, lc = lane >> 4;
    uint32_t a_base = (uint32_t)(wm * 32 + lr) * ROW_BYTES + (uint32_t)lc * 16;
    uint32_t b_base = (uint32_t)(wn * 16 + lr) * ROW_BYTES + (uint32_t)lc * 16;

    #pragma unroll
    for (int kk = 0; kk < 4; kk++) {
        uint32_t koff = (uint32_t)kk * 32;
        uint32_t a[2][4], b[4];
        #pragma unroll
        for (int mi = 0; mi < 2; mi++)
            ldm_x4(a[mi], sb + OFF_A + a_base + (uint32_t)mi * (16 * ROW_BYTES) + koff);
        ldm_x4(b, sb + OFF_B + b_base + koff);
        #pragma unroll
        for (int mi = 0; mi < 2; mi++) {
            #pragma unroll
            for (int ni = 0; ni < 2; ni++) {
                mma_f16(acc[mi][ni], a[mi], b[ni], b[ni + 2]);
            }
        }
    }
}

// Dual-segment continuous pipeline: stages [0,nst1) from set1, rest from set2.
__device__ void gemm_dual(
    uint32_t sbase,
    const __half* A1, int lda1, const __half* B1, int ldb1, int K1,
    const __half* A2, int lda2, const __half* B2, int ldb2, int K2,
    int m0, int n0, int kbase1, float (&acc)[2][2][4])
{
    int nst1 = K1 / BK;
    int nst = nst1 + K2 / BK;

    #pragma unroll
    for (int p = 0; p < DEPTH - 1; p++) {
        if (p < nst) {
            if (p < nst1)
                load_stage(sbase + (uint32_t)p * STAGE_BYTES,
                           A1, lda1, m0, B1, ldb1, n0, kbase1 + p * BK);
            else
                load_stage(sbase + (uint32_t)p * STAGE_BYTES,
                           A2, lda2, m0, B2, ldb2, n0, (p - nst1) * BK);
        }
        cp_commit();
    }
    for (int s = 0; s < nst; s++) {
        cp_wait<DEPTH - 2>();
        __syncthreads();
        int nf = s + DEPTH - 1;
        if (nf < nst) {
            uint32_t buf = sbase + (uint32_t)(nf % DEPTH) * STAGE_BYTES;
            if (nf < nst1)
                load_stage(buf, A1, lda1, m0, B1, ldb1, n0, kbase1 + nf * BK);
            else
                load_stage(buf, A2, lda2, m0, B2, ldb2, n0, (nf - nst1) * BK);
        }
        cp_commit();
        compute_stage(sbase + (uint32_t)(s % DEPTH) * STAGE_BYTES, acc);
    }
}

// ---------------------------------------------------------------------------
// Epilogue: bias / C2-add / rho, write fp16 state and/or fp32.
// Warp tile 32x16: nc = n0 + wn*16 + ni*8 + 2t;  mr = m0 + wm*32 + mi*16 + g + 8h
// ---------------------------------------------------------------------------
__device__ void epilogue(
    float (&acc)[2][2][4], int m0, int n0, int outw,
    const float* __restrict__ bias, const float* __restrict__ addm,
    const float* __restrict__ addm2, bool do_rho,
    __half* __restrict__ oh, float* __restrict__ of)
{
    int tid = threadIdx.x;
    int lane = tid & 31, wid = tid >> 5;
    int wm = wid >> 2, wn = wid & 3;
    int g = lane >> 2, t = lane & 3;

    #pragma unroll
    for (int mi = 0; mi < 2; mi++) {
        #pragma unroll
        for (int ni = 0; ni < 2; ni++) {
            int nc = n0 + wn * 16 + ni * 8 + 2 * t;
            float bv0 = 0.f, bv1 = 0.f;
            if (bias) { bv0 = bias[nc]; bv1 = bias[nc + 1]; }
            #pragma unroll
            for (int h = 0; h < 2; h++) {
                int mr = m0 + wm * 32 + mi * 16 + g + h * 8;
                float v0 = acc[mi][ni][2 * h + 0] + bv0;
                float v1 = acc[mi][ni][2 * h + 1] + bv1;
                size_t o = (size_t)mr * outw + nc;
                if (addm) {
                    float2 av = *(const float2*)&addm[o];
                    v0 += av.x; v1 += av.y;
                }
                if (addm2) {
                    float2 av = *(const float2*)&addm2[o];
                    v0 += av.x; v1 += av.y;
                }
                if (do_rho) {
                    v0 = fminf(fmaxf(v0, 0.f), 1.f);
                    v1 = fminf(fmaxf(v1, 0.f), 1.f);
                }
                if (oh) {
                    __half2 hp;
                    hp.x = __float2half_rn(v0);
                    hp.y = __float2half_rn(v1);
                    *(__half2*)&oh[o] = hp;
                }
                if (of) *(float2*)&of[o] = make_float2(v0, v1);
            }
        }
    }
}

// ---------------------------------------------------------------------------
// Persistent kernel: all T_STEPS steps, per-group dataflow flags.
// 144 CTAs: [0,16) G0 s0' 2x8   [16,80) G1 s1' 2x32   [80,144) G2 s2' 2x32
// ---------------------------------------------------------------------------
__global__ void __launch_bounds__(THREADS, 1) ep_steps_persist(
    __half* s0base, __half* s1base, __half* s2base,
    const __half* W0, const __half* W1,
    const __half* W0T, const __half* W1T,
    const float* b0, const float* b1,
    const float* c2, const float* c2p, float* out)
{
    extern __shared__ char dyn[];
    uint32_t sb = smem_u32(dyn);
    const size_t n0e = (size_t)BATCH * D0;
    const size_t n1e = (size_t)BATCH * D1;
    const size_t n2e = (size_t)BATCH * D2;
    int blk = blockIdx.x;
    int group = (blk < 16) ? 0 : (blk < 80 ? 1 : 2);

    for (int t = 1; t <= T_STEPS; t++) {
        // Wait for producers of the states this group reads at step t
        // (identical condition covers the WAR hazard on this group's output).
        if (t > 1) {
            if (group == 1) {
                wait_flag(&g_done0, (t - 1) * 16);
                wait_flag(&g_done2, (t - 1) * 64);
            } else {
                wait_flag(&g_done1, (t - 1) * 64);
            }
        }

        int pi = (t - 1) & 1, po = t & 1;
        const __half* i0 = s0base + (size_t)pi * n0e;
        const __half* i1 = s1base + (size_t)pi * n1e;
        const __half* i2 = s2base + (size_t)pi * n2e;
        bool last = (t == T_STEPS);
        __half *o0 = nullptr, *o1 = nullptr, *o2 = nullptr;
        float *f0 = nullptr, *f1 = nullptr, *f2 = nullptr;
        if (last) {
            f0 = out;
            f1 = out + n0e;
            f2 = out + n0e + n1e;
        } else {
            o0 = s0base + (size_t)po * n0e;
            o1 = s1base + (size_t)po * n1e;
            o2 = s2base + (size_t)po * n2e;
        }

        float acc[2][2][4];
        #pragma unroll
        for (int i = 0; i < 2; i++)
            #pragma unroll
            for (int j = 0; j < 2; j++)
                #pragma unroll
                for (int k = 0; k < 4; k++) acc[i][j][k] = 0.f;

        if (group == 0) {
            int m0 = (blk >> 3) * BM, n0 = (blk & 7) * BN;
            gemm_dual(sb, i1, D1, W0, D1, D1,
                      i1, D1, W0, D1, 0, m0, n0, 0, acc);
            epilogue(acc, m0, n0, D0, b0, nullptr, nullptr, true, o0, f0);
        } else if (group == 1) {
            int l = blk - 16;
            int m0 = (l >> 5) * BM, n0 = (l & 31) * BN;
            gemm_dual(sb, i2, D2, W1, D2, D2,
                      i0, D0, W0T, D0, D0, m0, n0, 0, acc);
            epilogue(acc, m0, n0, D1, b1, nullptr, nullptr, true, o1, f1);
        } else {
            int l = blk - 80;
            int m0 = (l >> 5) * BM, n0 = (l & 31) * BN;
            gemm_dual(sb, i1, D1, W1T, D1, D1,
                      i1, D1, W1T, D1, 0, m0, n0, 0, acc);
            epilogue(acc, m0, n0, D2, nullptr, c2, c2p, true, o2, f2);
        }

        if (t < T_STEPS) {
            if (group == 0)      signal_done(&g_done0);
            else if (group == 1) signal_done(&g_done1);
            else                 signal_done(&g_done2);
        }
    }
}

// C2 split-K: 128 CTAs. half 0: c2 = z(K[0,2048)) + b2. half 1: c2p = z(K[2048,4096)).
__global__ void __launch_bounds__(THREADS, 1) ep_c2_kernel(
    const __half* dh, const __half* W2, const float* b2,
    float* c2, float* c2p)
{
    extern __shared__ char dyn[];
    uint32_t sb = smem_u32(dyn);

    float acc[2][2][4];
    #pragma unroll
    for (int i = 0; i < 2; i++)
        #pragma unroll
        for (int j = 0; j < 2; j++)
            #pragma unroll
            for (int k = 0; k < 4; k++) acc[i][j][k] = 0.f;

    int blk = blockIdx.x;
    int half = blk >> 6;
    int l = blk & 63;
    int m0 = (l >> 5) * BM, n0 = (l & 31) * BN;
    int kbase = half * (DIN / 2);

    gemm_dual(sb, dh, DIN, W2, DIN, DIN / 2,
              dh, DIN, W2, DIN, 0, m0, n0, kbase, acc);

    int tid = threadIdx.x;
    int lane = tid & 31, wid = tid >> 5;
    int wm = wid >> 2, wn = wid & 3;
    int g = lane >> 2, t = lane & 3;
    float* dst = half ? c2p : c2;
    #pragma unroll
    for (int mi = 0; mi < 2; mi++) {
        #pragma unroll
        for (int ni = 0; ni < 2; ni++) {
            int nc = n0 + wn * 16 + ni * 8 + 2 * t;
            float bv0 = half ? 0.f : b2[nc];
            float bv1 = half ? 0.f : b2[nc + 1];
            #pragma unroll
            for (int h = 0; h < 2; h++) {
                int mr = m0 + wm * 32 + mi * 16 + g + h * 8;
                float v0 = acc[mi][ni][2 * h + 0] + bv0;
                float v1 = acc[mi][ni][2 * h + 1] + bv1;
                *(float2*)&dst[(size_t)mr * D2 + nc] = make_float2(v0, v1);
            }
        }
    }
}

// ====================== fused conversion kernel ============================
__device__ __forceinline__ void vec4_to_h(const float* x, __half* h, int idx) {
    float4 v = *(const float4*)&x[idx];
    __half2 p0, p1;
    p0.x = __float2half_rn(v.x); p0.y = __float2half_rn(v.y);
    p1.x = __float2half_rn(v.z); p1.y = __float2half_rn(v.w);
    *(__half2*)&h[idx] = p0;
    *(__half2*)&h[idx + 2] = p1;
}

// block ranges (each non-transpose block converts 1024 elems)
#define CB_W1   1024
#define CB_W2   5120
#define CB_DATA 13312
#define CB_S0   14336
#define CB_S1   14464
#define CB_S2   14976
#define CB_W0T  15488
#define CB_W1T  16512
#define CB_TOTAL 20608

__global__ void __launch_bounds__(256) fused_convert(
    const float* __restrict__ W0, const float* __restrict__ W1,
    const float* __restrict__ W2, const float* __restrict__ data,
    const float* __restrict__ s0, const float* __restrict__ s1,
    const float* __restrict__ s2,
    __half* hW0, __half* hW1, __half* hW0T, __half* hW1T,
    __half* hW2, __half* hd,
    __half* hs0, __half* hs1, __half* hs2)
{
    __shared__ float tile[32][33];
    int b = blockIdx.x, tid = threadIdx.x;
    if (b == 0 && tid == 0) { g_done0 = 0; g_done1 = 0; g_done2 = 0; }

    if (b < CB_W1) {
        vec4_to_h(W0, hW0, (b * 256 + tid) * 4);
    } else if (b < CB_W2) {
        vec4_to_h(W1, hW1, ((b - CB_W1) * 256 + tid) * 4);
    } else if (b < CB_DATA) {
        vec4_to_h(W2, hW2, ((b - CB_W2) * 256 + tid) * 4);
    } else if (b < CB_S0) {
        vec4_to_h(data, hd, ((b - CB_DATA) * 256 + tid) * 4);
    } else if (b < CB_S1) {
        vec4_to_h(s0, hs0, ((b - CB_S0) * 256 + tid) * 4);
    } else if (b < CB_S2) {
        vec4_to_h(s1, hs1, ((b - CB_S1) * 256 + tid) * 4);
    } else if (b < CB_W0T) {
        vec4_to_h(s2, hs2, ((b - CB_S2) * 256 + tid) * 4);
    } else if (b < CB_W1T) {
        int local = b - CB_W0T;
        int bx = local % (D1 / 32), by = local / (D1 / 32);
        int tx = tid & 31, ty = tid >> 5;
        int c0 = bx * 32, r0 = by * 32;
        #pragma unroll
        for (int k = 0; k < 4; k++)
            tile[ty + 8 * k][tx] = W0[(size_t)(r0 + ty + 8 * k) * D1 + c0 + tx];
        __syncthreads();
        #pragma unroll
        for (int k = 0; k < 4; k++) {
            size_t o = (size_t)(c0 + ty + 8 * k) * D0 + r0 + tx;
            hW0T[o] = __float2half_rn(tile[tx][ty + 8 * k]);
        }
    } else {
        int local = b - CB_W1T;
        int bx = local % (D2 / 32), by = local / (D2 / 32);
        int tx = tid & 31, ty = tid >> 5;
        int c0 = bx * 32, r0 = by * 32;
        #pragma unroll
        for (int k = 0; k < 4; k++)
            tile[ty + 8 * k][tx] = W1[(size_t)(r0 + ty + 8 * k) * D2 + c0 + tx];
        __syncthreads();
        #pragma unroll
        for (int k = 0; k < 4; k++) {
            size_t o = (size_t)(c0 + ty + 8 * k) * D1 + r0 + tx;
            hW1T[o] = __float2half_rn(tile[tx][ty + 8 * k]);
        }
    }
}

// ------------------------------- host side ---------------------------------
static inline void* sym(const void* s) {
    void* p = nullptr;
    cudaGetSymbolAddress(&p, s);
    return p;
}

extern "C" void kernel_launch(void* const* d_in, const int* in_sizes, int n_in,
                              void* d_out, int out_size)
{
    const float* data = (const float*)d_in[0];
    const float* in_s0 = (const float*)d_in[1];
    const float* in_s1 = (const float*)d_in[2];
    const float* in_s2 = (const float*)d_in[3];
    const float* W0 = (const float*)d_in[4];
    const float* b0 = (const float*)d_in[5];
    const float* W1 = (const float*)d_in[6];
    const float* b1 = (const float*)d_in[7];
    const float* W2 = (const float*)d_in[8];
    const float* b2 = (const float*)d_in[9];
    float* out = (float*)d_out;

    cudaFuncSetAttribute(ep_steps_persist, cudaFuncAttributeMaxDynamicSharedMemorySize, DSMEM_BYTES);
    cudaFuncSetAttribute(ep_c2_kernel,     cudaFuncAttributeMaxDynamicSharedMemorySize, DSMEM_BYTES);

    __half *hW0 = (__half*)sym(g_hW0), *hW1 = (__half*)sym(g_hW1);
    __half *hW0T = (__half*)sym(g_hW0T), *hW1T = (__half*)sym(g_hW1T);
    __half *hW2 = (__half*)sym(g_hW2), *hd = (__half*)sym(g_hd);
    __half *hs0 = (__half*)sym(g_hs0);
    __half *hs1 = (__half*)sym(g_hs1);
    __half *hs2 = (__half*)sym(g_hs2);
    float* c2 = (float*)sym(g_c2);
    float* c2p = (float*)sym(g_c2p);

    fused_convert<<<CB_TOTAL, 256>>>(
        W0, W1, W2, data, in_s0, in_s1, in_s2,
        hW0, hW1, hW0T, hW1T, hW2, hd, hs0, hs1, hs2);

    ep_c2_kernel<<<128, THREADS, DSMEM_BYTES>>>(hd, hW2, b2, c2, c2p);

    ep_steps_persist<<<144, THREADS, DSMEM_BYTES>>>(
        hs0, hs1, hs2,
        hW0, hW1, hW0T, hW1T,
        b0, b1, c2, c2p, out);
}

// round 10
// speedup vs baseline: 5.6207x; 1.0192x over previous
#include <cuda_runtime.h>
#include <cuda_fp16.h>
#include <cstdint>
#include <cstddef>

// ---------------------------------------------------------------------------
// EP free-phase relaxation. Persistent single-pass fp16 mma.sync kernel,
// 512 threads/CTA (16 warps 4x4), per-group dataflow flags, and split-K
// rebalance: G2 computes a 4-stage partial of G1's s0@W0 term so every
// group's per-step critical path is <= 36 stages (was 40).
//   G0 (16 CTAs): s0' = rho(s1 W0^T + b0)                      32 stages
//   G1 (64 CTAs): s1' = rho(s2 W1^T + s0 W0[k<256] + c1p + b1) 36 stages
//   G2 (64 CTAs): c1p = s0 W0[k 256:512]  (4 st)  then
//                 s2' = rho(C2 + s1 W1)          (32 st)       36 stages
// C2 = data@W2^T + b2 split-K over 128 CTAs (c2 + c2p).
// ---------------------------------------------------------------------------

#define BATCH 256
#define D0 512
#define D1 2048
#define D2 2048
#define DIN 4096
#define T_STEPS 20

#define BM 128
#define BN 64
#define BK 64
#define DEPTH 4
#define THREADS 512

#define ROW_BYTES 144                    // 64 halves (128B) + 16B pad
#define A_MAT (128 * ROW_BYTES)          // 18432
#define B_MAT (64 * ROW_BYTES)           // 9216
#define OFF_A 0
#define OFF_B (A_MAT)
#define STAGE_BYTES (A_MAT + B_MAT)      // 27648
#define DSMEM_BYTES (DEPTH * STAGE_BYTES) // 110592

// --------------------------- device scratch --------------------------------
__device__ __half g_hW0[D0 * D1];
__device__ __half g_hW1[D1 * D2];
__device__ __half g_hW0T[D1 * D0];
__device__ __half g_hW1T[D2 * D1];
__device__ __half g_hW2[D2 * DIN];
__device__ __half g_hd[BATCH * DIN];
__device__ __half g_hs0[2][BATCH * D0];
__device__ __half g_hs1[2][BATCH * D1];
__device__ __half g_hs2[2][BATCH * D2];
__device__ float g_c2[BATCH * D2];
__device__ float g_c2p[BATCH * D2];
__device__ float g_c1p[2][BATCH * D1];      // split-K partial of s0@W0 (parity)
__device__ int g_done0, g_done1, g_done2;   // per-group step counters
__device__ int g_part;                      // G2 partial completion counter

// ------------------------------ PTX helpers --------------------------------
__device__ __forceinline__ uint32_t smem_u32(const void* p) {
    uint32_t a;
    asm("{ .reg .u64 t; cvta.to.shared.u64 t, %1; cvt.u32.u64 %0, t; }"
        : "=r"(a) : "l"(p));
    return a;
}
__device__ __forceinline__ void cp16(uint32_t dst, const void* src) {
    asm volatile("cp.async.cg.shared.global [%0], [%1], 16;"
                 :: "r"(dst), "l"(src) : "memory");
}
__device__ __forceinline__ void cp_commit() {
    asm volatile("cp.async.commit_group;" ::: "memory");
}
template <int N>
__device__ __forceinline__ void cp_wait() {
    asm volatile("cp.async.wait_group %0;" :: "n"(N) : "memory");
}
__device__ __forceinline__ void ldm_x4(uint32_t (&r)[4], uint32_t addr) {
    asm volatile("ldmatrix.sync.aligned.m8n8.x4.shared.b16 {%0,%1,%2,%3}, [%4];"
                 : "=r"(r[0]), "=r"(r[1]), "=r"(r[2]), "=r"(r[3]) : "r"(addr));
}
__device__ __forceinline__ void mma_f16(float (&d)[4], const uint32_t (&a)[4],
                                        uint32_t b0, uint32_t b1) {
    asm volatile(
        "mma.sync.aligned.m16n8k16.row.col.f32.f16.f16.f32 "
        "{%0,%1,%2,%3}, {%4,%5,%6,%7}, {%8,%9}, {%0,%1,%2,%3};"
        : "+f"(d[0]), "+f"(d[1]), "+f"(d[2]), "+f"(d[3])
        : "r"(a[0]), "r"(a[1]), "r"(a[2]), "r"(a[3]), "r"(b0), "r"(b1));
}

// Dataflow sync
__device__ __forceinline__ void signal_flag(int* flag) {
    __syncthreads();
    if (threadIdx.x == 0) {
        __threadfence();
        atomicAdd(flag, 1);
    }
}
__device__ __forceinline__ void wait_flag(volatile int* flag, int target) {
    if (threadIdx.x == 0) {
        while (*flag < target) { }
        __threadfence();
    }
    __syncthreads();
}

// ---------------------------------------------------------------------------
// Stage loader: A rows [m0,m0+128) x k[k0,k0+64), B rows [n0,n0+64).
// 512 threads, 3 cp16 each (2 A, 1 B).
// ---------------------------------------------------------------------------
__device__ __forceinline__ void load_stage(
    uint32_t sb,
    const __half* __restrict__ A, int lda, int m0,
    const __half* __restrict__ B, int ldb, int n0, int k0)
{
    int t = threadIdx.x;
    {
        int r = t >> 2, cb = (t & 3) * 2;
        uint32_t rowoff = (uint32_t)r * ROW_BYTES;
        const __half* pa = A + (size_t)(m0 + r) * lda + k0;
        cp16(sb + OFF_A + rowoff + (uint32_t)cb * 16, pa + cb * 8);
        cp16(sb + OFF_A + rowoff + (uint32_t)(cb + 1) * 16, pa + (cb + 1) * 8);
    }
    {
        int r = t >> 3, c = t & 7;
        const __half* pb = B + (size_t)(n0 + r) * ldb + k0;
        cp16(sb + OFF_B + (uint32_t)r * ROW_BYTES + (uint32_t)c * 16, pb + c * 8);
    }
}

// ---------------------------------------------------------------------------
// One BK=64 stage. 16 warps in 4(m) x 4(n), warp tile 32x16, acc[2][2][4].
// ---------------------------------------------------------------------------
__device__ __forceinline__ void compute_stage(uint32_t sb, float (&acc)[2][2][4])
{
    int tid = threadIdx.x;
    int lane = tid & 31, wid = tid >> 5;
    int wm = wid >> 2, wn = wid & 3;
    int lr = lane & 15, lc = lane >> 4;
    uint32_t a_base = (uint32_t)(wm * 32 + lr) * ROW_BYTES + (uint32_t)lc * 16;
    uint32_t b_base = (uint32_t)(wn * 16 + lr) * ROW_BYTES + (uint32_t)lc * 16;

    #pragma unroll
    for (int kk = 0; kk < 4; kk++) {
        uint32_t koff = (uint32_t)kk * 32;
        uint32_t a[2][4], b[4];
        #pragma unroll
        for (int mi = 0; mi < 2; mi++)
            ldm_x4(a[mi], sb + OFF_A + a_base + (uint32_t)mi * (16 * ROW_BYTES) + koff);
        ldm_x4(b, sb + OFF_B + b_base + koff);
        #pragma unroll
        for (int mi = 0; mi < 2; mi++) {
            #pragma unroll
            for (int ni = 0; ni < 2; ni++) {
                mma_f16(acc[mi][ni], a[mi], b[ni], b[ni + 2]);
            }
        }
    }
}

// Dual-segment continuous pipeline: stages [0,nst1) from set1 (k offset
// kbase1), remaining from set2 (k offset kbase2).
__device__ void gemm_dual(
    uint32_t sbase,
    const __half* A1, int lda1, const __half* B1, int ldb1, int K1, int kbase1,
    const __half* A2, int lda2, const __half* B2, int ldb2, int K2, int kbase2,
    int m0, int n0, float (&acc)[2][2][4])
{
    int nst1 = K1 / BK;
    int nst = nst1 + K2 / BK;

    #pragma unroll
    for (int p = 0; p < DEPTH - 1; p++) {
        if (p < nst) {
            if (p < nst1)
                load_stage(sbase + (uint32_t)p * STAGE_BYTES,
                           A1, lda1, m0, B1, ldb1, n0, kbase1 + p * BK);
            else
                load_stage(sbase + (uint32_t)p * STAGE_BYTES,
                           A2, lda2, m0, B2, ldb2, n0, kbase2 + (p - nst1) * BK);
        }
        cp_commit();
    }
    for (int s = 0; s < nst; s++) {
        cp_wait<DEPTH - 2>();
        __syncthreads();
        int nf = s + DEPTH - 1;
        if (nf < nst) {
            uint32_t buf = sbase + (uint32_t)(nf % DEPTH) * STAGE_BYTES;
            if (nf < nst1)
                load_stage(buf, A1, lda1, m0, B1, ldb1, n0, kbase1 + nf * BK);
            else
                load_stage(buf, A2, lda2, m0, B2, ldb2, n0,
                           kbase2 + (nf - nst1) * BK);
        }
        cp_commit();
        compute_stage(sbase + (uint32_t)(s % DEPTH) * STAGE_BYTES, acc);
    }
}

// ---------------------------------------------------------------------------
// Epilogue: bias / add / rho, write fp16 state and/or fp32.
// ---------------------------------------------------------------------------
__device__ void epilogue(
    float (&acc)[2][2][4], int m0, int n0, int outw,
    const float* __restrict__ bias, const float* __restrict__ addm,
    const float* __restrict__ addm2, bool do_rho,
    __half* __restrict__ oh, float* __restrict__ of)
{
    int tid = threadIdx.x;
    int lane = tid & 31, wid = tid >> 5;
    int wm = wid >> 2, wn = wid & 3;
    int g = lane >> 2, t = lane & 3;

    #pragma unroll
    for (int mi = 0; mi < 2; mi++) {
        #pragma unroll
        for (int ni = 0; ni < 2; ni++) {
            int nc = n0 + wn * 16 + ni * 8 + 2 * t;
            float bv0 = 0.f, bv1 = 0.f;
            if (bias) { bv0 = bias[nc]; bv1 = bias[nc + 1]; }
            #pragma unroll
            for (int h = 0; h < 2; h++) {
                int mr = m0 + wm * 32 + mi * 16 + g + h * 8;
                float v0 = acc[mi][ni][2 * h + 0] + bv0;
                float v1 = acc[mi][ni][2 * h + 1] + bv1;
                size_t o = (size_t)mr * outw + nc;
                if (addm) {
                    float2 av = *(const float2*)&addm[o];
                    v0 += av.x; v1 += av.y;
                }
                if (addm2) {
                    float2 av = *(const float2*)&addm2[o];
                    v0 += av.x; v1 += av.y;
                }
                if (do_rho) {
                    v0 = fminf(fmaxf(v0, 0.f), 1.f);
                    v1 = fminf(fmaxf(v1, 0.f), 1.f);
                }
                if (oh) {
                    __half2 hp;
                    hp.x = __float2half_rn(v0);
                    hp.y = __float2half_rn(v1);
                    *(__half2*)&oh[o] = hp;
                }
                if (of) *(float2*)&of[o] = make_float2(v0, v1);
            }
        }
    }
}

// ---------------------------------------------------------------------------
// Persistent kernel.
// 144 CTAs: [0,16) G0 s0' 2x8   [16,80) G1 s1' 2x32   [80,144) G2 2x32
// ---------------------------------------------------------------------------
__global__ void __launch_bounds__(THREADS, 1) ep_steps_persist(
    __half* s0base, __half* s1base, __half* s2base,
    const __half* W0, const __half* W1,
    const __half* W0T, const __half* W1T,
    const float* b0, const float* b1,
    const float* c2, const float* c2p, float* c1pbase, float* out)
{
    extern __shared__ char dyn[];
    uint32_t sb = smem_u32(dyn);
    const size_t n0e = (size_t)BATCH * D0;
    const size_t n1e = (size_t)BATCH * D1;
    const size_t n2e = (size_t)BATCH * D2;
    int blk = blockIdx.x;
    int group = (blk < 16) ? 0 : (blk < 80 ? 1 : 2);

    for (int t = 1; t <= T_STEPS; t++) {
        // Wait for producers of the states this group reads at step t
        // (same condition covers the WAR hazards on this group's outputs).
        if (t > 1) {
            if (group == 0) {
                wait_flag(&g_done1, (t - 1) * 64);
            } else if (group == 1) {
                wait_flag(&g_done0, (t - 1) * 16);
                wait_flag(&g_done2, (t - 1) * 64);
            } else {
                wait_flag(&g_done1, (t - 1) * 64);  // s1 input + c1p WAR
                wait_flag(&g_done0, (t - 1) * 16);  // s0 input for partial
            }
        }

        int pi = (t - 1) & 1, po = t & 1;
        const __half* i0 = s0base + (size_t)pi * n0e;
        const __half* i1 = s1base + (size_t)pi * n1e;
        const __half* i2 = s2base + (size_t)pi * n2e;
        float* c1p = c1pbase + (size_t)po * n1e;
        bool last = (t == T_STEPS);
        __half *o0 = nullptr, *o1 = nullptr, *o2 = nullptr;
        float *f0 = nullptr, *f1 = nullptr, *f2 = nullptr;
        if (last) {
            f0 = out;
            f1 = out + n0e;
            f2 = out + n0e + n1e;
        } else {
            o0 = s0base + (size_t)po * n0e;
            o1 = s1base + (size_t)po * n1e;
            o2 = s2base + (size_t)po * n2e;
        }

        float acc[2][2][4];
        #pragma unroll
        for (int i = 0; i < 2; i++)
            #pragma unroll
            for (int j = 0; j < 2; j++)
                #pragma unroll
                for (int k = 0; k < 4; k++) acc[i][j][k] = 0.f;

        if (group == 0) {
            int m0 = (blk >> 3) * BM, n0 = (blk & 7) * BN;
            gemm_dual(sb, i1, D1, W0, D1, D1, 0,
                      i1, D1, W0, D1, 0, 0, m0, n0, acc);
            epilogue(acc, m0, n0, D0, b0, nullptr, nullptr, true, o0, f0);
            if (t < T_STEPS) signal_flag(&g_done0);
        } else if (group == 1) {
            int l = blk - 16;
            int m0 = (l >> 5) * BM, n0 = (l & 31) * BN;
            // 32 stages s2@W1^T + 4 stages s0@W0 (k < 256)
            gemm_dual(sb, i2, D2, W1, D2, D2, 0,
                      i0, D0, W0T, D0, 256, 0, m0, n0, acc);
            wait_flag(&g_part, t * 64);         // G2 partial (k 256:512) ready
            epilogue(acc, m0, n0, D1, b1, c1p, nullptr, true, o1, f1);
            if (t < T_STEPS) signal_flag(&g_done1);
        } else {
            int l = blk - 80;
            int m0 = (l >> 5) * BM, n0 = (l & 31) * BN;
            // 4-stage split-K partial of G1 tile l: s0[k 256:512] @ W0T
            gemm_dual(sb, i0, D0, W0T, D0, 256, 256,
                      i0, D0, W0T, D0, 0, 0, m0, n0, acc);
            epilogue(acc, m0, n0, D1, nullptr, nullptr, nullptr, false,
                     nullptr, c1p);
            signal_flag(&g_part);
            // Own 32-stage s2 update
            #pragma unroll
            for (int i = 0; i < 2; i++)
                #pragma unroll
                for (int j = 0; j < 2; j++)
                    #pragma unroll
                    for (int k = 0; k < 4; k++) acc[i][j][k] = 0.f;
            gemm_dual(sb, i1, D1, W1T, D1, D1, 0,
                      i1, D1, W1T, D1, 0, 0, m0, n0, acc);
            epilogue(acc, m0, n0, D2, nullptr, c2, c2p, true, o2, f2);
            if (t < T_STEPS) signal_flag(&g_done2);
        }
    }
}

// C2 split-K: 128 CTAs. half 0: c2 = z(K[0,2048)) + b2. half 1: c2p.
__global__ void __launch_bounds__(THREADS, 1) ep_c2_kernel(
    const __half* dh, const __half* W2, const float* b2,
    float* c2, float* c2p)
{
    extern __shared__ char dyn[];
    uint32_t sb = smem_u32(dyn);

    float acc[2][2][4];
    #pragma unroll
    for (int i = 0; i < 2; i++)
        #pragma unroll
        for (int j = 0; j < 2; j++)
            #pragma unroll
            for (int k = 0; k < 4; k++) acc[i][j][k] = 0.f;

    int blk = blockIdx.x;
    int half = blk >> 6;
    int l = blk & 63;
    int m0 = (l >> 5) * BM, n0 = (l & 31) * BN;
    int kbase = half * (DIN / 2);

    gemm_dual(sb, dh, DIN, W2, DIN, DIN / 2, kbase,
              dh, DIN, W2, DIN, 0, 0, m0, n0, acc);

    int tid = threadIdx.x;
    int lane = tid & 31, wid = tid >> 5;
    int wm = wid >> 2, wn = wid & 3;
    int g = lane >> 2, t = lane & 3;
    float* dst = half ? c2p : c2;
    #pragma unroll
    for (int mi = 0; mi < 2; mi++) {
        #pragma unroll
        for (int ni = 0; ni < 2; ni++) {
            int nc = n0 + wn * 16 + ni * 8 + 2 * t;
            float bv0 = half ? 0.f : b2[nc];
            float bv1 = half ? 0.f : b2[nc + 1];
            #pragma unroll
            for (int h = 0; h < 2; h++) {
                int mr = m0 + wm * 32 + mi * 16 + g + h * 8;
                float v0 = acc[mi][ni][2 * h + 0] + bv0;
                float v1 = acc[mi][ni][2 * h + 1] + bv1;
                *(float2*)&dst[(size_t)mr * D2 + nc] = make_float2(v0, v1);
            }
        }
    }
}

// ====================== fused conversion kernel ============================
__device__ __forceinline__ void vec4_to_h(const float* x, __half* h, int idx) {
    float4 v = *(const float4*)&x[idx];
    __half2 p0, p1;
    p0.x = __float2half_rn(v.x); p0.y = __float2half_rn(v.y);
    p1.x = __float2half_rn(v.z); p1.y = __float2half_rn(v.w);
    *(__half2*)&h[idx] = p0;
    *(__half2*)&h[idx + 2] = p1;
}

// block ranges (each non-transpose block converts 1024 elems)
#define CB_W1   1024
#define CB_W2   5120
#define CB_DATA 13312
#define CB_S0   14336
#define CB_S1   14464
#define CB_S2   14976
#define CB_W0T  15488
#define CB_W1T  16512
#define CB_TOTAL 20608

__global__ void __launch_bounds__(256) fused_convert(
    const float* __restrict__ W0, const float* __restrict__ W1,
    const float* __restrict__ W2, const float* __restrict__ data,
    const float* __restrict__ s0, const float* __restrict__ s1,
    const float* __restrict__ s2,
    __half* hW0, __half* hW1, __half* hW0T, __half* hW1T,
    __half* hW2, __half* hd,
    __half* hs0, __half* hs1, __half* hs2)
{
    __shared__ float tile[32][33];
    int b = blockIdx.x, tid = threadIdx.x;
    if (b == 0 && tid == 0) {
        g_done0 = 0; g_done1 = 0; g_done2 = 0; g_part = 0;
    }

    if (b < CB_W1) {
        vec4_to_h(W0, hW0, (b * 256 + tid) * 4);
    } else if (b < CB_W2) {
        vec4_to_h(W1, hW1, ((b - CB_W1) * 256 + tid) * 4);
    } else if (b < CB_DATA) {
        vec4_to_h(W2, hW2, ((b - CB_W2) * 256 + tid) * 4);
    } else if (b < CB_S0) {
        vec4_to_h(data, hd, ((b - CB_DATA) * 256 + tid) * 4);
    } else if (b < CB_S1) {
        vec4_to_h(s0, hs0, ((b - CB_S0) * 256 + tid) * 4);
    } else if (b < CB_S2) {
        vec4_to_h(s1, hs1, ((b - CB_S1) * 256 + tid) * 4);
    } else if (b < CB_W0T) {
        vec4_to_h(s2, hs2, ((b - CB_S2) * 256 + tid) * 4);
    } else if (b < CB_W1T) {
        int local = b - CB_W0T;
        int bx = local % (D1 / 32), by = local / (D1 / 32);
        int tx = tid & 31, ty = tid >> 5;
        int c0 = bx * 32, r0 = by * 32;
        #pragma unroll
        for (int k = 0; k < 4; k++)
            tile[ty + 8 * k][tx] = W0[(size_t)(r0 + ty + 8 * k) * D1 + c0 + tx];
        __syncthreads();
        #pragma unroll
        for (int k = 0; k < 4; k++) {
            size_t o = (size_t)(c0 + ty + 8 * k) * D0 + r0 + tx;
            hW0T[o] = __float2half_rn(tile[tx][ty + 8 * k]);
        }
    } else {
        int local = b - CB_W1T;
        int bx = local % (D2 / 32), by = local / (D2 / 32);
        int tx = tid & 31, ty = tid >> 5;
        int c0 = bx * 32, r0 = by * 32;
        #pragma unroll
        for (int k = 0; k < 4; k++)
            tile[ty + 8 * k][tx] = W1[(size_t)(r0 + ty + 8 * k) * D2 + c0 + tx];
        __syncthreads();
        #pragma unroll
        for (int k = 0; k < 4; k++) {
            size_t o = (size_t)(c0 + ty + 8 * k) * D1 + r0 + tx;
            hW1T[o] = __float2half_rn(tile[tx][ty + 8 * k]);
        }
    }
}

// ------------------------------- host side ---------------------------------
static inline void* sym(const void* s) {
    void* p = nullptr;
    cudaGetSymbolAddress(&p, s);
    return p;
}

extern "C" void kernel_launch(void* const* d_in, const int* in_sizes, int n_in,
                              void* d_out, int out_size)
{
    const float* data = (const float*)d_in[0];
    const float* in_s0 = (const float*)d_in[1];
    const float* in_s1 = (const float*)d_in[2];
    const float* in_s2 = (const float*)d_in[3];
    const float* W0 = (const float*)d_in[4];
    const float* b0 = (const float*)d_in[5];
    const float* W1 = (const float*)d_in[6];
    const float* b1 = (const float*)d_in[7];
    const float* W2 = (const float*)d_in[8];
    const float* b2 = (const float*)d_in[9];
    float* out = (float*)d_out;

    cudaFuncSetAttribute(ep_steps_persist, cudaFuncAttributeMaxDynamicSharedMemorySize, DSMEM_BYTES);
    cudaFuncSetAttribute(ep_c2_kernel,     cudaFuncAttributeMaxDynamicSharedMemorySize, DSMEM_BYTES);

    __half *hW0 = (__half*)sym(g_hW0), *hW1 = (__half*)sym(g_hW1);
    __half *hW0T = (__half*)sym(g_hW0T), *hW1T = (__half*)sym(g_hW1T);
    __half *hW2 = (__half*)sym(g_hW2), *hd = (__half*)sym(g_hd);
    __half *hs0 = (__half*)sym(g_hs0);
    __half *hs1 = (__half*)sym(g_hs1);
    __half *hs2 = (__half*)sym(g_hs2);
    float* c2 = (float*)sym(g_c2);
    float* c2p = (float*)sym(g_c2p);
    float* c1p = (float*)sym(g_c1p);

    fused_convert<<<CB_TOTAL, 256>>>(
        W0, W1, W2, data, in_s0, in_s1, in_s2,
        hW0, hW1, hW0T, hW1T, hW2, hd, hs0, hs1, hs2);

    ep_c2_kernel<<<128, THREADS, DSMEM_BYTES>>>(hd, hW2, b2, c2, c2p);

    ep_steps_persist<<<144, THREADS, DSMEM_BYTES>>>(
        hs0, hs1, hs2,
        hW0, hW1, hW0T, hW1T,
        b0, b1, c2, c2p, c1p, out);
}